// round 1
// baseline (speedup 1.0000x reference)
#include <cuda_runtime.h>

// Problem constants
#define Bc    2
#define Sc    2048
#define Hc    16
#define Dc    64
#define DMc   1024
#define NQKVc 3072   // 16 * (64+64+64)

// Head-major scratch: [B][H][S][D]
__device__ float g_Q[(size_t)Bc*Hc*Sc*Dc];
__device__ float g_K[(size_t)Bc*Hc*Sc*Dc];
__device__ float g_V[(size_t)Bc*Hc*Sc*Dc];

// ---------------------------------------------------------------------------
// Kernel 1: QKV = X @ W + b, scattered into head-major Q/K/V scratch.
// Tiled 64x64x64 SGEMM, 256 threads (16x16), 4x4 register fragment/thread.
// ---------------------------------------------------------------------------
__global__ __launch_bounds__(256) void qkv_kernel(const float* __restrict__ X,
                                                  const float* __restrict__ W,
                                                  const float* __restrict__ bias) {
    __shared__ float Xs[64 * 65];        // padded (2-way conflict max)
    __shared__ float Ws[64 * 64];        // row-broadcast access: no pad needed
    const int tx = threadIdx.x & 15;
    const int ty = threadIdx.x >> 4;
    const int nt = blockIdx.x;           // output col tile (48 tiles)
    const int mt = blockIdx.y;           // output row tile (64 tiles)

    float acc[4][4] = {};

    for (int kt = 0; kt < DMc / 64; kt++) {
        // Load X tile [64 rows][64 k] and W tile [64 k][64 cols], float4 gmem
        for (int t = threadIdx.x; t < 1024; t += 256) {
            int r = t >> 4, c4 = t & 15;
            float4 xv = *(const float4*)(X + (size_t)(mt * 64 + r) * DMc + kt * 64 + c4 * 4);
            Xs[r * 65 + c4 * 4 + 0] = xv.x;
            Xs[r * 65 + c4 * 4 + 1] = xv.y;
            Xs[r * 65 + c4 * 4 + 2] = xv.z;
            Xs[r * 65 + c4 * 4 + 3] = xv.w;
            float4 wv = *(const float4*)(W + (size_t)(kt * 64 + r) * NQKVc + nt * 64 + c4 * 4);
            *(float4*)(Ws + r * 64 + c4 * 4) = wv;
        }
        __syncthreads();

        #pragma unroll 8
        for (int kk = 0; kk < 64; kk++) {
            float xf[4], wf[4];
            #pragma unroll
            for (int i = 0; i < 4; i++) xf[i] = Xs[(4 * ty + i) * 65 + kk];
            #pragma unroll
            for (int j = 0; j < 4; j++) wf[j] = Ws[kk * 64 + 4 * tx + j];
            #pragma unroll
            for (int i = 0; i < 4; i++)
                #pragma unroll
                for (int j = 0; j < 4; j++) acc[i][j] += xf[i] * wf[j];
        }
        __syncthreads();
    }

    // Scatter into head-major Q/K/V (+bias)
    #pragma unroll
    for (int i = 0; i < 4; i++) {
        int row = mt * 64 + 4 * ty + i;          // global (b,s) row
        int b = row / Sc, s = row % Sc;
        #pragma unroll
        for (int j = 0; j < 4; j++) {
            int e = nt * 64 + 4 * tx + j;        // qkv column
            int h = e / 192, r = e % 192;
            float v = acc[i][j] + bias[e];
            size_t base = ((size_t)(b * Hc + h) * Sc + s) * Dc;
            if (r < 64)        g_Q[base + r]        = v;
            else if (r < 128)  g_K[base + r - 64]   = v;
            else               g_V[base + r - 128]  = v;
        }
    }
}

// ---------------------------------------------------------------------------
// Kernel 2: flash attention, fp32. One block per (q-tile of 64, head, batch).
// 256 threads (16x16), 4x4 fragments; online softmax; scores * 8.0 (ref
// MULTIPLIES by sqrt(dk)).
// Dynamic smem: Qs[64][65] Ks[64][65] Vs[64][64] Ps[64][65] = 66,304 B.
// ---------------------------------------------------------------------------
#define SMEM_ATTN ((64*65 + 64*65 + 64*64 + 64*65) * 4)

__global__ __launch_bounds__(256) void attn_kernel(float* __restrict__ out) {
    extern __shared__ float sm[];
    float* Qs = sm;                 // [64][65]
    float* Ks = Qs + 64 * 65;       // [64][65]
    float* Vs = Ks + 64 * 65;       // [64][64]
    float* Ps = Vs + 64 * 64;       // [64][65]

    const int qt = blockIdx.x;      // 32 q-tiles
    const int h  = blockIdx.y;      // 16 heads
    const int b  = blockIdx.z;      // 2 batches
    const int tid = threadIdx.x;
    const int tx = tid & 15, ty = tid >> 4;

    const size_t head_base = (size_t)(b * Hc + h) * Sc * Dc;
    const float* Qp = g_Q + head_base + (size_t)qt * 64 * Dc;
    const float* Kp = g_K + head_base;
    const float* Vp = g_V + head_base;

    // Load Q tile once
    for (int t = tid; t < 1024; t += 256) {
        int r = t >> 4, c4 = t & 15;
        float4 v = *(const float4*)(Qp + r * Dc + c4 * 4);
        Qs[r * 65 + c4 * 4 + 0] = v.x;
        Qs[r * 65 + c4 * 4 + 1] = v.y;
        Qs[r * 65 + c4 * 4 + 2] = v.z;
        Qs[r * 65 + c4 * 4 + 3] = v.w;
    }

    float m[4], l[4], O[4][4];
    #pragma unroll
    for (int i = 0; i < 4; i++) {
        m[i] = -1e30f; l[i] = 0.f;
        #pragma unroll
        for (int j = 0; j < 4; j++) O[i][j] = 0.f;
    }

    for (int kt = 0; kt < Sc / 64; kt++) {
        // Load K & V tiles
        for (int t = tid; t < 1024; t += 256) {
            int r = t >> 4, c4 = t & 15;
            float4 kv = *(const float4*)(Kp + (size_t)(kt * 64 + r) * Dc + c4 * 4);
            Ks[r * 65 + c4 * 4 + 0] = kv.x;
            Ks[r * 65 + c4 * 4 + 1] = kv.y;
            Ks[r * 65 + c4 * 4 + 2] = kv.z;
            Ks[r * 65 + c4 * 4 + 3] = kv.w;
            float4 vv = *(const float4*)(Vp + (size_t)(kt * 64 + r) * Dc + c4 * 4);
            *(float4*)(Vs + r * 64 + c4 * 4) = vv;
        }
        __syncthreads();

        // Scores s = Q K^T (4x4 per thread)
        float s[4][4] = {};
        #pragma unroll 8
        for (int kk = 0; kk < 64; kk++) {
            float q[4], k[4];
            #pragma unroll
            for (int i = 0; i < 4; i++) q[i] = Qs[(4 * ty + i) * 65 + kk];
            #pragma unroll
            for (int j = 0; j < 4; j++) k[j] = Ks[(4 * tx + j) * 65 + kk];
            #pragma unroll
            for (int i = 0; i < 4; i++)
                #pragma unroll
                for (int j = 0; j < 4; j++) s[i][j] += q[i] * k[j];
        }

        // Online softmax update, row stats reduced across the 16 tx lanes
        #pragma unroll
        for (int i = 0; i < 4; i++) {
            #pragma unroll
            for (int j = 0; j < 4; j++) s[i][j] *= 8.0f;   // * sqrt(64)
            float rm = fmaxf(fmaxf(s[i][0], s[i][1]), fmaxf(s[i][2], s[i][3]));
            #pragma unroll
            for (int o = 8; o >= 1; o >>= 1)
                rm = fmaxf(rm, __shfl_xor_sync(0xffffffffu, rm, o));
            float mn = fmaxf(m[i], rm);
            float corr = __expf(m[i] - mn);
            float rs = 0.f;
            #pragma unroll
            for (int j = 0; j < 4; j++) { s[i][j] = __expf(s[i][j] - mn); rs += s[i][j]; }
            #pragma unroll
            for (int o = 8; o >= 1; o >>= 1)
                rs += __shfl_xor_sync(0xffffffffu, rs, o);
            l[i] = l[i] * corr + rs;
            m[i] = mn;
            #pragma unroll
            for (int j = 0; j < 4; j++) O[i][j] *= corr;
        }

        // Stage P through smem
        #pragma unroll
        for (int i = 0; i < 4; i++)
            #pragma unroll
            for (int j = 0; j < 4; j++)
                Ps[(4 * ty + i) * 65 + 4 * tx + j] = s[i][j];
        __syncthreads();

        // O += P @ V
        #pragma unroll 8
        for (int kk = 0; kk < 64; kk++) {
            float p[4], v[4];
            #pragma unroll
            for (int i = 0; i < 4; i++) p[i] = Ps[(4 * ty + i) * 65 + kk];
            #pragma unroll
            for (int j = 0; j < 4; j++) v[j] = Vs[kk * 64 + 4 * tx + j];
            #pragma unroll
            for (int i = 0; i < 4; i++)
                #pragma unroll
                for (int j = 0; j < 4; j++) O[i][j] += p[i] * v[j];
        }
        __syncthreads();
    }

    // Epilogue: out[b][s][h*64 + c] = O / l
    #pragma unroll
    for (int i = 0; i < 4; i++) {
        int srow = qt * 64 + 4 * ty + i;
        float inv = 1.0f / l[i];
        #pragma unroll
        for (int j = 0; j < 4; j++) {
            out[((size_t)b * Sc + srow) * (Hc * Dc) + h * Dc + 4 * tx + j] = O[i][j] * inv;
        }
    }
}

// ---------------------------------------------------------------------------
extern "C" void kernel_launch(void* const* d_in, const int* in_sizes, int n_in,
                              void* d_out, int out_size) {
    const float* X    = (const float*)d_in[0];   // [B,S,DM] fp32
    const float* W    = (const float*)d_in[1];   // [DM, 3072] fp32
    const float* bias = (const float*)d_in[2];   // [3072] fp32
    float* out = (float*)d_out;                  // [B,S,1024] fp32

    qkv_kernel<<<dim3(NQKVc / 64, (Bc * Sc) / 64), 256>>>(X, W, bias);

    cudaFuncSetAttribute(attn_kernel, cudaFuncAttributeMaxDynamicSharedMemorySize, SMEM_ATTN);
    attn_kernel<<<dim3(Sc / 64, Hc, Bc), 256, SMEM_ATTN>>>(out);
}

// round 3
// speedup vs baseline: 1.0262x; 1.0262x over previous
#include <cuda_runtime.h>
#include <cstdint>

#define Bc    2
#define Sc    2048
#define Hc    16
#define Dc    64
#define DMc   1024
#define NQKVc 3072
#define MROWS (Bc*Sc)          // 4096

// ---------------------------------------------------------------------------
// Device scratch (static arrays: no runtime allocation)
// ---------------------------------------------------------------------------
__device__ float g_Q[(size_t)Bc*Hc*Sc*Dc];
__device__ float g_K[(size_t)Bc*Hc*Sc*Dc];
__device__ float g_V[(size_t)Bc*Hc*Sc*Dc];

// tf32 2-way splits (stored as fp32 bit patterns with tf32 mantissa)
__device__ float g_Xhi[(size_t)MROWS*DMc];
__device__ float g_Xlo[(size_t)MROWS*DMc];
__device__ float g_Whi[(size_t)NQKVc*DMc];   // W^T: [n][k], k contiguous
__device__ float g_Wlo[(size_t)NQKVc*DMc];

// ---------------------------------------------------------------------------
// tf32 helpers
// ---------------------------------------------------------------------------
__device__ __forceinline__ float f2tf32(float x) {
    uint32_t r;
    asm("cvt.rna.tf32.f32 %0, %1;" : "=r"(r) : "f"(x));
    return __uint_as_float(r);
}
__device__ __forceinline__ void split2(float x, float& hi, float& lo) {
    hi = f2tf32(x);
    lo = f2tf32(x - hi);
}

// m16n8k8 tf32 MMA (row.col), fp32 accumulate — sm_80 feature, sm_100-legal.
__device__ __forceinline__ void mma_tf32(float* c, const uint32_t* a, const uint32_t* b) {
    asm volatile(
        "mma.sync.aligned.m16n8k8.row.col.f32.tf32.tf32.f32 "
        "{%0,%1,%2,%3}, {%4,%5,%6,%7}, {%8,%9}, {%0,%1,%2,%3};"
        : "+f"(c[0]), "+f"(c[1]), "+f"(c[2]), "+f"(c[3])
        : "r"(a[0]), "r"(a[1]), "r"(a[2]), "r"(a[3]), "r"(b[0]), "r"(b[1]));
}

// ---------------------------------------------------------------------------
// Pre-pass: split X (row-major, already k-contiguous)
// ---------------------------------------------------------------------------
__global__ __launch_bounds__(256) void split_x_kernel(const float* __restrict__ X) {
    size_t i = (size_t)blockIdx.x * 256 + threadIdx.x;   // float4 index
    float4 v = ((const float4*)X)[i];
    float hi[4], lo[4], xs[4] = {v.x, v.y, v.z, v.w};
    #pragma unroll
    for (int e = 0; e < 4; e++) split2(xs[e], hi[e], lo[e]);
    ((float4*)g_Xhi)[i] = make_float4(hi[0], hi[1], hi[2], hi[3]);
    ((float4*)g_Xlo)[i] = make_float4(lo[0], lo[1], lo[2], lo[3]);
}

// Pre-pass: transpose + split W [1024][3072] -> Wt [3072][1024]
__global__ void split_w_kernel(const float* __restrict__ W) {
    __shared__ float tile[32][33];
    int n0 = blockIdx.x * 32, k0 = blockIdx.y * 32;
    int tx = threadIdx.x, ty = threadIdx.y;
    for (int i = ty; i < 32; i += 8)
        tile[i][tx] = W[(size_t)(k0 + i) * NQKVc + n0 + tx];
    __syncthreads();
    for (int i = ty; i < 32; i += 8) {
        float hi, lo;
        split2(tile[tx][i], hi, lo);                 // W[k0+tx][n0+i]
        size_t o = (size_t)(n0 + i) * DMc + k0 + tx;
        g_Whi[o] = hi; g_Wlo[o] = lo;
    }
}

// ---------------------------------------------------------------------------
// QKV GEMM on legacy tensor cores: C[4096,3072] = X@W + b via tf32 3-product.
// CTA tile 128x128, K-chunk 32, 8 warps (4m x 2n), warp tile 32m x 64n.
// smem pitch 36 floats -> conflict-free fragment loads (bank = 4*(l/4)+l%4).
// ---------------------------------------------------------------------------
#define KC     32
#define PIT    36
#define TILE_F (128 * PIT)                    // floats per smem tile
#define QKV_SMEM (4 * TILE_F * 4)             // Ah, Al, Bh, Bl

__global__ __launch_bounds__(256, 1) void qkv_mma_kernel(const float* __restrict__ bias) {
    extern __shared__ float sf[];
    float* Ah = sf;
    float* Al = sf + TILE_F;
    float* Bh = sf + 2 * TILE_F;
    float* Bl = sf + 3 * TILE_F;
    const uint32_t* AhU = (const uint32_t*)Ah;
    const uint32_t* AlU = (const uint32_t*)Al;
    const uint32_t* BhU = (const uint32_t*)Bh;
    const uint32_t* BlU = (const uint32_t*)Bl;

    const int tid  = threadIdx.x;
    const int lane = tid & 31;
    const int wid  = tid >> 5;
    const int wm   = wid & 3;            // 4 m-warps
    const int wn   = wid >> 2;           // 2 n-warps
    const int n0   = blockIdx.x * 128;
    const int m0   = blockIdx.y * 128;

    float acc[2][8][4];
    #pragma unroll
    for (int f = 0; f < 2; f++)
        #pragma unroll
        for (int g = 0; g < 8; g++)
            #pragma unroll
            for (int e = 0; e < 4; e++) acc[f][g][e] = 0.f;

    const float* srcs[4] = {g_Xhi + (size_t)m0 * DMc, g_Xlo + (size_t)m0 * DMc,
                            g_Whi + (size_t)n0 * DMc, g_Wlo + (size_t)n0 * DMc};
    float* dsts[4] = {Ah, Al, Bh, Bl};

    for (int kc = 0; kc < DMc / KC; kc++) {
        // Load 4 tiles of [128 rows][32 k] fp32, float4-wide
        #pragma unroll
        for (int t = tid; t < 4096; t += 256) {
            int tl = t >> 10, rem = t & 1023, r = rem >> 3, q = rem & 7;
            float4 v = *(const float4*)(srcs[tl] + (size_t)r * DMc + kc * KC + q * 4);
            *(float4*)(dsts[tl] + r * PIT + q * 4) = v;
        }
        __syncthreads();

        #pragma unroll
        for (int s = 0; s < 4; s++) {                 // 4 k-steps of 8
            uint32_t ah[2][4], al[2][4], bh[8][2], bl[8][2];
            #pragma unroll
            for (int f = 0; f < 2; f++) {
                int r0 = (wm * 32 + f * 16 + (lane >> 2)) * PIT + s * 8 + (lane & 3);
                ah[f][0] = AhU[r0];            ah[f][1] = AhU[r0 + 8 * PIT];
                ah[f][2] = AhU[r0 + 4];        ah[f][3] = AhU[r0 + 8 * PIT + 4];
                al[f][0] = AlU[r0];            al[f][1] = AlU[r0 + 8 * PIT];
                al[f][2] = AlU[r0 + 4];        al[f][3] = AlU[r0 + 8 * PIT + 4];
            }
            #pragma unroll
            for (int g = 0; g < 8; g++) {
                int r0 = (wn * 64 + g * 8 + (lane >> 2)) * PIT + s * 8 + (lane & 3);
                bh[g][0] = BhU[r0];  bh[g][1] = BhU[r0 + 4];
                bl[g][0] = BlU[r0];  bl[g][1] = BlU[r0 + 4];
            }
            #pragma unroll
            for (int f = 0; f < 2; f++)
                #pragma unroll
                for (int g = 0; g < 8; g++) {
                    mma_tf32(acc[f][g], ah[f], bh[g]);   // hi*hi
                    mma_tf32(acc[f][g], ah[f], bl[g]);   // hi*lo
                    mma_tf32(acc[f][g], al[f], bh[g]);   // lo*hi
                }
        }
        __syncthreads();
    }

    // Epilogue: +bias, scatter to head-major Q/K/V
    #pragma unroll
    for (int f = 0; f < 2; f++) {
        int rowg = m0 + wm * 32 + f * 16 + (lane >> 2);
        #pragma unroll
        for (int g = 0; g < 8; g++) {
            int col0 = n0 + wn * 64 + g * 8 + 2 * (lane & 3);
            #pragma unroll
            for (int e = 0; e < 4; e++) {
                int r  = rowg + (e >> 1) * 8;
                int cg = col0 + (e & 1);
                float v = acc[f][g][e] + bias[cg];
                int b = r >> 11, ss = r & 2047;
                int h = cg / 192, rr = cg - h * 192;
                size_t base = ((size_t)(b * Hc + h) * Sc + ss) * Dc;
                if (rr < 64)       g_Q[base + rr]       = v;
                else if (rr < 128) g_K[base + rr - 64]  = v;
                else               g_V[base + rr - 128] = v;
            }
        }
    }
}

// ---------------------------------------------------------------------------
// Attention: fp32 SIMT flash attention, conflict-free transposed smem.
// Block = 128 q-rows; KV tiles of 128. 256 threads (16x16), 8x8 score frag,
// 8x4 O frag. Q/K/P stored [d][s] with odd pitch 133 -> conflict-free.
// ---------------------------------------------------------------------------
#define P1 133
#define ATTN_SMEM ((64*P1 + 64*P1 + 128*68 + 128*P1) * 4)

__global__ __launch_bounds__(256) void attn_kernel(float* __restrict__ out) {
    extern __shared__ float sf[];
    float* Qt = sf;                       // [64][P1]  (d-major)
    float* Kt = sf + 64 * P1;             // [64][P1]
    float* Vs = sf + 2 * 64 * P1;         // [128][68] (s-major)
    float* Pt = Vs + 128 * 68;            // [128][P1] ([kv][q])

    const int qt = blockIdx.x, h = blockIdx.y, b = blockIdx.z;
    const int tid = threadIdx.x;
    const int tx = tid & 15, ty = tid >> 4;

    const size_t hb = (size_t)(b * Hc + h) * Sc * Dc;
    const float* Qp = g_Q + hb + (size_t)qt * 128 * Dc;
    const float* Kp = g_K + hb;
    const float* Vp = g_V + hb;

    for (int t = tid; t < 2048; t += 256) {
        int row = t >> 4, c4 = t & 15;
        float4 v = *(const float4*)(Qp + row * 64 + c4 * 4);
        int d = c4 * 4;
        Qt[(d + 0) * P1 + row] = v.x;
        Qt[(d + 1) * P1 + row] = v.y;
        Qt[(d + 2) * P1 + row] = v.z;
        Qt[(d + 3) * P1 + row] = v.w;
    }

    float m[8], l[8], O[8][4];
    #pragma unroll
    for (int i = 0; i < 8; i++) {
        m[i] = -1e30f; l[i] = 0.f;
        #pragma unroll
        for (int j = 0; j < 4; j++) O[i][j] = 0.f;
    }

    for (int kt = 0; kt < Sc / 128; kt++) {
        for (int t = tid; t < 2048; t += 256) {
            int row = t >> 4, c4 = t & 15;
            float4 kv = *(const float4*)(Kp + (size_t)(kt * 128 + row) * 64 + c4 * 4);
            int d = c4 * 4;
            Kt[(d + 0) * P1 + row] = kv.x;
            Kt[(d + 1) * P1 + row] = kv.y;
            Kt[(d + 2) * P1 + row] = kv.z;
            Kt[(d + 3) * P1 + row] = kv.w;
            float4 vv = *(const float4*)(Vp + (size_t)(kt * 128 + row) * 64 + c4 * 4);
            *(float4*)(Vs + row * 68 + c4 * 4) = vv;
        }
        __syncthreads();

        float s[8][8];
        #pragma unroll
        for (int i = 0; i < 8; i++)
            #pragma unroll
            for (int j = 0; j < 8; j++) s[i][j] = 0.f;

        #pragma unroll 4
        for (int kk = 0; kk < 64; kk++) {
            float q[8], kw[8];
            #pragma unroll
            for (int i = 0; i < 8; i++) q[i] = Qt[kk * P1 + 8 * ty + i];   // broadcast
            #pragma unroll
            for (int j = 0; j < 8; j++) kw[j] = Kt[kk * P1 + tx + 16 * j]; // conflict-free
            #pragma unroll
            for (int i = 0; i < 8; i++)
                #pragma unroll
                for (int j = 0; j < 8; j++) s[i][j] += q[i] * kw[j];
        }

        #pragma unroll
        for (int i = 0; i < 8; i++) {
            #pragma unroll
            for (int j = 0; j < 8; j++) s[i][j] *= 8.0f;     // * sqrt(64)
            float rm = s[i][0];
            #pragma unroll
            for (int j = 1; j < 8; j++) rm = fmaxf(rm, s[i][j]);
            #pragma unroll
            for (int o = 8; o >= 1; o >>= 1)
                rm = fmaxf(rm, __shfl_xor_sync(0xffffffffu, rm, o));
            float mn = fmaxf(m[i], rm);
            float corr = __expf(m[i] - mn);
            float rs = 0.f;
            #pragma unroll
            for (int j = 0; j < 8; j++) { s[i][j] = __expf(s[i][j] - mn); rs += s[i][j]; }
            #pragma unroll
            for (int o = 8; o >= 1; o >>= 1)
                rs += __shfl_xor_sync(0xffffffffu, rs, o);
            l[i] = l[i] * corr + rs;
            m[i] = mn;
            #pragma unroll
            for (int j = 0; j < 4; j++) O[i][j] *= corr;
        }

        #pragma unroll
        for (int j = 0; j < 8; j++)
            #pragma unroll
            for (int i = 0; i < 8; i++)
                Pt[(tx + 16 * j) * P1 + 8 * ty + i] = s[i][j];
        __syncthreads();

        #pragma unroll 4
        for (int kk = 0; kk < 128; kk++) {
            float p[8], v[4];
            #pragma unroll
            for (int i = 0; i < 8; i++) p[i] = Pt[kk * P1 + 8 * ty + i];   // broadcast
            #pragma unroll
            for (int j = 0; j < 4; j++) v[j] = Vs[kk * 68 + tx + 16 * j];  // conflict-free
            #pragma unroll
            for (int i = 0; i < 8; i++)
                #pragma unroll
                for (int j = 0; j < 4; j++) O[i][j] += p[i] * v[j];
        }
        __syncthreads();
    }

    #pragma unroll
    for (int i = 0; i < 8; i++) {
        int s_ = qt * 128 + 8 * ty + i;
        float inv = 1.0f / l[i];
        #pragma unroll
        for (int j = 0; j < 4; j++)
            out[((size_t)b * Sc + s_) * (Hc * Dc) + h * Dc + tx + 16 * j] = O[i][j] * inv;
    }
}

// ---------------------------------------------------------------------------
extern "C" void kernel_launch(void* const* d_in, const int* in_sizes, int n_in,
                              void* d_out, int out_size) {
    const float* X    = (const float*)d_in[0];   // [B,S,1024]
    const float* W    = (const float*)d_in[1];   // [1024,3072]
    const float* bias = (const float*)d_in[2];   // [3072]
    float* out = (float*)d_out;                  // [B,S,1024]

    split_x_kernel<<<(MROWS * DMc) / (256 * 4), 256>>>(X);
    split_w_kernel<<<dim3(NQKVc / 32, DMc / 32), dim3(32, 8)>>>(W);

    cudaFuncSetAttribute(qkv_mma_kernel, cudaFuncAttributeMaxDynamicSharedMemorySize, QKV_SMEM);
    qkv_mma_kernel<<<dim3(NQKVc / 128, MROWS / 128), 256, QKV_SMEM>>>(bias);

    cudaFuncSetAttribute(attn_kernel, cudaFuncAttributeMaxDynamicSharedMemorySize, ATTN_SMEM);
    attn_kernel<<<dim3(Sc / 128, Hc, Bc), 256, ATTN_SMEM>>>(out);
}

// round 4
// speedup vs baseline: 2.6073x; 2.5406x over previous
#include <cuda_runtime.h>
#include <cuda_bf16.h>
#include <cstdint>

#define Bc    2
#define Sc    2048
#define Hc    16
#define Dc    64
#define DMc   1024
#define NQKVc 3072
#define MROWS (Bc*Sc)          // 4096
#define BH    (Bc*Hc)          // 32

// ---------------------------------------------------------------------------
// Static device scratch
// ---------------------------------------------------------------------------
__device__ __nv_bfloat16 g_Xh[(size_t)MROWS*DMc];
__device__ __nv_bfloat16 g_Xl[(size_t)MROWS*DMc];
__device__ __nv_bfloat16 g_Wh[(size_t)NQKVc*DMc];   // W^T [n][k]
__device__ __nv_bfloat16 g_Wl[(size_t)NQKVc*DMc];

__device__ __nv_bfloat16 g_Qh[(size_t)BH*Sc*Dc];    // [bh][s][d]
__device__ __nv_bfloat16 g_Ql[(size_t)BH*Sc*Dc];
__device__ __nv_bfloat16 g_Kh[(size_t)BH*Sc*Dc];    // [bh][s][d]
__device__ __nv_bfloat16 g_Kl[(size_t)BH*Sc*Dc];
__device__ __nv_bfloat16 g_Vth[(size_t)BH*Dc*Sc];   // [bh][d][s]  (transposed)
__device__ __nv_bfloat16 g_Vtl[(size_t)BH*Dc*Sc];

// ---------------------------------------------------------------------------
// Helpers
// ---------------------------------------------------------------------------
__device__ __forceinline__ uint32_t smem_u32(const void* p) {
    uint32_t a;
    asm("{ .reg .u64 t; cvta.to.shared.u64 t, %1; cvt.u32.u64 %0, t; }" : "=r"(a) : "l"(p));
    return a;
}
__device__ __forceinline__ void ldsm4(uint32_t& d0, uint32_t& d1, uint32_t& d2,
                                      uint32_t& d3, uint32_t addr) {
    asm volatile("ldmatrix.sync.aligned.m8n8.x4.shared.b16 {%0,%1,%2,%3}, [%4];"
                 : "=r"(d0), "=r"(d1), "=r"(d2), "=r"(d3) : "r"(addr));
}
__device__ __forceinline__ void mma_bf16(float* c, const uint32_t* a,
                                         uint32_t b0, uint32_t b1) {
    asm volatile(
        "mma.sync.aligned.m16n8k16.row.col.f32.bf16.bf16.f32 "
        "{%0,%1,%2,%3}, {%4,%5,%6,%7}, {%8,%9}, {%0,%1,%2,%3};"
        : "+f"(c[0]), "+f"(c[1]), "+f"(c[2]), "+f"(c[3])
        : "r"(a[0]), "r"(a[1]), "r"(a[2]), "r"(a[3]), "r"(b0), "r"(b1));
}
// pack: low half = f_lo, high half = f_hi
__device__ __forceinline__ uint32_t pack2(float f_lo, float f_hi) {
    uint32_t r;
    asm("cvt.rn.bf16x2.f32 %0, %1, %2;" : "=r"(r) : "f"(f_hi), "f"(f_lo));
    return r;
}
__device__ __forceinline__ void split2b(float x, __nv_bfloat16& h, __nv_bfloat16& l) {
    h = __float2bfloat16_rn(x);
    l = __float2bfloat16_rn(x - __bfloat162float(h));
}

// ---------------------------------------------------------------------------
// Pre-pass: split X
// ---------------------------------------------------------------------------
__global__ __launch_bounds__(256) void split_x_kernel(const float* __restrict__ X) {
    size_t i = (size_t)blockIdx.x * 256 + threadIdx.x;   // float4 index
    float4 v = ((const float4*)X)[i];
    float xs[4] = {v.x, v.y, v.z, v.w};
    __nv_bfloat16 h[4], l[4];
    #pragma unroll
    for (int e = 0; e < 4; e++) split2b(xs[e], h[e], l[e]);
    *(uint2*)&g_Xh[4 * i] = *(uint2*)h;
    *(uint2*)&g_Xl[4 * i] = *(uint2*)l;
}

// Pre-pass: transpose + split W [1024][3072] -> Wt [3072][1024]
__global__ void split_w_kernel(const float* __restrict__ W) {
    __shared__ float tile[32][33];
    int n0 = blockIdx.x * 32, k0 = blockIdx.y * 32;
    int tx = threadIdx.x, ty = threadIdx.y;
    for (int i = ty; i < 32; i += 8)
        tile[i][tx] = W[(size_t)(k0 + i) * NQKVc + n0 + tx];
    __syncthreads();
    for (int i = ty; i < 32; i += 8) {
        __nv_bfloat16 h, l;
        split2b(tile[tx][i], h, l);                  // W[k0+tx][n0+i]
        size_t o = (size_t)(n0 + i) * DMc + k0 + tx;
        g_Wh[o] = h; g_Wl[o] = l;
    }
}

// ---------------------------------------------------------------------------
// QKV GEMM: C[4096,3072] = X@W + b via bf16 3-product mma.sync.m16n8k16.
// CTA 128x128, k-chunk 32; 8 warps (4m x 2n), warp 32m x 64n.
// smem tiles [128 rows][20 words] (16 used) -> conflict-free ldmatrix.
// ---------------------------------------------------------------------------
#define QPW   20
#define QTW   (128 * QPW)                 // words per tile
#define QKV_SMEM (4 * QTW * 4)            // Xh, Xl, Wh, Wl

__global__ __launch_bounds__(256, 2) void qkv_mma_kernel(const float* __restrict__ bias) {
    extern __shared__ uint32_t sw[];
    uint32_t* Xh = sw;
    uint32_t* Xl = sw + QTW;
    uint32_t* Bh = sw + 2 * QTW;
    uint32_t* Bl = sw + 3 * QTW;
    const uint32_t sb = smem_u32(sw);

    const int tid  = threadIdx.x;
    const int lane = tid & 31;
    const int wid  = tid >> 5;
    const int wm   = wid & 3;
    const int wn   = wid >> 2;
    const int n0   = blockIdx.x * 128;
    const int m0   = blockIdx.y * 128;

    float acc[2][8][4];
    #pragma unroll
    for (int mt = 0; mt < 2; mt++)
        #pragma unroll
        for (int j = 0; j < 8; j++)
            #pragma unroll
            for (int e = 0; e < 4; e++) acc[mt][j][e] = 0.f;

    // ldmatrix per-thread offsets (bytes)
    const uint32_t a_row = lane & 15;
    const uint32_t a_kw  = (lane & 16) >> 2;          // 0 or 4 words
    const uint32_t b_row = (lane & 7) + ((lane & 16) >> 1);
    const uint32_t b_kw  = (lane & 8) >> 1;           // 0 or 4 words

    const uint4* srcs[4] = {
        (const uint4*)g_Xh + (size_t)m0 * 128,   // row stride 1024 bf16 = 128 uint4
        (const uint4*)g_Xl + (size_t)m0 * 128,
        (const uint4*)g_Wh + (size_t)n0 * 128,
        (const uint4*)g_Wl + (size_t)n0 * 128};
    uint4* dsts[4] = {(uint4*)Xh, (uint4*)Xl, (uint4*)Bh, (uint4*)Bl};

    for (int kc = 0; kc < DMc / 32; kc++) {
        // load 4 tiles: each 128 rows x 16 words = 512 uint4
        #pragma unroll
        for (int t = tid; t < 2048; t += 256) {
            int tl = t >> 9, rem = t & 511, r = rem >> 2, q = rem & 3;
            uint4 v = srcs[tl][(size_t)r * 128 + kc * 4 + q];
            dsts[tl][r * 5 + q] = v;     // 20 words = 5 uint4 per row
        }
        __syncthreads();

        #pragma unroll
        for (int s = 0; s < 2; s++) {
            uint32_t axh[2][4], axl[2][4];
            #pragma unroll
            for (int mt = 0; mt < 2; mt++) {
                uint32_t ra = ((wm * 32 + mt * 16 + a_row) * QPW + s * 8 + a_kw) * 4;
                ldsm4(axh[mt][0], axh[mt][1], axh[mt][2], axh[mt][3], sb + ra);
                ldsm4(axl[mt][0], axl[mt][1], axl[mt][2], axl[mt][3], sb + QTW * 4 + ra);
            }
            #pragma unroll
            for (int j2 = 0; j2 < 4; j2++) {
                uint32_t rb = ((wn * 64 + j2 * 16 + b_row) * QPW + s * 8 + b_kw) * 4;
                uint32_t bh0, bh1, bh2, bh3, bl0, bl1, bl2, bl3;
                ldsm4(bh0, bh1, bh2, bh3, sb + 2 * QTW * 4 + rb);
                ldsm4(bl0, bl1, bl2, bl3, sb + 3 * QTW * 4 + rb);
                #pragma unroll
                for (int mt = 0; mt < 2; mt++) {
                    mma_bf16(acc[mt][2 * j2],     axh[mt], bh0, bh1);
                    mma_bf16(acc[mt][2 * j2],     axh[mt], bl0, bl1);
                    mma_bf16(acc[mt][2 * j2],     axl[mt], bh0, bh1);
                    mma_bf16(acc[mt][2 * j2 + 1], axh[mt], bh2, bh3);
                    mma_bf16(acc[mt][2 * j2 + 1], axh[mt], bl2, bl3);
                    mma_bf16(acc[mt][2 * j2 + 1], axl[mt], bh2, bh3);
                }
            }
        }
        __syncthreads();
    }

    // Epilogue: +bias, split to bf16 hi/lo, scatter (Q,K natural; V transposed)
    #pragma unroll
    for (int mt = 0; mt < 2; mt++) {
        #pragma unroll
        for (int j = 0; j < 8; j++) {
            #pragma unroll
            for (int e = 0; e < 4; e++) {
                int r  = m0 + wm * 32 + mt * 16 + (lane >> 2) + (e >> 1) * 8;
                int cg = n0 + wn * 64 + j * 8 + 2 * (lane & 3) + (e & 1);
                float v = acc[mt][j][e] + __ldg(&bias[cg]);
                __nv_bfloat16 h, l;
                split2b(v, h, l);
                int b = r >> 11, s = r & 2047;
                int hh = cg / 192, rr = cg - hh * 192;
                int bh = b * Hc + hh;
                if (rr < 64) {
                    size_t o = ((size_t)bh * Sc + s) * Dc + rr;
                    g_Qh[o] = h; g_Ql[o] = l;
                } else if (rr < 128) {
                    size_t o = ((size_t)bh * Sc + s) * Dc + rr - 64;
                    g_Kh[o] = h; g_Kl[o] = l;
                } else {
                    size_t o = ((size_t)bh * Dc + rr - 128) * Sc + s;
                    g_Vth[o] = h; g_Vtl[o] = l;
                }
            }
        }
    }
}

// ---------------------------------------------------------------------------
// Attention: FA2 on mma.sync bf16. CTA = 128 q rows, 8 warps x 16 rows.
// KV tile 128. QK^T 3 products; P single bf16 (l summed over rounded P);
// PV 2 products (V hi+lo). K smem [128][36w], Vt smem [64][68w].
// ---------------------------------------------------------------------------
#define KPW 36
#define VPW 68
#define KH0 0
#define KL0 (128 * KPW)
#define VH0 (2 * 128 * KPW)
#define VL0 (VH0 + 64 * VPW)
#define ATTN_WORDS (VL0 + 64 * VPW)
#define ATTN_SMEM (ATTN_WORDS * 4)

__global__ __launch_bounds__(256) void attn_kernel(float* __restrict__ out) {
    extern __shared__ uint32_t sw[];
    const uint32_t sb = smem_u32(sw);

    const int qt = blockIdx.x, h = blockIdx.y, b = blockIdx.z;
    const int bh = b * Hc + h;
    const int tid = threadIdx.x;
    const int lane = tid & 31;
    const int wid = tid >> 5;
    const int qg = qt * 128 + wid * 16;      // warp's first q row (within head)

    // ---- preload Q fragments from gmem (A operand, k = d, 4 k-steps) ----
    uint32_t qh[4][4], ql[4][4];
    {
        const uint32_t* Qhw = (const uint32_t*)g_Qh + (size_t)bh * Sc * 32;
        const uint32_t* Qlw = (const uint32_t*)g_Ql + (size_t)bh * Sc * 32;
        int r0 = qg + (lane >> 2);
        #pragma unroll
        for (int s = 0; s < 4; s++) {
            int w0 = s * 8 + (lane & 3);
            qh[s][0] = Qhw[(size_t)r0 * 32 + w0];
            qh[s][1] = Qhw[(size_t)(r0 + 8) * 32 + w0];
            qh[s][2] = Qhw[(size_t)r0 * 32 + w0 + 4];
            qh[s][3] = Qhw[(size_t)(r0 + 8) * 32 + w0 + 4];
            ql[s][0] = Qlw[(size_t)r0 * 32 + w0];
            ql[s][1] = Qlw[(size_t)(r0 + 8) * 32 + w0];
            ql[s][2] = Qlw[(size_t)r0 * 32 + w0 + 4];
            ql[s][3] = Qlw[(size_t)(r0 + 8) * 32 + w0 + 4];
        }
    }

    float o[8][4];
    #pragma unroll
    for (int nd = 0; nd < 8; nd++)
        #pragma unroll
        for (int e = 0; e < 4; e++) o[nd][e] = 0.f;
    float m0 = -1e30f, m1 = -1e30f, l0 = 0.f, l1 = 0.f;

    // ldmatrix offsets
    const uint32_t f_row = (lane & 7) + ((lane & 16) >> 1);
    const uint32_t f_kw  = (lane & 8) >> 1;

    const uint4* Kh4 = (const uint4*)g_Kh + (size_t)bh * Sc * 8;
    const uint4* Kl4 = (const uint4*)g_Kl + (size_t)bh * Sc * 8;
    const uint4* Vh4 = (const uint4*)g_Vth + (size_t)bh * Dc * 256;
    const uint4* Vl4 = (const uint4*)g_Vtl + (size_t)bh * Dc * 256;
    uint4* s4 = (uint4*)sw;

    for (int kt = 0; kt < Sc / 128; kt++) {
        const int kv0 = kt * 128;
        // ---- load K tile (hi/lo): 128 rows x 32 words each ----
        {
            int r = tid >> 1, half = tid & 1;
            #pragma unroll
            for (int q = 0; q < 4; q++) {
                s4[(KH0 >> 2) + r * 9 + half * 4 + q] = Kh4[(size_t)(kv0 + r) * 8 + half * 4 + q];
                s4[(KL0 >> 2) + r * 9 + half * 4 + q] = Kl4[(size_t)(kv0 + r) * 8 + half * 4 + q];
            }
            // ---- load Vt tile: 64 rows x 64 words each ----
            int vr = tid >> 2, c = tid & 3;
            #pragma unroll
            for (int k = 0; k < 4; k++) {
                s4[(VH0 >> 2) + vr * 17 + c + 4 * k] = Vh4[(size_t)vr * 256 + kt * 16 + c + 4 * k];
                s4[(VL0 >> 2) + vr * 17 + c + 4 * k] = Vl4[(size_t)vr * 256 + kt * 16 + c + 4 * k];
            }
        }
        __syncthreads();

        // ---- scores = Q K^T ----
        float sc[16][4];
        #pragma unroll
        for (int j = 0; j < 16; j++)
            #pragma unroll
            for (int e = 0; e < 4; e++) sc[j][e] = 0.f;

        #pragma unroll
        for (int j2 = 0; j2 < 8; j2++) {
            uint32_t rbase = (j2 * 16 + f_row) * KPW;
            #pragma unroll
            for (int s = 0; s < 4; s++) {
                uint32_t ra = sb + (rbase + s * 8 + f_kw) * 4;
                uint32_t bh0, bh1, bh2, bh3, bl0, bl1, bl2, bl3;
                ldsm4(bh0, bh1, bh2, bh3, ra + KH0 * 4);
                ldsm4(bl0, bl1, bl2, bl3, ra + KL0 * 4);
                mma_bf16(sc[2 * j2],     qh[s], bh0, bh1);
                mma_bf16(sc[2 * j2],     qh[s], bl0, bl1);
                mma_bf16(sc[2 * j2],     ql[s], bh0, bh1);
                mma_bf16(sc[2 * j2 + 1], qh[s], bh2, bh3);
                mma_bf16(sc[2 * j2 + 1], qh[s], bl2, bl3);
                mma_bf16(sc[2 * j2 + 1], ql[s], bh2, bh3);
            }
        }

        // ---- online softmax ----
        float tm0 = -1e30f, tm1 = -1e30f;
        #pragma unroll
        for (int j = 0; j < 16; j++) {
            #pragma unroll
            for (int e = 0; e < 4; e++) sc[j][e] *= 8.0f;   // * sqrt(64)
            tm0 = fmaxf(tm0, fmaxf(sc[j][0], sc[j][1]));
            tm1 = fmaxf(tm1, fmaxf(sc[j][2], sc[j][3]));
        }
        tm0 = fmaxf(tm0, __shfl_xor_sync(0xffffffffu, tm0, 1));
        tm0 = fmaxf(tm0, __shfl_xor_sync(0xffffffffu, tm0, 2));
        tm1 = fmaxf(tm1, __shfl_xor_sync(0xffffffffu, tm1, 1));
        tm1 = fmaxf(tm1, __shfl_xor_sync(0xffffffffu, tm1, 2));
        float mn0 = fmaxf(m0, tm0), mn1 = fmaxf(m1, tm1);
        float c0 = __expf(m0 - mn0), c1 = __expf(m1 - mn1);

        // exp, round to bf16, sum rounded values, pack P fragments
        uint32_t pk[16][2];
        float ls0 = 0.f, ls1 = 0.f;
        #pragma unroll
        for (int j = 0; j < 16; j++) {
            float p0 = __expf(sc[j][0] - mn0);
            float p1 = __expf(sc[j][1] - mn0);
            float p2 = __expf(sc[j][2] - mn1);
            float p3 = __expf(sc[j][3] - mn1);
            float r0 = __bfloat162float(__float2bfloat16_rn(p0));
            float r1 = __bfloat162float(__float2bfloat16_rn(p1));
            float r2 = __bfloat162float(__float2bfloat16_rn(p2));
            float r3 = __bfloat162float(__float2bfloat16_rn(p3));
            ls0 += r0 + r1;
            ls1 += r2 + r3;
            pk[j][0] = pack2(r0, r1);
            pk[j][1] = pack2(r2, r3);
        }
        ls0 += __shfl_xor_sync(0xffffffffu, ls0, 1);
        ls0 += __shfl_xor_sync(0xffffffffu, ls0, 2);
        ls1 += __shfl_xor_sync(0xffffffffu, ls1, 1);
        ls1 += __shfl_xor_sync(0xffffffffu, ls1, 2);
        l0 = l0 * c0 + ls0;
        l1 = l1 * c1 + ls1;
        m0 = mn0; m1 = mn1;
        #pragma unroll
        for (int nd = 0; nd < 8; nd++) {
            o[nd][0] *= c0; o[nd][1] *= c0;
            o[nd][2] *= c1; o[nd][3] *= c1;
        }

        // ---- O += P~ @ V ----
        #pragma unroll
        for (int g = 0; g < 4; g++) {
            uint32_t rbase = (g * 16 + f_row) * VPW;
            #pragma unroll
            for (int t = 0; t < 8; t++) {
                uint32_t ra = sb + (rbase + t * 8 + f_kw) * 4;
                uint32_t vh0, vh1, vh2, vh3, vl0, vl1, vl2, vl3;
                ldsm4(vh0, vh1, vh2, vh3, ra + VH0 * 4);
                ldsm4(vl0, vl1, vl2, vl3, ra + VL0 * 4);
                uint32_t a[4] = {pk[2 * t][0], pk[2 * t][1], pk[2 * t + 1][0], pk[2 * t + 1][1]};
                mma_bf16(o[2 * g],     a, vh0, vh1);
                mma_bf16(o[2 * g],     a, vl0, vl1);
                mma_bf16(o[2 * g + 1], a, vh2, vh3);
                mma_bf16(o[2 * g + 1], a, vl2, vl3);
            }
        }
        __syncthreads();
    }

    // ---- epilogue ----
    float inv0 = 1.0f / l0, inv1 = 1.0f / l1;
    int r0 = qg + (lane >> 2);
    #pragma unroll
    for (int nd = 0; nd < 8; nd++) {
        int d = h * Dc + nd * 8 + 2 * (lane & 3);
        float2 v0 = make_float2(o[nd][0] * inv0, o[nd][1] * inv0);
        float2 v1 = make_float2(o[nd][2] * inv1, o[nd][3] * inv1);
        *(float2*)(out + ((size_t)b * Sc + r0) * 1024 + d)     = v0;
        *(float2*)(out + ((size_t)b * Sc + r0 + 8) * 1024 + d) = v1;
    }
}

// ---------------------------------------------------------------------------
extern "C" void kernel_launch(void* const* d_in, const int* in_sizes, int n_in,
                              void* d_out, int out_size) {
    const float* X    = (const float*)d_in[0];
    const float* W    = (const float*)d_in[1];
    const float* bias = (const float*)d_in[2];
    float* out = (float*)d_out;

    split_x_kernel<<<(MROWS * DMc) / (256 * 4), 256>>>(X);
    split_w_kernel<<<dim3(NQKVc / 32, DMc / 32), dim3(32, 8)>>>(W);

    cudaFuncSetAttribute(qkv_mma_kernel, cudaFuncAttributeMaxDynamicSharedMemorySize, QKV_SMEM);
    qkv_mma_kernel<<<dim3(NQKVc / 128, MROWS / 128), 256, QKV_SMEM>>>(bias);

    cudaFuncSetAttribute(attn_kernel, cudaFuncAttributeMaxDynamicSharedMemorySize, ATTN_SMEM);
    attn_kernel<<<dim3(Sc / 128, Hc, Bc), 256, ATTN_SMEM>>>(out);
}

// round 5
// speedup vs baseline: 2.9072x; 1.1150x over previous
#include <cuda_runtime.h>
#include <cuda_bf16.h>
#include <cstdint>

#define Bc    2
#define Sc    2048
#define Hc    16
#define Dc    64
#define DMc   1024
#define NQKVc 3072
#define MROWS (Bc*Sc)
#define BH    (Bc*Hc)

// ---------------------------------------------------------------------------
__device__ __nv_bfloat16 g_Xh[(size_t)MROWS*DMc];
__device__ __nv_bfloat16 g_Xl[(size_t)MROWS*DMc];
__device__ __nv_bfloat16 g_Wh[(size_t)NQKVc*DMc];
__device__ __nv_bfloat16 g_Wl[(size_t)NQKVc*DMc];

__device__ __nv_bfloat16 g_Qh[(size_t)BH*Sc*Dc];
__device__ __nv_bfloat16 g_Ql[(size_t)BH*Sc*Dc];
__device__ __nv_bfloat16 g_Kh[(size_t)BH*Sc*Dc];
__device__ __nv_bfloat16 g_Kl[(size_t)BH*Sc*Dc];
__device__ __nv_bfloat16 g_Vth[(size_t)BH*Dc*Sc];
__device__ __nv_bfloat16 g_Vtl[(size_t)BH*Dc*Sc];

// ---------------------------------------------------------------------------
__device__ __forceinline__ uint32_t smem_u32(const void* p) {
    uint32_t a;
    asm("{ .reg .u64 t; cvta.to.shared.u64 t, %1; cvt.u32.u64 %0, t; }" : "=r"(a) : "l"(p));
    return a;
}
__device__ __forceinline__ void ldsm4(uint32_t& d0, uint32_t& d1, uint32_t& d2,
                                      uint32_t& d3, uint32_t addr) {
    asm volatile("ldmatrix.sync.aligned.m8n8.x4.shared.b16 {%0,%1,%2,%3}, [%4];"
                 : "=r"(d0), "=r"(d1), "=r"(d2), "=r"(d3) : "r"(addr));
}
__device__ __forceinline__ void mma_bf16(float* c, const uint32_t* a,
                                         uint32_t b0, uint32_t b1) {
    asm volatile(
        "mma.sync.aligned.m16n8k16.row.col.f32.bf16.bf16.f32 "
        "{%0,%1,%2,%3}, {%4,%5,%6,%7}, {%8,%9}, {%0,%1,%2,%3};"
        : "+f"(c[0]), "+f"(c[1]), "+f"(c[2]), "+f"(c[3])
        : "r"(a[0]), "r"(a[1]), "r"(a[2]), "r"(a[3]), "r"(b0), "r"(b1));
}
__device__ __forceinline__ uint32_t pack2(float f_lo, float f_hi) {
    uint32_t r;
    asm("cvt.rn.bf16x2.f32 %0, %1, %2;" : "=r"(r) : "f"(f_hi), "f"(f_lo));
    return r;
}
__device__ __forceinline__ void split2b(float x, __nv_bfloat16& h, __nv_bfloat16& l) {
    h = __float2bfloat16_rn(x);
    l = __float2bfloat16_rn(x - __bfloat162float(h));
}
__device__ __forceinline__ void cpa16(uint32_t dst, const void* src) {
    asm volatile("cp.async.cg.shared.global [%0], [%1], 16;" :: "r"(dst), "l"(src) : "memory");
}
#define CPA_COMMIT() asm volatile("cp.async.commit_group;" ::: "memory")
#define CPA_WAIT(n)  asm volatile("cp.async.wait_group %0;" :: "n"(n) : "memory")

// ---------------------------------------------------------------------------
__global__ __launch_bounds__(256) void split_x_kernel(const float* __restrict__ X) {
    size_t i = (size_t)blockIdx.x * 256 + threadIdx.x;
    float4 v = ((const float4*)X)[i];
    float xs[4] = {v.x, v.y, v.z, v.w};
    __nv_bfloat16 h[4], l[4];
    #pragma unroll
    for (int e = 0; e < 4; e++) split2b(xs[e], h[e], l[e]);
    *(uint2*)&g_Xh[4 * i] = *(uint2*)h;
    *(uint2*)&g_Xl[4 * i] = *(uint2*)l;
}

__global__ void split_w_kernel(const float* __restrict__ W) {
    __shared__ float tile[32][33];
    int n0 = blockIdx.x * 32, k0 = blockIdx.y * 32;
    int tx = threadIdx.x, ty = threadIdx.y;
    for (int i = ty; i < 32; i += 8)
        tile[i][tx] = W[(size_t)(k0 + i) * NQKVc + n0 + tx];
    __syncthreads();
    for (int i = ty; i < 32; i += 8) {
        __nv_bfloat16 h, l;
        split2b(tile[tx][i], h, l);
        size_t o = (size_t)(n0 + i) * DMc + k0 + tx;
        g_Wh[o] = h; g_Wl[o] = l;
    }
}

// ---------------------------------------------------------------------------
// QKV GEMM: bf16 3-product m16n8k16, cp.async double-buffered k-chunks of 32.
// ---------------------------------------------------------------------------
#define QPW     20
#define QTW     (128 * QPW)                 // words per tile
#define QSTAGEW (4 * QTW)                   // words per stage (4 tiles)
#define QKV_SMEM (2 * QSTAGEW * 4)

__global__ __launch_bounds__(256, 2) void qkv_mma_kernel(const float* __restrict__ bias) {
    extern __shared__ uint32_t sw[];
    const uint32_t sb = smem_u32(sw);

    const int tid  = threadIdx.x;
    const int lane = tid & 31;
    const int wid  = tid >> 5;
    const int wm   = wid & 3;
    const int wn   = wid >> 2;
    const int n0   = blockIdx.x * 128;
    const int m0   = blockIdx.y * 128;

    float acc[2][8][4];
    #pragma unroll
    for (int mt = 0; mt < 2; mt++)
        #pragma unroll
        for (int j = 0; j < 8; j++)
            #pragma unroll
            for (int e = 0; e < 4; e++) acc[mt][j][e] = 0.f;

    const uint32_t a_row = lane & 15;
    const uint32_t a_kw  = (lane & 16) >> 2;
    const uint32_t b_row = (lane & 7) + ((lane & 16) >> 1);
    const uint32_t b_kw  = (lane & 8) >> 1;

    const uint4* srcs[4] = {
        (const uint4*)g_Xh + (size_t)m0 * 128,
        (const uint4*)g_Xl + (size_t)m0 * 128,
        (const uint4*)g_Wh + (size_t)n0 * 128,
        (const uint4*)g_Wl + (size_t)n0 * 128};

    // async-load one k-chunk into stage buf
    auto load_chunk = [&](int buf, int kc) {
        uint32_t base = sb + (buf * QSTAGEW) * 4;
        #pragma unroll
        for (int t = tid; t < 2048; t += 256) {
            int tl = t >> 9, rem = t & 511, r = rem >> 2, q = rem & 3;
            cpa16(base + (tl * QTW + r * QPW + q * 4) * 4,
                  srcs[tl] + (size_t)r * 128 + kc * 4 + q);
        }
    };

    load_chunk(0, 0);
    CPA_COMMIT();

    for (int kc = 0; kc < DMc / 32; kc++) {
        int buf = kc & 1;
        if (kc + 1 < DMc / 32) { load_chunk(buf ^ 1, kc + 1); CPA_COMMIT(); CPA_WAIT(1); }
        else                   { CPA_WAIT(0); }
        __syncthreads();

        uint32_t stage = sb + (buf * QSTAGEW) * 4;
        #pragma unroll
        for (int s = 0; s < 2; s++) {
            uint32_t axh[2][4], axl[2][4];
            #pragma unroll
            for (int mt = 0; mt < 2; mt++) {
                uint32_t ra = ((wm * 32 + mt * 16 + a_row) * QPW + s * 8 + a_kw) * 4;
                ldsm4(axh[mt][0], axh[mt][1], axh[mt][2], axh[mt][3], stage + ra);
                ldsm4(axl[mt][0], axl[mt][1], axl[mt][2], axl[mt][3], stage + QTW * 4 + ra);
            }
            #pragma unroll
            for (int j2 = 0; j2 < 4; j2++) {
                uint32_t rb = ((wn * 64 + j2 * 16 + b_row) * QPW + s * 8 + b_kw) * 4;
                uint32_t bh0, bh1, bh2, bh3, bl0, bl1, bl2, bl3;
                ldsm4(bh0, bh1, bh2, bh3, stage + 2 * QTW * 4 + rb);
                ldsm4(bl0, bl1, bl2, bl3, stage + 3 * QTW * 4 + rb);
                #pragma unroll
                for (int mt = 0; mt < 2; mt++) {
                    mma_bf16(acc[mt][2 * j2],     axh[mt], bh0, bh1);
                    mma_bf16(acc[mt][2 * j2],     axh[mt], bl0, bl1);
                    mma_bf16(acc[mt][2 * j2],     axl[mt], bh0, bh1);
                    mma_bf16(acc[mt][2 * j2 + 1], axh[mt], bh2, bh3);
                    mma_bf16(acc[mt][2 * j2 + 1], axh[mt], bl2, bl3);
                    mma_bf16(acc[mt][2 * j2 + 1], axl[mt], bh2, bh3);
                }
            }
        }
        __syncthreads();
    }

    // Epilogue: +bias, split bf16, scatter (Q,K natural; V transposed)
    #pragma unroll
    for (int mt = 0; mt < 2; mt++) {
        #pragma unroll
        for (int j = 0; j < 8; j++) {
            #pragma unroll
            for (int e = 0; e < 4; e++) {
                int r  = m0 + wm * 32 + mt * 16 + (lane >> 2) + (e >> 1) * 8;
                int cg = n0 + wn * 64 + j * 8 + 2 * (lane & 3) + (e & 1);
                float v = acc[mt][j][e] + __ldg(&bias[cg]);
                __nv_bfloat16 h, l;
                split2b(v, h, l);
                int b = r >> 11, s = r & 2047;
                int hh = cg / 192, rr = cg - hh * 192;
                int bh = b * Hc + hh;
                if (rr < 64) {
                    size_t o = ((size_t)bh * Sc + s) * Dc + rr;
                    g_Qh[o] = h; g_Ql[o] = l;
                } else if (rr < 128) {
                    size_t o = ((size_t)bh * Sc + s) * Dc + rr - 64;
                    g_Kh[o] = h; g_Kl[o] = l;
                } else {
                    size_t o = ((size_t)bh * Dc + rr - 128) * Sc + s;
                    g_Vth[o] = h; g_Vtl[o] = l;
                }
            }
        }
    }
}

// ---------------------------------------------------------------------------
// Attention FA2 on mma.sync bf16, cp.async double-buffered KV tiles of 128.
// ---------------------------------------------------------------------------
#define KPW 36
#define VPW 68
#define KH0 0
#define KL0 (128 * KPW)
#define VH0 (2 * 128 * KPW)
#define VL0 (VH0 + 64 * VPW)
#define ABUFW (VL0 + 64 * VPW)          // 17920 words per buffer
#define ATTN_SMEM (2 * ABUFW * 4)       // 143360 B

__global__ __launch_bounds__(256) void attn_kernel(float* __restrict__ out) {
    extern __shared__ uint32_t sw[];
    const uint32_t sb = smem_u32(sw);

    const int qt = blockIdx.x, h = blockIdx.y, b = blockIdx.z;
    const int bh = b * Hc + h;
    const int tid = threadIdx.x;
    const int lane = tid & 31;
    const int wid = tid >> 5;
    const int qg = qt * 128 + wid * 16;

    const uint4* Kh4 = (const uint4*)g_Kh + (size_t)bh * Sc * 8;
    const uint4* Kl4 = (const uint4*)g_Kl + (size_t)bh * Sc * 8;
    const uint4* Vh4 = (const uint4*)g_Vth + (size_t)bh * Dc * 256;
    const uint4* Vl4 = (const uint4*)g_Vtl + (size_t)bh * Dc * 256;

    auto load_kv = [&](int buf, int kt) {
        uint32_t base = sb + (buf * ABUFW) * 4;
        int kv0 = kt * 128;
        #pragma unroll
        for (int t = tid; t < 4096; t += 256) {
            int sec = t >> 10, rem = t & 1023;
            if (sec < 2) {                     // K hi/lo: 128 rows x 8 uint4
                int r = rem >> 3, q = rem & 7;
                const uint4* src = (sec == 0 ? Kh4 : Kl4) + (size_t)(kv0 + r) * 8 + q;
                cpa16(base + ((sec == 0 ? KH0 : KL0) + r * KPW + q * 4) * 4, src);
            } else {                           // V hi/lo: 64 rows x 16 uint4
                int r = rem >> 4, q = rem & 15;
                const uint4* src = (sec == 2 ? Vh4 : Vl4) + (size_t)r * 256 + kt * 16 + q;
                cpa16(base + ((sec == 2 ? VH0 : VL0) + r * VPW + q * 4) * 4, src);
            }
        }
    };

    // ---- preload Q fragments ----
    uint32_t qh[4][4], ql[4][4];
    {
        const uint32_t* Qhw = (const uint32_t*)g_Qh + (size_t)bh * Sc * 32;
        const uint32_t* Qlw = (const uint32_t*)g_Ql + (size_t)bh * Sc * 32;
        int r0 = qg + (lane >> 2);
        #pragma unroll
        for (int s = 0; s < 4; s++) {
            int w0 = s * 8 + (lane & 3);
            qh[s][0] = Qhw[(size_t)r0 * 32 + w0];
            qh[s][1] = Qhw[(size_t)(r0 + 8) * 32 + w0];
            qh[s][2] = Qhw[(size_t)r0 * 32 + w0 + 4];
            qh[s][3] = Qhw[(size_t)(r0 + 8) * 32 + w0 + 4];
            ql[s][0] = Qlw[(size_t)r0 * 32 + w0];
            ql[s][1] = Qlw[(size_t)(r0 + 8) * 32 + w0];
            ql[s][2] = Qlw[(size_t)r0 * 32 + w0 + 4];
            ql[s][3] = Qlw[(size_t)(r0 + 8) * 32 + w0 + 4];
        }
    }

    float o[8][4];
    #pragma unroll
    for (int nd = 0; nd < 8; nd++)
        #pragma unroll
        for (int e = 0; e < 4; e++) o[nd][e] = 0.f;
    float m0 = -1e30f, m1 = -1e30f, l0 = 0.f, l1 = 0.f;

    const uint32_t f_row = (lane & 7) + ((lane & 16) >> 1);
    const uint32_t f_kw  = (lane & 8) >> 1;

    load_kv(0, 0);
    CPA_COMMIT();

    for (int kt = 0; kt < Sc / 128; kt++) {
        int buf = kt & 1;
        if (kt + 1 < Sc / 128) { load_kv(buf ^ 1, kt + 1); CPA_COMMIT(); CPA_WAIT(1); }
        else                   { CPA_WAIT(0); }
        __syncthreads();

        uint32_t stage = sb + (buf * ABUFW) * 4;

        // ---- scores ----
        float sc[16][4];
        #pragma unroll
        for (int j = 0; j < 16; j++)
            #pragma unroll
            for (int e = 0; e < 4; e++) sc[j][e] = 0.f;

        #pragma unroll
        for (int j2 = 0; j2 < 8; j2++) {
            uint32_t rbase = (j2 * 16 + f_row) * KPW;
            #pragma unroll
            for (int s = 0; s < 4; s++) {
                uint32_t ra = stage + (rbase + s * 8 + f_kw) * 4;
                uint32_t bh0, bh1, bh2, bh3, bl0, bl1, bl2, bl3;
                ldsm4(bh0, bh1, bh2, bh3, ra + KH0 * 4);
                ldsm4(bl0, bl1, bl2, bl3, ra + KL0 * 4);
                mma_bf16(sc[2 * j2],     qh[s], bh0, bh1);
                mma_bf16(sc[2 * j2],     qh[s], bl0, bl1);
                mma_bf16(sc[2 * j2],     ql[s], bh0, bh1);
                mma_bf16(sc[2 * j2 + 1], qh[s], bh2, bh3);
                mma_bf16(sc[2 * j2 + 1], qh[s], bl2, bl3);
                mma_bf16(sc[2 * j2 + 1], ql[s], bh2, bh3);
            }
        }

        // ---- online softmax ----
        float tm0 = -1e30f, tm1 = -1e30f;
        #pragma unroll
        for (int j = 0; j < 16; j++) {
            #pragma unroll
            for (int e = 0; e < 4; e++) sc[j][e] *= 8.0f;
            tm0 = fmaxf(tm0, fmaxf(sc[j][0], sc[j][1]));
            tm1 = fmaxf(tm1, fmaxf(sc[j][2], sc[j][3]));
        }
        tm0 = fmaxf(tm0, __shfl_xor_sync(0xffffffffu, tm0, 1));
        tm0 = fmaxf(tm0, __shfl_xor_sync(0xffffffffu, tm0, 2));
        tm1 = fmaxf(tm1, __shfl_xor_sync(0xffffffffu, tm1, 1));
        tm1 = fmaxf(tm1, __shfl_xor_sync(0xffffffffu, tm1, 2));
        float mn0 = fmaxf(m0, tm0), mn1 = fmaxf(m1, tm1);
        float c0 = __expf(m0 - mn0), c1 = __expf(m1 - mn1);

        uint32_t pk[16][2];
        float ls0 = 0.f, ls1 = 0.f;
        #pragma unroll
        for (int j = 0; j < 16; j++) {
            float p0 = __expf(sc[j][0] - mn0);
            float p1 = __expf(sc[j][1] - mn0);
            float p2 = __expf(sc[j][2] - mn1);
            float p3 = __expf(sc[j][3] - mn1);
            float r0 = __bfloat162float(__float2bfloat16_rn(p0));
            float r1 = __bfloat162float(__float2bfloat16_rn(p1));
            float r2 = __bfloat162float(__float2bfloat16_rn(p2));
            float r3 = __bfloat162float(__float2bfloat16_rn(p3));
            ls0 += r0 + r1;
            ls1 += r2 + r3;
            pk[j][0] = pack2(r0, r1);
            pk[j][1] = pack2(r2, r3);
        }
        ls0 += __shfl_xor_sync(0xffffffffu, ls0, 1);
        ls0 += __shfl_xor_sync(0xffffffffu, ls0, 2);
        ls1 += __shfl_xor_sync(0xffffffffu, ls1, 1);
        ls1 += __shfl_xor_sync(0xffffffffu, ls1, 2);
        l0 = l0 * c0 + ls0;
        l1 = l1 * c1 + ls1;
        m0 = mn0; m1 = mn1;
        #pragma unroll
        for (int nd = 0; nd < 8; nd++) {
            o[nd][0] *= c0; o[nd][1] *= c0;
            o[nd][2] *= c1; o[nd][3] *= c1;
        }

        // ---- O += P~ @ V ----
        #pragma unroll
        for (int g = 0; g < 4; g++) {
            uint32_t rbase = (g * 16 + f_row) * VPW;
            #pragma unroll
            for (int t = 0; t < 8; t++) {
                uint32_t ra = stage + (rbase + t * 8 + f_kw) * 4;
                uint32_t vh0, vh1, vh2, vh3, vl0, vl1, vl2, vl3;
                ldsm4(vh0, vh1, vh2, vh3, ra + VH0 * 4);
                ldsm4(vl0, vl1, vl2, vl3, ra + VL0 * 4);
                uint32_t a[4] = {pk[2 * t][0], pk[2 * t][1], pk[2 * t + 1][0], pk[2 * t + 1][1]};
                mma_bf16(o[2 * g],     a, vh0, vh1);
                mma_bf16(o[2 * g],     a, vl0, vl1);
                mma_bf16(o[2 * g + 1], a, vh2, vh3);
                mma_bf16(o[2 * g + 1], a, vl2, vl3);
            }
        }
        __syncthreads();
    }

    float inv0 = 1.0f / l0, inv1 = 1.0f / l1;
    int r0 = qg + (lane >> 2);
    #pragma unroll
    for (int nd = 0; nd < 8; nd++) {
        int d = h * Dc + nd * 8 + 2 * (lane & 3);
        float2 v0 = make_float2(o[nd][0] * inv0, o[nd][1] * inv0);
        float2 v1 = make_float2(o[nd][2] * inv1, o[nd][3] * inv1);
        *(float2*)(out + ((size_t)b * Sc + r0) * 1024 + d)     = v0;
        *(float2*)(out + ((size_t)b * Sc + r0 + 8) * 1024 + d) = v1;
    }
}

// ---------------------------------------------------------------------------
extern "C" void kernel_launch(void* const* d_in, const int* in_sizes, int n_in,
                              void* d_out, int out_size) {
    const float* X    = (const float*)d_in[0];
    const float* W    = (const float*)d_in[1];
    const float* bias = (const float*)d_in[2];
    float* out = (float*)d_out;

    split_x_kernel<<<(MROWS * DMc) / (256 * 4), 256>>>(X);
    split_w_kernel<<<dim3(NQKVc / 32, DMc / 32), dim3(32, 8)>>>(W);

    cudaFuncSetAttribute(qkv_mma_kernel, cudaFuncAttributeMaxDynamicSharedMemorySize, QKV_SMEM);
    qkv_mma_kernel<<<dim3(NQKVc / 128, MROWS / 128), 256, QKV_SMEM>>>(bias);

    cudaFuncSetAttribute(attn_kernel, cudaFuncAttributeMaxDynamicSharedMemorySize, ATTN_SMEM);
    attn_kernel<<<dim3(Sc / 128, Hc, Bc), 256, ATTN_SMEM>>>(out);
}

// round 6
// speedup vs baseline: 2.9905x; 1.0287x over previous
#include <cuda_runtime.h>
#include <cuda_bf16.h>
#include <cstdint>

#define Bc    2
#define Sc    2048
#define Hc    16
#define Dc    64
#define DMc   1024
#define NQKVc 3072
#define MROWS (Bc*Sc)
#define BH    (Bc*Hc)

// ---------------------------------------------------------------------------
__device__ __nv_bfloat16 g_Xh[(size_t)MROWS*DMc];
__device__ __nv_bfloat16 g_Xl[(size_t)MROWS*DMc];
__device__ __nv_bfloat16 g_Wh[(size_t)NQKVc*DMc];
__device__ __nv_bfloat16 g_Wl[(size_t)NQKVc*DMc];

__device__ __nv_bfloat16 g_Qh[(size_t)BH*Sc*Dc];    // holds split of 8*q
__device__ __nv_bfloat16 g_Ql[(size_t)BH*Sc*Dc];
__device__ __nv_bfloat16 g_Kh[(size_t)BH*Sc*Dc];
__device__ __nv_bfloat16 g_Kl[(size_t)BH*Sc*Dc];
__device__ __nv_bfloat16 g_Vth[(size_t)BH*Dc*Sc];   // [bh][d][s]
__device__ __nv_bfloat16 g_Vtl[(size_t)BH*Dc*Sc];

// ---------------------------------------------------------------------------
__device__ __forceinline__ uint32_t smem_u32(const void* p) {
    uint32_t a;
    asm("{ .reg .u64 t; cvta.to.shared.u64 t, %1; cvt.u32.u64 %0, t; }" : "=r"(a) : "l"(p));
    return a;
}
__device__ __forceinline__ void ldsm4(uint32_t& d0, uint32_t& d1, uint32_t& d2,
                                      uint32_t& d3, uint32_t addr) {
    asm volatile("ldmatrix.sync.aligned.m8n8.x4.shared.b16 {%0,%1,%2,%3}, [%4];"
                 : "=r"(d0), "=r"(d1), "=r"(d2), "=r"(d3) : "r"(addr));
}
__device__ __forceinline__ void mma_bf16(float* c, const uint32_t* a,
                                         uint32_t b0, uint32_t b1) {
    asm volatile(
        "mma.sync.aligned.m16n8k16.row.col.f32.bf16.bf16.f32 "
        "{%0,%1,%2,%3}, {%4,%5,%6,%7}, {%8,%9}, {%0,%1,%2,%3};"
        : "+f"(c[0]), "+f"(c[1]), "+f"(c[2]), "+f"(c[3])
        : "r"(a[0]), "r"(a[1]), "r"(a[2]), "r"(a[3]), "r"(b0), "r"(b1));
}
__device__ __forceinline__ uint32_t pack2(float f_lo, float f_hi) {
    uint32_t r;
    asm("cvt.rn.bf16x2.f32 %0, %1, %2;" : "=r"(r) : "f"(f_hi), "f"(f_lo));
    return r;
}
__device__ __forceinline__ void split2b(float x, __nv_bfloat16& h, __nv_bfloat16& l) {
    h = __float2bfloat16_rn(x);
    l = __float2bfloat16_rn(x - __bfloat162float(h));
}
__device__ __forceinline__ void cpa16(uint32_t dst, const void* src) {
    asm volatile("cp.async.cg.shared.global [%0], [%1], 16;" :: "r"(dst), "l"(src) : "memory");
}
#define CPA_COMMIT() asm volatile("cp.async.commit_group;" ::: "memory")
#define CPA_WAIT(n)  asm volatile("cp.async.wait_group %0;" :: "n"(n) : "memory")

// ---------------------------------------------------------------------------
__global__ __launch_bounds__(256) void split_x_kernel(const float* __restrict__ X) {
    size_t i = (size_t)blockIdx.x * 256 + threadIdx.x;
    float4 v = ((const float4*)X)[i];
    float xs[4] = {v.x, v.y, v.z, v.w};
    __nv_bfloat16 h[4], l[4];
    #pragma unroll
    for (int e = 0; e < 4; e++) split2b(xs[e], h[e], l[e]);
    *(uint2*)&g_Xh[4 * i] = *(uint2*)h;
    *(uint2*)&g_Xl[4 * i] = *(uint2*)l;
}

__global__ void split_w_kernel(const float* __restrict__ W) {
    __shared__ float tile[32][33];
    int n0 = blockIdx.x * 32, k0 = blockIdx.y * 32;
    int tx = threadIdx.x, ty = threadIdx.y;
    for (int i = ty; i < 32; i += 8)
        tile[i][tx] = W[(size_t)(k0 + i) * NQKVc + n0 + tx];
    __syncthreads();
    for (int i = ty; i < 32; i += 8) {
        __nv_bfloat16 h, l;
        split2b(tile[tx][i], h, l);
        size_t o = (size_t)(n0 + i) * DMc + k0 + tx;
        g_Wh[o] = h; g_Wl[o] = l;
    }
}

// ---------------------------------------------------------------------------
// QKV GEMM: bf16 3-product m16n8k16, cp.async double-buffered k-chunks of 32.
// Epilogue staged through smem for fully coalesced head-major stores.
// ---------------------------------------------------------------------------
#define QPW     20
#define QTW     (128 * QPW)
#define QSTAGEW (4 * QTW)
#define QKV_SMEM (2 * QSTAGEW * 4)        // 81920 B (also fits C-stage 128x129 f32)

__global__ __launch_bounds__(256, 2) void qkv_mma_kernel(const float* __restrict__ bias) {
    extern __shared__ uint32_t sw[];
    const uint32_t sb = smem_u32(sw);

    const int tid  = threadIdx.x;
    const int lane = tid & 31;
    const int wid  = tid >> 5;
    const int wm   = wid & 3;
    const int wn   = wid >> 2;
    const int n0   = blockIdx.x * 128;
    const int m0   = blockIdx.y * 128;

    float acc[2][8][4];
    #pragma unroll
    for (int mt = 0; mt < 2; mt++)
        #pragma unroll
        for (int j = 0; j < 8; j++)
            #pragma unroll
            for (int e = 0; e < 4; e++) acc[mt][j][e] = 0.f;

    const uint32_t a_row = lane & 15;
    const uint32_t a_kw  = (lane & 16) >> 2;
    const uint32_t b_row = (lane & 7) + ((lane & 16) >> 1);
    const uint32_t b_kw  = (lane & 8) >> 1;

    const uint4* srcs[4] = {
        (const uint4*)g_Xh + (size_t)m0 * 128,
        (const uint4*)g_Xl + (size_t)m0 * 128,
        (const uint4*)g_Wh + (size_t)n0 * 128,
        (const uint4*)g_Wl + (size_t)n0 * 128};

    auto load_chunk = [&](int buf, int kc) {
        uint32_t base = sb + (buf * QSTAGEW) * 4;
        #pragma unroll
        for (int t = tid; t < 2048; t += 256) {
            int tl = t >> 9, rem = t & 511, r = rem >> 2, q = rem & 3;
            cpa16(base + (tl * QTW + r * QPW + q * 4) * 4,
                  srcs[tl] + (size_t)r * 128 + kc * 4 + q);
        }
    };

    load_chunk(0, 0);
    CPA_COMMIT();

    for (int kc = 0; kc < DMc / 32; kc++) {
        int buf = kc & 1;
        if (kc + 1 < DMc / 32) { load_chunk(buf ^ 1, kc + 1); CPA_COMMIT(); CPA_WAIT(1); }
        else                   { CPA_WAIT(0); }
        __syncthreads();

        uint32_t stage = sb + (buf * QSTAGEW) * 4;
        #pragma unroll
        for (int s = 0; s < 2; s++) {
            uint32_t axh[2][4], axl[2][4];
            #pragma unroll
            for (int mt = 0; mt < 2; mt++) {
                uint32_t ra = ((wm * 32 + mt * 16 + a_row) * QPW + s * 8 + a_kw) * 4;
                ldsm4(axh[mt][0], axh[mt][1], axh[mt][2], axh[mt][3], stage + ra);
                ldsm4(axl[mt][0], axl[mt][1], axl[mt][2], axl[mt][3], stage + QTW * 4 + ra);
            }
            #pragma unroll
            for (int j2 = 0; j2 < 4; j2++) {
                uint32_t rb = ((wn * 64 + j2 * 16 + b_row) * QPW + s * 8 + b_kw) * 4;
                uint32_t bh0, bh1, bh2, bh3, bl0, bl1, bl2, bl3;
                ldsm4(bh0, bh1, bh2, bh3, stage + 2 * QTW * 4 + rb);
                ldsm4(bl0, bl1, bl2, bl3, stage + 3 * QTW * 4 + rb);
                #pragma unroll
                for (int mt = 0; mt < 2; mt++) {
                    mma_bf16(acc[mt][2 * j2],     axh[mt], bh0, bh1);
                    mma_bf16(acc[mt][2 * j2],     axh[mt], bl0, bl1);
                    mma_bf16(acc[mt][2 * j2],     axl[mt], bh0, bh1);
                    mma_bf16(acc[mt][2 * j2 + 1], axh[mt], bh2, bh3);
                    mma_bf16(acc[mt][2 * j2 + 1], axh[mt], bl2, bl3);
                    mma_bf16(acc[mt][2 * j2 + 1], axl[mt], bh2, bh3);
                }
            }
        }
        __syncthreads();
    }

    // ---- Epilogue: stage C tile (+bias) in smem, pitch 129 ----
    float* Cs = (float*)sw;
    #pragma unroll
    for (int mt = 0; mt < 2; mt++) {
        #pragma unroll
        for (int j = 0; j < 8; j++) {
            #pragma unroll
            for (int e = 0; e < 4; e++) {
                int rl = wm * 32 + mt * 16 + (lane >> 2) + (e >> 1) * 8;
                int cl = wn * 64 + j * 8 + 2 * (lane & 3) + (e & 1);
                Cs[rl * 129 + cl] = acc[mt][j][e] + __ldg(&bias[n0 + cl]);
            }
        }
    }
    __syncthreads();

    const int b  = (m0 >> 11);
    const int s0 = m0 & 2047;

    // Q/K: row-wise, adjacent threads adjacent columns (coalesced d runs)
    for (int idx = tid; idx < 16384; idx += 256) {
        int r = idx >> 7, c = idx & 127;
        int cg = n0 + c;
        int hh = cg / 192, rr = cg - hh * 192;
        if (rr < 128) {
            float v = Cs[r * 129 + c];
            int bh = b * Hc + hh;
            __nv_bfloat16 h, l;
            if (rr < 64) {
                split2b(8.0f * v, h, l);           // fold score scale into Q
                size_t o = ((size_t)bh * Sc + s0 + r) * Dc + rr;
                g_Qh[o] = h; g_Ql[o] = l;
            } else {
                split2b(v, h, l);
                size_t o = ((size_t)bh * Sc + s0 + r) * Dc + rr - 64;
                g_Kh[o] = h; g_Kl[o] = l;
            }
        }
    }

    // V: column-wise (128 threads run down s for one column => coalesced runs)
    {
        int cgrp = tid >> 7;            // 0..1
        int sr   = tid & 127;           // s within tile
        #pragma unroll 2
        for (int cp = 0; cp < 64; cp++) {
            int c  = cp * 2 + cgrp;
            int cg = n0 + c;
            int hh = cg / 192, rr = cg - hh * 192;
            if (rr >= 128) {
                float v = Cs[sr * 129 + c];
                __nv_bfloat16 h, l;
                split2b(v, h, l);
                size_t o = ((size_t)(b * Hc + hh) * Dc + rr - 128) * Sc + s0 + sr;
                g_Vth[o] = h; g_Vtl[o] = l;
            }
        }
    }
}

// ---------------------------------------------------------------------------
// Attention FA2 on mma.sync bf16, cp.async double-buffered KV tiles of 128.
// Q pre-scaled by 8; P rounded via single bf16x2 cvt.
// ---------------------------------------------------------------------------
#define KPW 36
#define VPW 68
#define KH0 0
#define KL0 (128 * KPW)
#define VH0 (2 * 128 * KPW)
#define VL0 (VH0 + 64 * VPW)
#define ABUFW (VL0 + 64 * VPW)
#define ATTN_SMEM (2 * ABUFW * 4)

__global__ __launch_bounds__(256) void attn_kernel(float* __restrict__ out) {
    extern __shared__ uint32_t sw[];
    const uint32_t sb = smem_u32(sw);

    const int qt = blockIdx.x, h = blockIdx.y, b = blockIdx.z;
    const int bh = b * Hc + h;
    const int tid = threadIdx.x;
    const int lane = tid & 31;
    const int wid = tid >> 5;
    const int qg = qt * 128 + wid * 16;

    const uint4* Kh4 = (const uint4*)g_Kh + (size_t)bh * Sc * 8;
    const uint4* Kl4 = (const uint4*)g_Kl + (size_t)bh * Sc * 8;
    const uint4* Vh4 = (const uint4*)g_Vth + (size_t)bh * Dc * 256;
    const uint4* Vl4 = (const uint4*)g_Vtl + (size_t)bh * Dc * 256;

    auto load_kv = [&](int buf, int kt) {
        uint32_t base = sb + (buf * ABUFW) * 4;
        int kv0 = kt * 128;
        #pragma unroll
        for (int t = tid; t < 4096; t += 256) {
            int sec = t >> 10, rem = t & 1023;
            if (sec < 2) {
                int r = rem >> 3, q = rem & 7;
                const uint4* src = (sec == 0 ? Kh4 : Kl4) + (size_t)(kv0 + r) * 8 + q;
                cpa16(base + ((sec == 0 ? KH0 : KL0) + r * KPW + q * 4) * 4, src);
            } else {
                int r = rem >> 4, q = rem & 15;
                const uint4* src = (sec == 2 ? Vh4 : Vl4) + (size_t)r * 256 + kt * 16 + q;
                cpa16(base + ((sec == 2 ? VH0 : VL0) + r * VPW + q * 4) * 4, src);
            }
        }
    };

    // ---- preload Q fragments (already scaled by 8) ----
    uint32_t qh[4][4], ql[4][4];
    {
        const uint32_t* Qhw = (const uint32_t*)g_Qh + (size_t)bh * Sc * 32;
        const uint32_t* Qlw = (const uint32_t*)g_Ql + (size_t)bh * Sc * 32;
        int r0 = qg + (lane >> 2);
        #pragma unroll
        for (int s = 0; s < 4; s++) {
            int w0 = s * 8 + (lane & 3);
            qh[s][0] = Qhw[(size_t)r0 * 32 + w0];
            qh[s][1] = Qhw[(size_t)(r0 + 8) * 32 + w0];
            qh[s][2] = Qhw[(size_t)r0 * 32 + w0 + 4];
            qh[s][3] = Qhw[(size_t)(r0 + 8) * 32 + w0 + 4];
            ql[s][0] = Qlw[(size_t)r0 * 32 + w0];
            ql[s][1] = Qlw[(size_t)(r0 + 8) * 32 + w0];
            ql[s][2] = Qlw[(size_t)r0 * 32 + w0 + 4];
            ql[s][3] = Qlw[(size_t)(r0 + 8) * 32 + w0 + 4];
        }
    }

    float o[8][4];
    #pragma unroll
    for (int nd = 0; nd < 8; nd++)
        #pragma unroll
        for (int e = 0; e < 4; e++) o[nd][e] = 0.f;
    float m0 = -1e30f, m1 = -1e30f, l0 = 0.f, l1 = 0.f;

    const uint32_t f_row = (lane & 7) + ((lane & 16) >> 1);
    const uint32_t f_kw  = (lane & 8) >> 1;

    load_kv(0, 0);
    CPA_COMMIT();

    for (int kt = 0; kt < Sc / 128; kt++) {
        int buf = kt & 1;
        if (kt + 1 < Sc / 128) { load_kv(buf ^ 1, kt + 1); CPA_COMMIT(); CPA_WAIT(1); }
        else                   { CPA_WAIT(0); }
        __syncthreads();

        uint32_t stage = sb + (buf * ABUFW) * 4;

        // ---- scores (Q pre-scaled by 8) ----
        float sc[16][4];
        #pragma unroll
        for (int j = 0; j < 16; j++)
            #pragma unroll
            for (int e = 0; e < 4; e++) sc[j][e] = 0.f;

        #pragma unroll
        for (int j2 = 0; j2 < 8; j2++) {
            uint32_t rbase = (j2 * 16 + f_row) * KPW;
            #pragma unroll
            for (int s = 0; s < 4; s++) {
                uint32_t ra = stage + (rbase + s * 8 + f_kw) * 4;
                uint32_t bh0, bh1, bh2, bh3, bl0, bl1, bl2, bl3;
                ldsm4(bh0, bh1, bh2, bh3, ra + KH0 * 4);
                ldsm4(bl0, bl1, bl2, bl3, ra + KL0 * 4);
                mma_bf16(sc[2 * j2],     qh[s], bh0, bh1);
                mma_bf16(sc[2 * j2],     qh[s], bl0, bl1);
                mma_bf16(sc[2 * j2],     ql[s], bh0, bh1);
                mma_bf16(sc[2 * j2 + 1], qh[s], bh2, bh3);
                mma_bf16(sc[2 * j2 + 1], qh[s], bl2, bl3);
                mma_bf16(sc[2 * j2 + 1], ql[s], bh2, bh3);
            }
        }

        // ---- online softmax ----
        float tm0 = -1e30f, tm1 = -1e30f;
        #pragma unroll
        for (int j = 0; j < 16; j++) {
            tm0 = fmaxf(tm0, fmaxf(sc[j][0], sc[j][1]));
            tm1 = fmaxf(tm1, fmaxf(sc[j][2], sc[j][3]));
        }
        tm0 = fmaxf(tm0, __shfl_xor_sync(0xffffffffu, tm0, 1));
        tm0 = fmaxf(tm0, __shfl_xor_sync(0xffffffffu, tm0, 2));
        tm1 = fmaxf(tm1, __shfl_xor_sync(0xffffffffu, tm1, 1));
        tm1 = fmaxf(tm1, __shfl_xor_sync(0xffffffffu, tm1, 2));
        float mn0 = fmaxf(m0, tm0), mn1 = fmaxf(m1, tm1);
        float c0 = __expf(m0 - mn0), c1 = __expf(m1 - mn1);

        uint32_t pk[16][2];
        float ls0 = 0.f, ls1 = 0.f;
        #pragma unroll
        for (int j = 0; j < 16; j++) {
            float p0 = __expf(sc[j][0] - mn0);
            float p1 = __expf(sc[j][1] - mn0);
            float p2 = __expf(sc[j][2] - mn1);
            float p3 = __expf(sc[j][3] - mn1);
            uint32_t k0 = pack2(p0, p1);          // rounds both to bf16
            uint32_t k1 = pack2(p2, p3);
            pk[j][0] = k0; pk[j][1] = k1;
            // recover rounded values for the l-sum (bf16 -> f32 is bit shift)
            ls0 += __uint_as_float(k0 << 16) + __uint_as_float(k0 & 0xffff0000u);
            ls1 += __uint_as_float(k1 << 16) + __uint_as_float(k1 & 0xffff0000u);
        }
        ls0 += __shfl_xor_sync(0xffffffffu, ls0, 1);
        ls0 += __shfl_xor_sync(0xffffffffu, ls0, 2);
        ls1 += __shfl_xor_sync(0xffffffffu, ls1, 1);
        ls1 += __shfl_xor_sync(0xffffffffu, ls1, 2);
        l0 = l0 * c0 + ls0;
        l1 = l1 * c1 + ls1;
        m0 = mn0; m1 = mn1;
        #pragma unroll
        for (int nd = 0; nd < 8; nd++) {
            o[nd][0] *= c0; o[nd][1] *= c0;
            o[nd][2] *= c1; o[nd][3] *= c1;
        }

        // ---- O += P~ @ V ----
        #pragma unroll
        for (int g = 0; g < 4; g++) {
            uint32_t rbase = (g * 16 + f_row) * VPW;
            #pragma unroll
            for (int t = 0; t < 8; t++) {
                uint32_t ra = stage + (rbase + t * 8 + f_kw) * 4;
                uint32_t vh0, vh1, vh2, vh3, vl0, vl1, vl2, vl3;
                ldsm4(vh0, vh1, vh2, vh3, ra + VH0 * 4);
                ldsm4(vl0, vl1, vl2, vl3, ra + VL0 * 4);
                uint32_t a[4] = {pk[2 * t][0], pk[2 * t][1], pk[2 * t + 1][0], pk[2 * t + 1][1]};
                mma_bf16(o[2 * g],     a, vh0, vh1);
                mma_bf16(o[2 * g],     a, vl0, vl1);
                mma_bf16(o[2 * g + 1], a, vh2, vh3);
                mma_bf16(o[2 * g + 1], a, vl2, vl3);
            }
        }
        __syncthreads();
    }

    float inv0 = 1.0f / l0, inv1 = 1.0f / l1;
    int r0 = qg + (lane >> 2);
    #pragma unroll
    for (int nd = 0; nd < 8; nd++) {
        int d = h * Dc + nd * 8 + 2 * (lane & 3);
        float2 v0 = make_float2(o[nd][0] * inv0, o[nd][1] * inv0);
        float2 v1 = make_float2(o[nd][2] * inv1, o[nd][3] * inv1);
        *(float2*)(out + ((size_t)b * Sc + r0) * 1024 + d)     = v0;
        *(float2*)(out + ((size_t)b * Sc + r0 + 8) * 1024 + d) = v1;
    }
}

// ---------------------------------------------------------------------------
extern "C" void kernel_launch(void* const* d_in, const int* in_sizes, int n_in,
                              void* d_out, int out_size) {
    const float* X    = (const float*)d_in[0];
    const float* W    = (const float*)d_in[1];
    const float* bias = (const float*)d_in[2];
    float* out = (float*)d_out;

    split_x_kernel<<<(MROWS * DMc) / (256 * 4), 256>>>(X);
    split_w_kernel<<<dim3(NQKVc / 32, DMc / 32), dim3(32, 8)>>>(W);

    cudaFuncSetAttribute(qkv_mma_kernel, cudaFuncAttributeMaxDynamicSharedMemorySize, QKV_SMEM);
    qkv_mma_kernel<<<dim3(NQKVc / 128, MROWS / 128), 256, QKV_SMEM>>>(bias);

    cudaFuncSetAttribute(attn_kernel, cudaFuncAttributeMaxDynamicSharedMemorySize, ATTN_SMEM);
    attn_kernel<<<dim3(Sc / 128, Hc, Bc), 256, ATTN_SMEM>>>(out);
}

// round 7
// speedup vs baseline: 3.0690x; 1.0263x over previous
#include <cuda_runtime.h>
#include <cuda_bf16.h>
#include <cstdint>

#define Bc    2
#define Sc    2048
#define Hc    16
#define Dc    64
#define DMc   1024
#define NQKVc 3072
#define MROWS (Bc*Sc)
#define BH    (Bc*Hc)

// ---------------------------------------------------------------------------
__device__ __nv_bfloat16 g_Xh[(size_t)MROWS*DMc];
__device__ __nv_bfloat16 g_Xl[(size_t)MROWS*DMc];
__device__ __nv_bfloat16 g_Wh[(size_t)NQKVc*DMc];
__device__ __nv_bfloat16 g_Wl[(size_t)NQKVc*DMc];

__device__ __nv_bfloat16 g_Qh[(size_t)BH*Sc*Dc];    // holds split of 8*q
__device__ __nv_bfloat16 g_Ql[(size_t)BH*Sc*Dc];
__device__ __nv_bfloat16 g_Kh[(size_t)BH*Sc*Dc];
__device__ __nv_bfloat16 g_Kl[(size_t)BH*Sc*Dc];
__device__ __nv_bfloat16 g_Vth[(size_t)BH*Dc*Sc];   // [bh][d][s]
__device__ __nv_bfloat16 g_Vtl[(size_t)BH*Dc*Sc];

// ---------------------------------------------------------------------------
__device__ __forceinline__ uint32_t smem_u32(const void* p) {
    uint32_t a;
    asm("{ .reg .u64 t; cvta.to.shared.u64 t, %1; cvt.u32.u64 %0, t; }" : "=r"(a) : "l"(p));
    return a;
}
__device__ __forceinline__ void ldsm4(uint32_t& d0, uint32_t& d1, uint32_t& d2,
                                      uint32_t& d3, uint32_t addr) {
    asm volatile("ldmatrix.sync.aligned.m8n8.x4.shared.b16 {%0,%1,%2,%3}, [%4];"
                 : "=r"(d0), "=r"(d1), "=r"(d2), "=r"(d3) : "r"(addr));
}
__device__ __forceinline__ void mma_bf16(float* c, const uint32_t* a,
                                         uint32_t b0, uint32_t b1) {
    asm volatile(
        "mma.sync.aligned.m16n8k16.row.col.f32.bf16.bf16.f32 "
        "{%0,%1,%2,%3}, {%4,%5,%6,%7}, {%8,%9}, {%0,%1,%2,%3};"
        : "+f"(c[0]), "+f"(c[1]), "+f"(c[2]), "+f"(c[3])
        : "r"(a[0]), "r"(a[1]), "r"(a[2]), "r"(a[3]), "r"(b0), "r"(b1));
}
__device__ __forceinline__ uint32_t pack2(float f_lo, float f_hi) {
    uint32_t r;
    asm("cvt.rn.bf16x2.f32 %0, %1, %2;" : "=r"(r) : "f"(f_hi), "f"(f_lo));
    return r;
}
__device__ __forceinline__ void split2b(float x, __nv_bfloat16& h, __nv_bfloat16& l) {
    h = __float2bfloat16_rn(x);
    l = __float2bfloat16_rn(x - __bfloat162float(h));
}
__device__ __forceinline__ void cpa16(uint32_t dst, const void* src) {
    asm volatile("cp.async.cg.shared.global [%0], [%1], 16;" :: "r"(dst), "l"(src) : "memory");
}
#define CPA_COMMIT() asm volatile("cp.async.commit_group;" ::: "memory")
#define CPA_WAIT(n)  asm volatile("cp.async.wait_group %0;" :: "n"(n) : "memory")

// ---------------------------------------------------------------------------
__global__ __launch_bounds__(256) void split_x_kernel(const float* __restrict__ X) {
    size_t i = (size_t)blockIdx.x * 256 + threadIdx.x;
    float4 v = ((const float4*)X)[i];
    float xs[4] = {v.x, v.y, v.z, v.w};
    __nv_bfloat16 h[4], l[4];
    #pragma unroll
    for (int e = 0; e < 4; e++) split2b(xs[e], h[e], l[e]);
    *(uint2*)&g_Xh[4 * i] = *(uint2*)h;
    *(uint2*)&g_Xl[4 * i] = *(uint2*)l;
}

__global__ void split_w_kernel(const float* __restrict__ W) {
    __shared__ float tile[32][33];
    int n0 = blockIdx.x * 32, k0 = blockIdx.y * 32;
    int tx = threadIdx.x, ty = threadIdx.y;
    for (int i = ty; i < 32; i += 8)
        tile[i][tx] = W[(size_t)(k0 + i) * NQKVc + n0 + tx];
    __syncthreads();
    for (int i = ty; i < 32; i += 8) {
        __nv_bfloat16 h, l;
        split2b(tile[tx][i], h, l);
        size_t o = (size_t)(n0 + i) * DMc + k0 + tx;
        g_Wh[o] = h; g_Wl[o] = l;
    }
}

// ---------------------------------------------------------------------------
// QKV GEMM (unchanged from R6): bf16 3-product m16n8k16, double-buffered.
// ---------------------------------------------------------------------------
#define QPW     20
#define QTW     (128 * QPW)
#define QSTAGEW (4 * QTW)
#define QKV_SMEM (2 * QSTAGEW * 4)

__global__ __launch_bounds__(256, 2) void qkv_mma_kernel(const float* __restrict__ bias) {
    extern __shared__ uint32_t sw[];
    const uint32_t sb = smem_u32(sw);

    const int tid  = threadIdx.x;
    const int lane = tid & 31;
    const int wid  = tid >> 5;
    const int wm   = wid & 3;
    const int wn   = wid >> 2;
    const int n0   = blockIdx.x * 128;
    const int m0   = blockIdx.y * 128;

    float acc[2][8][4];
    #pragma unroll
    for (int mt = 0; mt < 2; mt++)
        #pragma unroll
        for (int j = 0; j < 8; j++)
            #pragma unroll
            for (int e = 0; e < 4; e++) acc[mt][j][e] = 0.f;

    const uint32_t a_row = lane & 15;
    const uint32_t a_kw  = (lane & 16) >> 2;
    const uint32_t b_row = (lane & 7) + ((lane & 16) >> 1);
    const uint32_t b_kw  = (lane & 8) >> 1;

    const uint4* srcs[4] = {
        (const uint4*)g_Xh + (size_t)m0 * 128,
        (const uint4*)g_Xl + (size_t)m0 * 128,
        (const uint4*)g_Wh + (size_t)n0 * 128,
        (const uint4*)g_Wl + (size_t)n0 * 128};

    auto load_chunk = [&](int buf, int kc) {
        uint32_t base = sb + (buf * QSTAGEW) * 4;
        #pragma unroll
        for (int t = tid; t < 2048; t += 256) {
            int tl = t >> 9, rem = t & 511, r = rem >> 2, q = rem & 3;
            cpa16(base + (tl * QTW + r * QPW + q * 4) * 4,
                  srcs[tl] + (size_t)r * 128 + kc * 4 + q);
        }
    };

    load_chunk(0, 0);
    CPA_COMMIT();

    for (int kc = 0; kc < DMc / 32; kc++) {
        int buf = kc & 1;
        if (kc + 1 < DMc / 32) { load_chunk(buf ^ 1, kc + 1); CPA_COMMIT(); CPA_WAIT(1); }
        else                   { CPA_WAIT(0); }
        __syncthreads();

        uint32_t stage = sb + (buf * QSTAGEW) * 4;
        #pragma unroll
        for (int s = 0; s < 2; s++) {
            uint32_t axh[2][4], axl[2][4];
            #pragma unroll
            for (int mt = 0; mt < 2; mt++) {
                uint32_t ra = ((wm * 32 + mt * 16 + a_row) * QPW + s * 8 + a_kw) * 4;
                ldsm4(axh[mt][0], axh[mt][1], axh[mt][2], axh[mt][3], stage + ra);
                ldsm4(axl[mt][0], axl[mt][1], axl[mt][2], axl[mt][3], stage + QTW * 4 + ra);
            }
            #pragma unroll
            for (int j2 = 0; j2 < 4; j2++) {
                uint32_t rb = ((wn * 64 + j2 * 16 + b_row) * QPW + s * 8 + b_kw) * 4;
                uint32_t bh0, bh1, bh2, bh3, bl0, bl1, bl2, bl3;
                ldsm4(bh0, bh1, bh2, bh3, stage + 2 * QTW * 4 + rb);
                ldsm4(bl0, bl1, bl2, bl3, stage + 3 * QTW * 4 + rb);
                #pragma unroll
                for (int mt = 0; mt < 2; mt++) {
                    mma_bf16(acc[mt][2 * j2],     axh[mt], bh0, bh1);
                    mma_bf16(acc[mt][2 * j2],     axh[mt], bl0, bl1);
                    mma_bf16(acc[mt][2 * j2],     axl[mt], bh0, bh1);
                    mma_bf16(acc[mt][2 * j2 + 1], axh[mt], bh2, bh3);
                    mma_bf16(acc[mt][2 * j2 + 1], axh[mt], bl2, bl3);
                    mma_bf16(acc[mt][2 * j2 + 1], axl[mt], bh2, bh3);
                }
            }
        }
        __syncthreads();
    }

    // ---- Epilogue: stage C tile (+bias) in smem, pitch 129 ----
    float* Cs = (float*)sw;
    #pragma unroll
    for (int mt = 0; mt < 2; mt++) {
        #pragma unroll
        for (int j = 0; j < 8; j++) {
            #pragma unroll
            for (int e = 0; e < 4; e++) {
                int rl = wm * 32 + mt * 16 + (lane >> 2) + (e >> 1) * 8;
                int cl = wn * 64 + j * 8 + 2 * (lane & 3) + (e & 1);
                Cs[rl * 129 + cl] = acc[mt][j][e] + __ldg(&bias[n0 + cl]);
            }
        }
    }
    __syncthreads();

    const int b  = (m0 >> 11);
    const int s0 = m0 & 2047;

    for (int idx = tid; idx < 16384; idx += 256) {
        int r = idx >> 7, c = idx & 127;
        int cg = n0 + c;
        int hh = cg / 192, rr = cg - hh * 192;
        if (rr < 128) {
            float v = Cs[r * 129 + c];
            int bh = b * Hc + hh;
            __nv_bfloat16 h, l;
            if (rr < 64) {
                split2b(8.0f * v, h, l);
                size_t o = ((size_t)bh * Sc + s0 + r) * Dc + rr;
                g_Qh[o] = h; g_Ql[o] = l;
            } else {
                split2b(v, h, l);
                size_t o = ((size_t)bh * Sc + s0 + r) * Dc + rr - 64;
                g_Kh[o] = h; g_Kl[o] = l;
            }
        }
    }

    {
        int cgrp = tid >> 7;
        int sr   = tid & 127;
        #pragma unroll 2
        for (int cp = 0; cp < 64; cp++) {
            int c  = cp * 2 + cgrp;
            int cg = n0 + c;
            int hh = cg / 192, rr = cg - hh * 192;
            if (rr >= 128) {
                float v = Cs[sr * 129 + c];
                __nv_bfloat16 h, l;
                split2b(v, h, l);
                size_t o = ((size_t)(b * Hc + hh) * Dc + rr - 128) * Sc + s0 + sr;
                g_Vth[o] = h; g_Vtl[o] = l;
            }
        }
    }
}

// ---------------------------------------------------------------------------
// Attention FA2: KV tile 64, double-buffered, 2 CTAs/SM target.
// ---------------------------------------------------------------------------
#define KPW 36
#define KH0 0
#define KL0 (64 * KPW)
#define VH0 (2 * 64 * KPW)
#define VL0 (VH0 + 64 * KPW)
#define ABUFW (VL0 + 64 * KPW)          // 9216 words = 36,864 B per buffer
#define ATTN_SMEM (2 * ABUFW * 4)       // 73,728 B

__global__ __launch_bounds__(256, 2) void attn_kernel(float* __restrict__ out) {
    extern __shared__ uint32_t sw[];
    const uint32_t sb = smem_u32(sw);

    const int qt = blockIdx.x, h = blockIdx.y, b = blockIdx.z;
    const int bh = b * Hc + h;
    const int tid = threadIdx.x;
    const int lane = tid & 31;
    const int wid = tid >> 5;
    const int qg = qt * 128 + wid * 16;

    const uint4* Kh4 = (const uint4*)g_Kh + (size_t)bh * Sc * 8;
    const uint4* Kl4 = (const uint4*)g_Kl + (size_t)bh * Sc * 8;
    const uint4* Vh4 = (const uint4*)g_Vth + (size_t)bh * Dc * 256;
    const uint4* Vl4 = (const uint4*)g_Vtl + (size_t)bh * Dc * 256;

    // one KV tile of 64: K hi/lo 64 rows x 8 uint4, V hi/lo 64 rows x 8 uint4
    auto load_kv = [&](int buf, int kt) {
        uint32_t base = sb + (buf * ABUFW) * 4;
        int kv0 = kt * 64;
        #pragma unroll
        for (int t = tid; t < 2048; t += 256) {
            int sec = t >> 9, rem = t & 511;
            int r = rem >> 3, q = rem & 7;
            if (sec < 2) {
                const uint4* src = (sec == 0 ? Kh4 : Kl4) + (size_t)(kv0 + r) * 8 + q;
                cpa16(base + ((sec == 0 ? KH0 : KL0) + r * KPW + q * 4) * 4, src);
            } else {
                const uint4* src = (sec == 2 ? Vh4 : Vl4) + (size_t)r * 256 + kt * 8 + q;
                cpa16(base + ((sec == 2 ? VH0 : VL0) + r * KPW + q * 4) * 4, src);
            }
        }
    };

    // ---- preload Q fragments (pre-scaled by 8) ----
    uint32_t qh[4][4], ql[4][4];
    {
        const uint32_t* Qhw = (const uint32_t*)g_Qh + (size_t)bh * Sc * 32;
        const uint32_t* Qlw = (const uint32_t*)g_Ql + (size_t)bh * Sc * 32;
        int r0 = qg + (lane >> 2);
        #pragma unroll
        for (int s = 0; s < 4; s++) {
            int w0 = s * 8 + (lane & 3);
            qh[s][0] = Qhw[(size_t)r0 * 32 + w0];
            qh[s][1] = Qhw[(size_t)(r0 + 8) * 32 + w0];
            qh[s][2] = Qhw[(size_t)r0 * 32 + w0 + 4];
            qh[s][3] = Qhw[(size_t)(r0 + 8) * 32 + w0 + 4];
            ql[s][0] = Qlw[(size_t)r0 * 32 + w0];
            ql[s][1] = Qlw[(size_t)(r0 + 8) * 32 + w0];
            ql[s][2] = Qlw[(size_t)r0 * 32 + w0 + 4];
            ql[s][3] = Qlw[(size_t)(r0 + 8) * 32 + w0 + 4];
        }
    }

    float o[8][4];
    #pragma unroll
    for (int nd = 0; nd < 8; nd++)
        #pragma unroll
        for (int e = 0; e < 4; e++) o[nd][e] = 0.f;
    float m0 = -1e30f, m1 = -1e30f, l0 = 0.f, l1 = 0.f;

    const uint32_t f_row = (lane & 7) + ((lane & 16) >> 1);
    const uint32_t f_kw  = (lane & 8) >> 1;

    load_kv(0, 0);
    CPA_COMMIT();

    for (int kt = 0; kt < Sc / 64; kt++) {
        int buf = kt & 1;
        if (kt + 1 < Sc / 64) { load_kv(buf ^ 1, kt + 1); CPA_COMMIT(); CPA_WAIT(1); }
        else                  { CPA_WAIT(0); }
        __syncthreads();

        uint32_t stage = sb + (buf * ABUFW) * 4;

        // ---- scores: 16 q x 64 kv ----
        float sc[8][4];
        #pragma unroll
        for (int j = 0; j < 8; j++)
            #pragma unroll
            for (int e = 0; e < 4; e++) sc[j][e] = 0.f;

        #pragma unroll
        for (int j2 = 0; j2 < 4; j2++) {
            uint32_t rbase = (j2 * 16 + f_row) * KPW;
            #pragma unroll
            for (int s = 0; s < 4; s++) {
                uint32_t ra = stage + (rbase + s * 8 + f_kw) * 4;
                uint32_t bh0, bh1, bh2, bh3, bl0, bl1, bl2, bl3;
                ldsm4(bh0, bh1, bh2, bh3, ra + KH0 * 4);
                ldsm4(bl0, bl1, bl2, bl3, ra + KL0 * 4);
                mma_bf16(sc[2 * j2],     qh[s], bh0, bh1);
                mma_bf16(sc[2 * j2],     qh[s], bl0, bl1);
                mma_bf16(sc[2 * j2],     ql[s], bh0, bh1);
                mma_bf16(sc[2 * j2 + 1], qh[s], bh2, bh3);
                mma_bf16(sc[2 * j2 + 1], qh[s], bl2, bl3);
                mma_bf16(sc[2 * j2 + 1], ql[s], bh2, bh3);
            }
        }

        // ---- online softmax ----
        float tm0 = -1e30f, tm1 = -1e30f;
        #pragma unroll
        for (int j = 0; j < 8; j++) {
            tm0 = fmaxf(tm0, fmaxf(sc[j][0], sc[j][1]));
            tm1 = fmaxf(tm1, fmaxf(sc[j][2], sc[j][3]));
        }
        tm0 = fmaxf(tm0, __shfl_xor_sync(0xffffffffu, tm0, 1));
        tm0 = fmaxf(tm0, __shfl_xor_sync(0xffffffffu, tm0, 2));
        tm1 = fmaxf(tm1, __shfl_xor_sync(0xffffffffu, tm1, 1));
        tm1 = fmaxf(tm1, __shfl_xor_sync(0xffffffffu, tm1, 2));
        float mn0 = fmaxf(m0, tm0), mn1 = fmaxf(m1, tm1);
        float c0 = __expf(m0 - mn0), c1 = __expf(m1 - mn1);

        uint32_t pk[8][2];
        float ls0 = 0.f, ls1 = 0.f;
        #pragma unroll
        for (int j = 0; j < 8; j++) {
            float p0 = __expf(sc[j][0] - mn0);
            float p1 = __expf(sc[j][1] - mn0);
            float p2 = __expf(sc[j][2] - mn1);
            float p3 = __expf(sc[j][3] - mn1);
            uint32_t k0 = pack2(p0, p1);
            uint32_t k1 = pack2(p2, p3);
            pk[j][0] = k0; pk[j][1] = k1;
            ls0 += __uint_as_float(k0 << 16) + __uint_as_float(k0 & 0xffff0000u);
            ls1 += __uint_as_float(k1 << 16) + __uint_as_float(k1 & 0xffff0000u);
        }
        ls0 += __shfl_xor_sync(0xffffffffu, ls0, 1);
        ls0 += __shfl_xor_sync(0xffffffffu, ls0, 2);
        ls1 += __shfl_xor_sync(0xffffffffu, ls1, 1);
        ls1 += __shfl_xor_sync(0xffffffffu, ls1, 2);
        l0 = l0 * c0 + ls0;
        l1 = l1 * c1 + ls1;
        m0 = mn0; m1 = mn1;
        #pragma unroll
        for (int nd = 0; nd < 8; nd++) {
            o[nd][0] *= c0; o[nd][1] *= c0;
            o[nd][2] *= c1; o[nd][3] *= c1;
        }

        // ---- O += P~ @ V ----
        #pragma unroll
        for (int g = 0; g < 4; g++) {
            uint32_t rbase = (g * 16 + f_row) * KPW;
            #pragma unroll
            for (int t = 0; t < 4; t++) {
                uint32_t ra = stage + (rbase + t * 8 + f_kw) * 4;
                uint32_t vh0, vh1, vh2, vh3, vl0, vl1, vl2, vl3;
                ldsm4(vh0, vh1, vh2, vh3, ra + VH0 * 4);
                ldsm4(vl0, vl1, vl2, vl3, ra + VL0 * 4);
                uint32_t a[4] = {pk[2 * t][0], pk[2 * t][1], pk[2 * t + 1][0], pk[2 * t + 1][1]};
                mma_bf16(o[2 * g],     a, vh0, vh1);
                mma_bf16(o[2 * g],     a, vl0, vl1);
                mma_bf16(o[2 * g + 1], a, vh2, vh3);
                mma_bf16(o[2 * g + 1], a, vl2, vl3);
            }
        }
        __syncthreads();
    }

    float inv0 = 1.0f / l0, inv1 = 1.0f / l1;
    int r0 = qg + (lane >> 2);
    #pragma unroll
    for (int nd = 0; nd < 8; nd++) {
        int d = h * Dc + nd * 8 + 2 * (lane & 3);
        float2 v0 = make_float2(o[nd][0] * inv0, o[nd][1] * inv0);
        float2 v1 = make_float2(o[nd][2] * inv1, o[nd][3] * inv1);
        *(float2*)(out + ((size_t)b * Sc + r0) * 1024 + d)     = v0;
        *(float2*)(out + ((size_t)b * Sc + r0 + 8) * 1024 + d) = v1;
    }
}

// ---------------------------------------------------------------------------
extern "C" void kernel_launch(void* const* d_in, const int* in_sizes, int n_in,
                              void* d_out, int out_size) {
    const float* X    = (const float*)d_in[0];
    const float* W    = (const float*)d_in[1];
    const float* bias = (const float*)d_in[2];
    float* out = (float*)d_out;

    split_x_kernel<<<(MROWS * DMc) / (256 * 4), 256>>>(X);
    split_w_kernel<<<dim3(NQKVc / 32, DMc / 32), dim3(32, 8)>>>(W);

    cudaFuncSetAttribute(qkv_mma_kernel, cudaFuncAttributeMaxDynamicSharedMemorySize, QKV_SMEM);
    qkv_mma_kernel<<<dim3(NQKVc / 128, MROWS / 128), 256, QKV_SMEM>>>(bias);

    cudaFuncSetAttribute(attn_kernel, cudaFuncAttributeMaxDynamicSharedMemorySize, ATTN_SMEM);
    attn_kernel<<<dim3(Sc / 128, Hc, Bc), 256, ATTN_SMEM>>>(out);
}

// round 9
// speedup vs baseline: 3.2814x; 1.0692x over previous
#include <cuda_runtime.h>
#include <cuda_bf16.h>
#include <cuda_fp16.h>
#include <cstdint>

#define Bc    2
#define Sc    2048
#define Hc    16
#define Dc    64
#define DMc   1024
#define NQKVc 3072
#define MROWS (Bc*Sc)
#define BH    (Bc*Hc)

// ---------------------------------------------------------------------------
__device__ __nv_bfloat16 g_Xh[(size_t)MROWS*DMc];
__device__ __nv_bfloat16 g_Xl[(size_t)MROWS*DMc];
__device__ __nv_bfloat16 g_Wh[(size_t)NQKVc*DMc];
__device__ __nv_bfloat16 g_Wl[(size_t)NQKVc*DMc];

__device__ __nv_bfloat16 g_Qh[(size_t)BH*Sc*Dc];    // split of 8*q
__device__ __nv_bfloat16 g_Ql[(size_t)BH*Sc*Dc];
__device__ __nv_bfloat16 g_Kh[(size_t)BH*Sc*Dc];
__device__ __nv_bfloat16 g_Kl[(size_t)BH*Sc*Dc];
__device__ __half        g_Vt[(size_t)BH*Dc*Sc];    // [bh][d][s], fp16 single

// ---------------------------------------------------------------------------
__device__ __forceinline__ uint32_t smem_u32(const void* p) {
    uint32_t a;
    asm("{ .reg .u64 t; cvta.to.shared.u64 t, %1; cvt.u32.u64 %0, t; }" : "=r"(a) : "l"(p));
    return a;
}
__device__ __forceinline__ void ldsm4(uint32_t& d0, uint32_t& d1, uint32_t& d2,
                                      uint32_t& d3, uint32_t addr) {
    asm volatile("ldmatrix.sync.aligned.m8n8.x4.shared.b16 {%0,%1,%2,%3}, [%4];"
                 : "=r"(d0), "=r"(d1), "=r"(d2), "=r"(d3) : "r"(addr));
}
__device__ __forceinline__ void mma_bf16(float* c, const uint32_t* a,
                                         uint32_t b0, uint32_t b1) {
    asm volatile(
        "mma.sync.aligned.m16n8k16.row.col.f32.bf16.bf16.f32 "
        "{%0,%1,%2,%3}, {%4,%5,%6,%7}, {%8,%9}, {%0,%1,%2,%3};"
        : "+f"(c[0]), "+f"(c[1]), "+f"(c[2]), "+f"(c[3])
        : "r"(a[0]), "r"(a[1]), "r"(a[2]), "r"(a[3]), "r"(b0), "r"(b1));
}
__device__ __forceinline__ void mma_f16(float* c, const uint32_t* a,
                                        uint32_t b0, uint32_t b1) {
    asm volatile(
        "mma.sync.aligned.m16n8k16.row.col.f32.f16.f16.f32 "
        "{%0,%1,%2,%3}, {%4,%5,%6,%7}, {%8,%9}, {%0,%1,%2,%3};"
        : "+f"(c[0]), "+f"(c[1]), "+f"(c[2]), "+f"(c[3])
        : "r"(a[0]), "r"(a[1]), "r"(a[2]), "r"(a[3]), "r"(b0), "r"(b1));
}
__device__ __forceinline__ uint32_t packh2(float f_lo, float f_hi) {
    uint32_t r;
    asm("cvt.rn.f16x2.f32 %0, %1, %2;" : "=r"(r) : "f"(f_hi), "f"(f_lo));
    return r;
}
__device__ __forceinline__ float2 h2f2(uint32_t h) {
    __half2 hh = *reinterpret_cast<__half2*>(&h);
    return __half22float2(hh);
}
__device__ __forceinline__ void split2b(float x, __nv_bfloat16& h, __nv_bfloat16& l) {
    h = __float2bfloat16_rn(x);
    l = __float2bfloat16_rn(x - __bfloat162float(h));
}
__device__ __forceinline__ void cpa16(uint32_t dst, const void* src) {
    asm volatile("cp.async.cg.shared.global [%0], [%1], 16;" :: "r"(dst), "l"(src) : "memory");
}
#define CPA_COMMIT() asm volatile("cp.async.commit_group;" ::: "memory")
#define CPA_WAIT(n)  asm volatile("cp.async.wait_group %0;" :: "n"(n) : "memory")

// ---------------------------------------------------------------------------
__global__ __launch_bounds__(256) void split_x_kernel(const float* __restrict__ X) {
    size_t i = (size_t)blockIdx.x * 256 + threadIdx.x;
    float4 v = ((const float4*)X)[i];
    float xs[4] = {v.x, v.y, v.z, v.w};
    __nv_bfloat16 h[4], l[4];
    #pragma unroll
    for (int e = 0; e < 4; e++) split2b(xs[e], h[e], l[e]);
    *(uint2*)&g_Xh[4 * i] = *(uint2*)h;
    *(uint2*)&g_Xl[4 * i] = *(uint2*)l;
}

__global__ void split_w_kernel(const float* __restrict__ W) {
    __shared__ float tile[32][33];
    int n0 = blockIdx.x * 32, k0 = blockIdx.y * 32;
    int tx = threadIdx.x, ty = threadIdx.y;
    for (int i = ty; i < 32; i += 8)
        tile[i][tx] = W[(size_t)(k0 + i) * NQKVc + n0 + tx];
    __syncthreads();
    for (int i = ty; i < 32; i += 8) {
        __nv_bfloat16 h, l;
        split2b(tile[tx][i], h, l);
        size_t o = (size_t)(n0 + i) * DMc + k0 + tx;
        g_Wh[o] = h; g_Wl[o] = l;
    }
}

// ---------------------------------------------------------------------------
// QKV GEMM: bf16 3-product m16n8k16, 2-stage cp.async.
// ---------------------------------------------------------------------------
#define QPW     20
#define QTW     (128 * QPW)
#define QSTAGEW (4 * QTW)
#define QKV_SMEM (2 * QSTAGEW * 4)

__global__ __launch_bounds__(256, 2) void qkv_mma_kernel(const float* __restrict__ bias) {
    extern __shared__ uint32_t sw[];
    const uint32_t sb = smem_u32(sw);

    const int tid  = threadIdx.x;
    const int lane = tid & 31;
    const int wid  = tid >> 5;
    const int wm   = wid & 3;
    const int wn   = wid >> 2;
    const int n0   = blockIdx.x * 128;
    const int m0   = blockIdx.y * 128;

    float acc[2][8][4];
    #pragma unroll
    for (int mt = 0; mt < 2; mt++)
        #pragma unroll
        for (int j = 0; j < 8; j++)
            #pragma unroll
            for (int e = 0; e < 4; e++) acc[mt][j][e] = 0.f;

    const uint32_t a_row = lane & 15;
    const uint32_t a_kw  = (lane & 16) >> 2;
    const uint32_t b_row = (lane & 7) + ((lane & 16) >> 1);
    const uint32_t b_kw  = (lane & 8) >> 1;

    const uint4* srcs[4] = {
        (const uint4*)g_Xh + (size_t)m0 * 128,
        (const uint4*)g_Xl + (size_t)m0 * 128,
        (const uint4*)g_Wh + (size_t)n0 * 128,
        (const uint4*)g_Wl + (size_t)n0 * 128};

    auto load_chunk = [&](int buf, int kc) {
        uint32_t base = sb + (buf * QSTAGEW) * 4;
        #pragma unroll
        for (int t = tid; t < 2048; t += 256) {
            int tl = t >> 9, rem = t & 511, r = rem >> 2, q = rem & 3;
            cpa16(base + (tl * QTW + r * QPW + q * 4) * 4,
                  srcs[tl] + (size_t)r * 128 + kc * 4 + q);
        }
    };

    load_chunk(0, 0);
    CPA_COMMIT();

    for (int kc = 0; kc < DMc / 32; kc++) {
        int buf = kc & 1;
        if (kc + 1 < DMc / 32) { load_chunk(buf ^ 1, kc + 1); CPA_COMMIT(); CPA_WAIT(1); }
        else                   { CPA_WAIT(0); }
        __syncthreads();

        uint32_t stage = sb + (buf * QSTAGEW) * 4;
        #pragma unroll
        for (int s = 0; s < 2; s++) {
            uint32_t axh[2][4], axl[2][4];
            #pragma unroll
            for (int mt = 0; mt < 2; mt++) {
                uint32_t ra = ((wm * 32 + mt * 16 + a_row) * QPW + s * 8 + a_kw) * 4;
                ldsm4(axh[mt][0], axh[mt][1], axh[mt][2], axh[mt][3], stage + ra);
                ldsm4(axl[mt][0], axl[mt][1], axl[mt][2], axl[mt][3], stage + QTW * 4 + ra);
            }
            #pragma unroll
            for (int j2 = 0; j2 < 4; j2++) {
                uint32_t rb = ((wn * 64 + j2 * 16 + b_row) * QPW + s * 8 + b_kw) * 4;
                uint32_t bh0, bh1, bh2, bh3, bl0, bl1, bl2, bl3;
                ldsm4(bh0, bh1, bh2, bh3, stage + 2 * QTW * 4 + rb);
                ldsm4(bl0, bl1, bl2, bl3, stage + 3 * QTW * 4 + rb);
                #pragma unroll
                for (int mt = 0; mt < 2; mt++) {
                    mma_bf16(acc[mt][2 * j2],     axh[mt], bh0, bh1);
                    mma_bf16(acc[mt][2 * j2],     axh[mt], bl0, bl1);
                    mma_bf16(acc[mt][2 * j2],     axl[mt], bh0, bh1);
                    mma_bf16(acc[mt][2 * j2 + 1], axh[mt], bh2, bh3);
                    mma_bf16(acc[mt][2 * j2 + 1], axh[mt], bl2, bl3);
                    mma_bf16(acc[mt][2 * j2 + 1], axl[mt], bh2, bh3);
                }
            }
        }
        __syncthreads();
    }

    // ---- Epilogue via smem, pitch 129 ----
    float* Cs = (float*)sw;
    #pragma unroll
    for (int mt = 0; mt < 2; mt++) {
        #pragma unroll
        for (int j = 0; j < 8; j++) {
            #pragma unroll
            for (int e = 0; e < 4; e++) {
                int rl = wm * 32 + mt * 16 + (lane >> 2) + (e >> 1) * 8;
                int cl = wn * 64 + j * 8 + 2 * (lane & 3) + (e & 1);
                Cs[rl * 129 + cl] = acc[mt][j][e] + __ldg(&bias[n0 + cl]);
            }
        }
    }
    __syncthreads();

    const int b  = (m0 >> 11);
    const int s0 = m0 & 2047;

    for (int idx = tid; idx < 16384; idx += 256) {
        int r = idx >> 7, c = idx & 127;
        int cg = n0 + c;
        int hh = cg / 192, rr = cg - hh * 192;
        if (rr < 128) {
            float v = Cs[r * 129 + c];
            int bh = b * Hc + hh;
            __nv_bfloat16 h, l;
            if (rr < 64) {
                split2b(8.0f * v, h, l);
                size_t o = ((size_t)bh * Sc + s0 + r) * Dc + rr;
                g_Qh[o] = h; g_Ql[o] = l;
            } else {
                split2b(v, h, l);
                size_t o = ((size_t)bh * Sc + s0 + r) * Dc + rr - 64;
                g_Kh[o] = h; g_Kl[o] = l;
            }
        }
    }

    {   // V: fp16 single, transposed store (coalesced down s)
        int cgrp = tid >> 7;
        int sr   = tid & 127;
        #pragma unroll 2
        for (int cp = 0; cp < 64; cp++) {
            int c  = cp * 2 + cgrp;
            int cg = n0 + c;
            int hh = cg / 192, rr = cg - hh * 192;
            if (rr >= 128) {
                float v = Cs[sr * 129 + c];
                size_t o = ((size_t)(b * Hc + hh) * Dc + rr - 128) * Sc + s0 + sr;
                g_Vt[o] = __float2half_rn(v);
            }
        }
    }
}

// ---------------------------------------------------------------------------
// Attention FA2: KV tile 64, 3-stage cp.async, ONE barrier/iter.
// QK^T: bf16 3-product. PV: fp16 single-product (P fp16, V fp16).
// ---------------------------------------------------------------------------
#define KPW 36
#define KH0 0
#define KL0 (64 * KPW)
#define VF0 (2 * 64 * KPW)
#define ABUFW (3 * 64 * KPW)            // 6912 words = 27,648 B per stage
#define NSTAGE 3
#define ATTN_SMEM (NSTAGE * ABUFW * 4)  // 82,944 B

__global__ __launch_bounds__(256, 2) void attn_kernel(float* __restrict__ out) {
    extern __shared__ uint32_t sw[];
    const uint32_t sb = smem_u32(sw);

    const int qt = blockIdx.x, h = blockIdx.y, b = blockIdx.z;
    const int bh = b * Hc + h;
    const int tid = threadIdx.x;
    const int lane = tid & 31;
    const int wid = tid >> 5;
    const int qg = qt * 128 + wid * 16;
    const int NT = Sc / 64;

    const uint4* Kh4 = (const uint4*)g_Kh + (size_t)bh * Sc * 8;
    const uint4* Kl4 = (const uint4*)g_Kl + (size_t)bh * Sc * 8;
    const uint4* Vf4 = (const uint4*)g_Vt + (size_t)bh * Dc * 256;

    auto load_kv = [&](int stg, int kt) {
        uint32_t base = sb + (stg * ABUFW) * 4;
        int kv0 = kt * 64;
        #pragma unroll
        for (int t = tid; t < 1536; t += 256) {
            int sec = t >> 9, rem = t & 511;
            int r = rem >> 3, q = rem & 7;
            if (sec == 0)
                cpa16(base + (KH0 + r * KPW + q * 4) * 4, Kh4 + (size_t)(kv0 + r) * 8 + q);
            else if (sec == 1)
                cpa16(base + (KL0 + r * KPW + q * 4) * 4, Kl4 + (size_t)(kv0 + r) * 8 + q);
            else
                cpa16(base + (VF0 + r * KPW + q * 4) * 4, Vf4 + (size_t)r * 256 + kt * 8 + q);
        }
    };

    // ---- preload Q fragments (pre-scaled by 8) ----
    uint32_t qh[4][4], ql[4][4];
    {
        const uint32_t* Qhw = (const uint32_t*)g_Qh + (size_t)bh * Sc * 32;
        const uint32_t* Qlw = (const uint32_t*)g_Ql + (size_t)bh * Sc * 32;
        int r0 = qg + (lane >> 2);
        #pragma unroll
        for (int s = 0; s < 4; s++) {
            int w0 = s * 8 + (lane & 3);
            qh[s][0] = Qhw[(size_t)r0 * 32 + w0];
            qh[s][1] = Qhw[(size_t)(r0 + 8) * 32 + w0];
            qh[s][2] = Qhw[(size_t)r0 * 32 + w0 + 4];
            qh[s][3] = Qhw[(size_t)(r0 + 8) * 32 + w0 + 4];
            ql[s][0] = Qlw[(size_t)r0 * 32 + w0];
            ql[s][1] = Qlw[(size_t)(r0 + 8) * 32 + w0];
            ql[s][2] = Qlw[(size_t)r0 * 32 + w0 + 4];
            ql[s][3] = Qlw[(size_t)(r0 + 8) * 32 + w0 + 4];
        }
    }

    float o[8][4];
    #pragma unroll
    for (int nd = 0; nd < 8; nd++)
        #pragma unroll
        for (int e = 0; e < 4; e++) o[nd][e] = 0.f;
    float m0 = -1e30f, m1 = -1e30f, l0 = 0.f, l1 = 0.f;

    const uint32_t f_row = (lane & 7) + ((lane & 16) >> 1);
    const uint32_t f_kw  = (lane & 8) >> 1;

    load_kv(0, 0); CPA_COMMIT();
    load_kv(1, 1); CPA_COMMIT();

    for (int kt = 0; kt < NT; kt++) {
        if (kt == NT - 1) { CPA_WAIT(0); } else { CPA_WAIT(1); }
        __syncthreads();
        if (kt + 2 < NT) { load_kv((kt + 2) % NSTAGE, kt + 2); CPA_COMMIT(); }

        uint32_t stage = sb + ((kt % NSTAGE) * ABUFW) * 4;

        // ---- scores: 16 q x 64 kv ----
        float sc[8][4];
        #pragma unroll
        for (int j = 0; j < 8; j++)
            #pragma unroll
            for (int e = 0; e < 4; e++) sc[j][e] = 0.f;

        #pragma unroll
        for (int j2 = 0; j2 < 4; j2++) {
            uint32_t rbase = (j2 * 16 + f_row) * KPW;
            #pragma unroll
            for (int s = 0; s < 4; s++) {
                uint32_t ra = stage + (rbase + s * 8 + f_kw) * 4;
                uint32_t bh0, bh1, bh2, bh3, bl0, bl1, bl2, bl3;
                ldsm4(bh0, bh1, bh2, bh3, ra + KH0 * 4);
                ldsm4(bl0, bl1, bl2, bl3, ra + KL0 * 4);
                mma_bf16(sc[2 * j2],     qh[s], bh0, bh1);
                mma_bf16(sc[2 * j2],     qh[s], bl0, bl1);
                mma_bf16(sc[2 * j2],     ql[s], bh0, bh1);
                mma_bf16(sc[2 * j2 + 1], qh[s], bh2, bh3);
                mma_bf16(sc[2 * j2 + 1], qh[s], bl2, bl3);
                mma_bf16(sc[2 * j2 + 1], ql[s], bh2, bh3);
            }
        }

        // ---- online softmax ----
        float tm0 = -1e30f, tm1 = -1e30f;
        #pragma unroll
        for (int j = 0; j < 8; j++) {
            tm0 = fmaxf(tm0, fmaxf(sc[j][0], sc[j][1]));
            tm1 = fmaxf(tm1, fmaxf(sc[j][2], sc[j][3]));
        }
        tm0 = fmaxf(tm0, __shfl_xor_sync(0xffffffffu, tm0, 1));
        tm0 = fmaxf(tm0, __shfl_xor_sync(0xffffffffu, tm0, 2));
        tm1 = fmaxf(tm1, __shfl_xor_sync(0xffffffffu, tm1, 1));
        tm1 = fmaxf(tm1, __shfl_xor_sync(0xffffffffu, tm1, 2));
        float mn0 = fmaxf(m0, tm0), mn1 = fmaxf(m1, tm1);
        float c0 = __expf(m0 - mn0), c1 = __expf(m1 - mn1);

        uint32_t pk[8][2];
        float ls0 = 0.f, ls1 = 0.f;
        #pragma unroll
        for (int j = 0; j < 8; j++) {
            float p0 = __expf(sc[j][0] - mn0);
            float p1 = __expf(sc[j][1] - mn0);
            float p2 = __expf(sc[j][2] - mn1);
            float p3 = __expf(sc[j][3] - mn1);
            uint32_t k0 = packh2(p0, p1);       // fp16 rounding
            uint32_t k1 = packh2(p2, p3);
            pk[j][0] = k0; pk[j][1] = k1;
            float2 f0 = h2f2(k0), f1 = h2f2(k1);
            ls0 += f0.x + f0.y;
            ls1 += f1.x + f1.y;
        }
        ls0 += __shfl_xor_sync(0xffffffffu, ls0, 1);
        ls0 += __shfl_xor_sync(0xffffffffu, ls0, 2);
        ls1 += __shfl_xor_sync(0xffffffffu, ls1, 1);
        ls1 += __shfl_xor_sync(0xffffffffu, ls1, 2);
        l0 = l0 * c0 + ls0;
        l1 = l1 * c1 + ls1;
        m0 = mn0; m1 = mn1;
        #pragma unroll
        for (int nd = 0; nd < 8; nd++) {
            o[nd][0] *= c0; o[nd][1] *= c0;
            o[nd][2] *= c1; o[nd][3] *= c1;
        }

        // ---- O += P(fp16) @ V(fp16) ----
        #pragma unroll
        for (int g = 0; g < 4; g++) {
            uint32_t rbase = (g * 16 + f_row) * KPW;
            #pragma unroll
            for (int t = 0; t < 4; t++) {
                uint32_t ra = stage + (rbase + t * 8 + f_kw) * 4 + VF0 * 4;
                uint32_t v0, v1, v2, v3;
                ldsm4(v0, v1, v2, v3, ra);
                uint32_t a[4] = {pk[2 * t][0], pk[2 * t][1], pk[2 * t + 1][0], pk[2 * t + 1][1]};
                mma_f16(o[2 * g],     a, v0, v1);
                mma_f16(o[2 * g + 1], a, v2, v3);
            }
        }
    }

    float inv0 = 1.0f / l0, inv1 = 1.0f / l1;
    int r0 = qg + (lane >> 2);
    #pragma unroll
    for (int nd = 0; nd < 8; nd++) {
        int d = h * Dc + nd * 8 + 2 * (lane & 3);
        float2 v0 = make_float2(o[nd][0] * inv0, o[nd][1] * inv0);
        float2 v1 = make_float2(o[nd][2] * inv1, o[nd][3] * inv1);
        *(float2*)(out + ((size_t)b * Sc + r0) * 1024 + d)     = v0;
        *(float2*)(out + ((size_t)b * Sc + r0 + 8) * 1024 + d) = v1;
    }
}

// ---------------------------------------------------------------------------
extern "C" void kernel_launch(void* const* d_in, const int* in_sizes, int n_in,
                              void* d_out, int out_size) {
    const float* X    = (const float*)d_in[0];
    const float* W    = (const float*)d_in[1];
    const float* bias = (const float*)d_in[2];
    float* out = (float*)d_out;

    split_x_kernel<<<(MROWS * DMc) / (256 * 4), 256>>>(X);
    split_w_kernel<<<dim3(NQKVc / 32, DMc / 32), dim3(32, 8)>>>(W);

    cudaFuncSetAttribute(qkv_mma_kernel, cudaFuncAttributeMaxDynamicSharedMemorySize, QKV_SMEM);
    qkv_mma_kernel<<<dim3(NQKVc / 128, MROWS / 128), 256, QKV_SMEM>>>(bias);

    cudaFuncSetAttribute(attn_kernel, cudaFuncAttributeMaxDynamicSharedMemorySize, ATTN_SMEM);
    attn_kernel<<<dim3(Sc / 128, Hc, Bc), 256, ATTN_SMEM>>>(out);
}

// round 10
// speedup vs baseline: 3.3490x; 1.0206x over previous
#include <cuda_runtime.h>
#include <cuda_bf16.h>
#include <cuda_fp16.h>
#include <cstdint>

#define Bc    2
#define Sc    2048
#define Hc    16
#define Dc    64
#define DMc   1024
#define NQKVc 3072
#define MROWS (Bc*Sc)
#define BH    (Bc*Hc)

// ---------------------------------------------------------------------------
__device__ __nv_bfloat16 g_Xh[(size_t)MROWS*DMc];
__device__ __nv_bfloat16 g_Xl[(size_t)MROWS*DMc];
__device__ __nv_bfloat16 g_Wh[(size_t)NQKVc*DMc];
__device__ __nv_bfloat16 g_Wl[(size_t)NQKVc*DMc];

__device__ __nv_bfloat16 g_Qh[(size_t)BH*Sc*Dc];    // split of 8*log2(e)*q
__device__ __nv_bfloat16 g_Ql[(size_t)BH*Sc*Dc];
__device__ __nv_bfloat16 g_Kh[(size_t)BH*Sc*Dc];
__device__ __nv_bfloat16 g_Kl[(size_t)BH*Sc*Dc];
__device__ __half        g_Vt[(size_t)BH*Dc*Sc];    // [bh][d][s], fp16

// ---------------------------------------------------------------------------
__device__ __forceinline__ uint32_t smem_u32(const void* p) {
    uint32_t a;
    asm("{ .reg .u64 t; cvta.to.shared.u64 t, %1; cvt.u32.u64 %0, t; }" : "=r"(a) : "l"(p));
    return a;
}
__device__ __forceinline__ void ldsm4(uint32_t& d0, uint32_t& d1, uint32_t& d2,
                                      uint32_t& d3, uint32_t addr) {
    asm volatile("ldmatrix.sync.aligned.m8n8.x4.shared.b16 {%0,%1,%2,%3}, [%4];"
                 : "=r"(d0), "=r"(d1), "=r"(d2), "=r"(d3) : "r"(addr));
}
__device__ __forceinline__ void mma_bf16(float* c, const uint32_t* a,
                                         uint32_t b0, uint32_t b1) {
    asm volatile(
        "mma.sync.aligned.m16n8k16.row.col.f32.bf16.bf16.f32 "
        "{%0,%1,%2,%3}, {%4,%5,%6,%7}, {%8,%9}, {%0,%1,%2,%3};"
        : "+f"(c[0]), "+f"(c[1]), "+f"(c[2]), "+f"(c[3])
        : "r"(a[0]), "r"(a[1]), "r"(a[2]), "r"(a[3]), "r"(b0), "r"(b1));
}
__device__ __forceinline__ void mma_f16(float* c, const uint32_t* a,
                                        uint32_t b0, uint32_t b1) {
    asm volatile(
        "mma.sync.aligned.m16n8k16.row.col.f32.f16.f16.f32 "
        "{%0,%1,%2,%3}, {%4,%5,%6,%7}, {%8,%9}, {%0,%1,%2,%3};"
        : "+f"(c[0]), "+f"(c[1]), "+f"(c[2]), "+f"(c[3])
        : "r"(a[0]), "r"(a[1]), "r"(a[2]), "r"(a[3]), "r"(b0), "r"(b1));
}
__device__ __forceinline__ uint32_t packh2(float f_lo, float f_hi) {
    uint32_t r;
    asm("cvt.rn.f16x2.f32 %0, %1, %2;" : "=r"(r) : "f"(f_hi), "f"(f_lo));
    return r;
}
__device__ __forceinline__ float2 h2f2(uint32_t h) {
    __half2 hh = *reinterpret_cast<__half2*>(&h);
    return __half22float2(hh);
}
__device__ __forceinline__ float ex2f(float x) {
    float r;
    asm("ex2.approx.f32 %0, %1;" : "=f"(r) : "f"(x));
    return r;
}
__device__ __forceinline__ uint32_t ex2h2(uint32_t x) {
    uint32_t r;
    asm("ex2.approx.f16x2 %0, %1;" : "=r"(r) : "r"(x));
    return r;
}
__device__ __forceinline__ void split2b(float x, __nv_bfloat16& h, __nv_bfloat16& l) {
    h = __float2bfloat16_rn(x);
    l = __float2bfloat16_rn(x - __bfloat162float(h));
}
__device__ __forceinline__ void cpa16(uint32_t dst, const void* src) {
    asm volatile("cp.async.cg.shared.global [%0], [%1], 16;" :: "r"(dst), "l"(src) : "memory");
}
#define CPA_COMMIT() asm volatile("cp.async.commit_group;" ::: "memory")
#define CPA_WAIT(n)  asm volatile("cp.async.wait_group %0;" :: "n"(n) : "memory")

// ---------------------------------------------------------------------------
__global__ __launch_bounds__(256) void split_x_kernel(const float* __restrict__ X) {
    size_t i = (size_t)blockIdx.x * 256 + threadIdx.x;
    float4 v = ((const float4*)X)[i];
    float xs[4] = {v.x, v.y, v.z, v.w};
    __nv_bfloat16 h[4], l[4];
    #pragma unroll
    for (int e = 0; e < 4; e++) split2b(xs[e], h[e], l[e]);
    *(uint2*)&g_Xh[4 * i] = *(uint2*)h;
    *(uint2*)&g_Xl[4 * i] = *(uint2*)l;
}

__global__ void split_w_kernel(const float* __restrict__ W) {
    __shared__ float tile[32][33];
    int n0 = blockIdx.x * 32, k0 = blockIdx.y * 32;
    int tx = threadIdx.x, ty = threadIdx.y;
    for (int i = ty; i < 32; i += 8)
        tile[i][tx] = W[(size_t)(k0 + i) * NQKVc + n0 + tx];
    __syncthreads();
    for (int i = ty; i < 32; i += 8) {
        __nv_bfloat16 h, l;
        split2b(tile[tx][i], h, l);
        size_t o = (size_t)(n0 + i) * DMc + k0 + tx;
        g_Wh[o] = h; g_Wl[o] = l;
    }
}

// ---------------------------------------------------------------------------
// QKV GEMM: bf16 3-product m16n8k16, 2-stage cp.async.
// ---------------------------------------------------------------------------
#define QPW     20
#define QTW     (128 * QPW)
#define QSTAGEW (4 * QTW)
#define QKV_SMEM (2 * QSTAGEW * 4)

__global__ __launch_bounds__(256, 2) void qkv_mma_kernel(const float* __restrict__ bias) {
    extern __shared__ uint32_t sw[];
    const uint32_t sb = smem_u32(sw);

    const int tid  = threadIdx.x;
    const int lane = tid & 31;
    const int wid  = tid >> 5;
    const int wm   = wid & 3;
    const int wn   = wid >> 2;
    const int n0   = blockIdx.x * 128;
    const int m0   = blockIdx.y * 128;

    float acc[2][8][4];
    #pragma unroll
    for (int mt = 0; mt < 2; mt++)
        #pragma unroll
        for (int j = 0; j < 8; j++)
            #pragma unroll
            for (int e = 0; e < 4; e++) acc[mt][j][e] = 0.f;

    const uint32_t a_row = lane & 15;
    const uint32_t a_kw  = (lane & 16) >> 2;
    const uint32_t b_row = (lane & 7) + ((lane & 16) >> 1);
    const uint32_t b_kw  = (lane & 8) >> 1;

    const uint4* srcs[4] = {
        (const uint4*)g_Xh + (size_t)m0 * 128,
        (const uint4*)g_Xl + (size_t)m0 * 128,
        (const uint4*)g_Wh + (size_t)n0 * 128,
        (const uint4*)g_Wl + (size_t)n0 * 128};

    auto load_chunk = [&](int buf, int kc) {
        uint32_t base = sb + (buf * QSTAGEW) * 4;
        #pragma unroll
        for (int t = tid; t < 2048; t += 256) {
            int tl = t >> 9, rem = t & 511, r = rem >> 2, q = rem & 3;
            cpa16(base + (tl * QTW + r * QPW + q * 4) * 4,
                  srcs[tl] + (size_t)r * 128 + kc * 4 + q);
        }
    };

    load_chunk(0, 0);
    CPA_COMMIT();

    for (int kc = 0; kc < DMc / 32; kc++) {
        int buf = kc & 1;
        if (kc + 1 < DMc / 32) { load_chunk(buf ^ 1, kc + 1); CPA_COMMIT(); CPA_WAIT(1); }
        else                   { CPA_WAIT(0); }
        __syncthreads();

        uint32_t stage = sb + (buf * QSTAGEW) * 4;
        #pragma unroll
        for (int s = 0; s < 2; s++) {
            uint32_t axh[2][4], axl[2][4];
            #pragma unroll
            for (int mt = 0; mt < 2; mt++) {
                uint32_t ra = ((wm * 32 + mt * 16 + a_row) * QPW + s * 8 + a_kw) * 4;
                ldsm4(axh[mt][0], axh[mt][1], axh[mt][2], axh[mt][3], stage + ra);
                ldsm4(axl[mt][0], axl[mt][1], axl[mt][2], axl[mt][3], stage + QTW * 4 + ra);
            }
            #pragma unroll
            for (int j2 = 0; j2 < 4; j2++) {
                uint32_t rb = ((wn * 64 + j2 * 16 + b_row) * QPW + s * 8 + b_kw) * 4;
                uint32_t bh0, bh1, bh2, bh3, bl0, bl1, bl2, bl3;
                ldsm4(bh0, bh1, bh2, bh3, stage + 2 * QTW * 4 + rb);
                ldsm4(bl0, bl1, bl2, bl3, stage + 3 * QTW * 4 + rb);
                #pragma unroll
                for (int mt = 0; mt < 2; mt++) {
                    mma_bf16(acc[mt][2 * j2],     axh[mt], bh0, bh1);
                    mma_bf16(acc[mt][2 * j2],     axh[mt], bl0, bl1);
                    mma_bf16(acc[mt][2 * j2],     axl[mt], bh0, bh1);
                    mma_bf16(acc[mt][2 * j2 + 1], axh[mt], bh2, bh3);
                    mma_bf16(acc[mt][2 * j2 + 1], axh[mt], bl2, bl3);
                    mma_bf16(acc[mt][2 * j2 + 1], axl[mt], bh2, bh3);
                }
            }
        }
        __syncthreads();
    }

    // ---- Epilogue via smem, pitch 129 ----
    float* Cs = (float*)sw;
    #pragma unroll
    for (int mt = 0; mt < 2; mt++) {
        #pragma unroll
        for (int j = 0; j < 8; j++) {
            #pragma unroll
            for (int e = 0; e < 4; e++) {
                int rl = wm * 32 + mt * 16 + (lane >> 2) + (e >> 1) * 8;
                int cl = wn * 64 + j * 8 + 2 * (lane & 3) + (e & 1);
                Cs[rl * 129 + cl] = acc[mt][j][e] + __ldg(&bias[n0 + cl]);
            }
        }
    }
    __syncthreads();

    const int b  = (m0 >> 11);
    const int s0 = m0 & 2047;

    for (int idx = tid; idx < 16384; idx += 256) {
        int r = idx >> 7, c = idx & 127;
        int cg = n0 + c;
        int hh = cg / 192, rr = cg - hh * 192;
        if (rr < 128) {
            float v = Cs[r * 129 + c];
            int bh = b * Hc + hh;
            __nv_bfloat16 h, l;
            if (rr < 64) {
                // logits in log2 domain: fold 8*log2(e) into Q
                split2b(11.5415603272f * v, h, l);
                size_t o = ((size_t)bh * Sc + s0 + r) * Dc + rr;
                g_Qh[o] = h; g_Ql[o] = l;
            } else {
                split2b(v, h, l);
                size_t o = ((size_t)bh * Sc + s0 + r) * Dc + rr - 64;
                g_Kh[o] = h; g_Kl[o] = l;
            }
        }
    }

    {   // V: fp16 single, transposed store
        int cgrp = tid >> 7;
        int sr   = tid & 127;
        #pragma unroll 2
        for (int cp = 0; cp < 64; cp++) {
            int c  = cp * 2 + cgrp;
            int cg = n0 + c;
            int hh = cg / 192, rr = cg - hh * 192;
            if (rr >= 128) {
                float v = Cs[sr * 129 + c];
                size_t o = ((size_t)(b * Hc + hh) * Dc + rr - 128) * Sc + s0 + sr;
                g_Vt[o] = __float2half_rn(v);
            }
        }
    }
}

// ---------------------------------------------------------------------------
// Attention FA2: KV tile 64, 3-stage cp.async, 1 barrier/iter.
// QK^T: bf16 3-product (log2-domain logits). Softmax: ex2.approx.f16x2.
// PV: fp16 single-product.
// ---------------------------------------------------------------------------
#define KPW 36
#define KH0 0
#define KL0 (64 * KPW)
#define VF0 (2 * 64 * KPW)
#define ABUFW (3 * 64 * KPW)
#define NSTAGE 3
#define ATTN_SMEM (NSTAGE * ABUFW * 4)

__global__ __launch_bounds__(256, 2) void attn_kernel(float* __restrict__ out) {
    extern __shared__ uint32_t sw[];
    const uint32_t sb = smem_u32(sw);

    const int qt = blockIdx.x, h = blockIdx.y, b = blockIdx.z;
    const int bh = b * Hc + h;
    const int tid = threadIdx.x;
    const int lane = tid & 31;
    const int wid = tid >> 5;
    const int qg = qt * 128 + wid * 16;
    const int NT = Sc / 64;

    const uint4* Kh4 = (const uint4*)g_Kh + (size_t)bh * Sc * 8;
    const uint4* Kl4 = (const uint4*)g_Kl + (size_t)bh * Sc * 8;
    const uint4* Vf4 = (const uint4*)g_Vt + (size_t)bh * Dc * 256;

    auto load_kv = [&](int stg, int kt) {
        uint32_t base = sb + (stg * ABUFW) * 4;
        int kv0 = kt * 64;
        #pragma unroll
        for (int t = tid; t < 1536; t += 256) {
            int sec = t >> 9, rem = t & 511;
            int r = rem >> 3, q = rem & 7;
            if (sec == 0)
                cpa16(base + (KH0 + r * KPW + q * 4) * 4, Kh4 + (size_t)(kv0 + r) * 8 + q);
            else if (sec == 1)
                cpa16(base + (KL0 + r * KPW + q * 4) * 4, Kl4 + (size_t)(kv0 + r) * 8 + q);
            else
                cpa16(base + (VF0 + r * KPW + q * 4) * 4, Vf4 + (size_t)r * 256 + kt * 8 + q);
        }
    };

    // ---- preload Q fragments (pre-scaled by 8*log2e) ----
    uint32_t qh[4][4], ql[4][4];
    {
        const uint32_t* Qhw = (const uint32_t*)g_Qh + (size_t)bh * Sc * 32;
        const uint32_t* Qlw = (const uint32_t*)g_Ql + (size_t)bh * Sc * 32;
        int r0 = qg + (lane >> 2);
        #pragma unroll
        for (int s = 0; s < 4; s++) {
            int w0 = s * 8 + (lane & 3);
            qh[s][0] = Qhw[(size_t)r0 * 32 + w0];
            qh[s][1] = Qhw[(size_t)(r0 + 8) * 32 + w0];
            qh[s][2] = Qhw[(size_t)r0 * 32 + w0 + 4];
            qh[s][3] = Qhw[(size_t)(r0 + 8) * 32 + w0 + 4];
            ql[s][0] = Qlw[(size_t)r0 * 32 + w0];
            ql[s][1] = Qlw[(size_t)(r0 + 8) * 32 + w0];
            ql[s][2] = Qlw[(size_t)r0 * 32 + w0 + 4];
            ql[s][3] = Qlw[(size_t)(r0 + 8) * 32 + w0 + 4];
        }
    }

    float o[8][4];
    #pragma unroll
    for (int nd = 0; nd < 8; nd++)
        #pragma unroll
        for (int e = 0; e < 4; e++) o[nd][e] = 0.f;
    float m0 = -1e30f, m1 = -1e30f, l0 = 0.f, l1 = 0.f;

    const uint32_t f_row = (lane & 7) + ((lane & 16) >> 1);
    const uint32_t f_kw  = (lane & 8) >> 1;

    load_kv(0, 0); CPA_COMMIT();
    load_kv(1, 1); CPA_COMMIT();

    for (int kt = 0; kt < NT; kt++) {
        if (kt == NT - 1) { CPA_WAIT(0); } else { CPA_WAIT(1); }
        __syncthreads();
        if (kt + 2 < NT) { load_kv((kt + 2) % NSTAGE, kt + 2); CPA_COMMIT(); }

        uint32_t stage = sb + ((kt % NSTAGE) * ABUFW) * 4;

        // ---- scores (log2-domain) ----
        float sc[8][4];
        #pragma unroll
        for (int j = 0; j < 8; j++)
            #pragma unroll
            for (int e = 0; e < 4; e++) sc[j][e] = 0.f;

        #pragma unroll
        for (int j2 = 0; j2 < 4; j2++) {
            uint32_t rbase = (j2 * 16 + f_row) * KPW;
            #pragma unroll
            for (int s = 0; s < 4; s++) {
                uint32_t ra = stage + (rbase + s * 8 + f_kw) * 4;
                uint32_t bh0, bh1, bh2, bh3, bl0, bl1, bl2, bl3;
                ldsm4(bh0, bh1, bh2, bh3, ra + KH0 * 4);
                ldsm4(bl0, bl1, bl2, bl3, ra + KL0 * 4);
                mma_bf16(sc[2 * j2],     qh[s], bh0, bh1);
                mma_bf16(sc[2 * j2],     qh[s], bl0, bl1);
                mma_bf16(sc[2 * j2],     ql[s], bh0, bh1);
                mma_bf16(sc[2 * j2 + 1], qh[s], bh2, bh3);
                mma_bf16(sc[2 * j2 + 1], qh[s], bl2, bl3);
                mma_bf16(sc[2 * j2 + 1], ql[s], bh2, bh3);
            }
        }

        // ---- online softmax (base-2) ----
        float tm0 = -1e30f, tm1 = -1e30f;
        #pragma unroll
        for (int j = 0; j < 8; j++) {
            tm0 = fmaxf(tm0, fmaxf(sc[j][0], sc[j][1]));
            tm1 = fmaxf(tm1, fmaxf(sc[j][2], sc[j][3]));
        }
        tm0 = fmaxf(tm0, __shfl_xor_sync(0xffffffffu, tm0, 1));
        tm0 = fmaxf(tm0, __shfl_xor_sync(0xffffffffu, tm0, 2));
        tm1 = fmaxf(tm1, __shfl_xor_sync(0xffffffffu, tm1, 1));
        tm1 = fmaxf(tm1, __shfl_xor_sync(0xffffffffu, tm1, 2));
        float mn0 = fmaxf(m0, tm0), mn1 = fmaxf(m1, tm1);
        float c0 = ex2f(m0 - mn0), c1 = ex2f(m1 - mn1);

        uint32_t pk[8][2];
        float ls0 = 0.f, ls1 = 0.f;
        #pragma unroll
        for (int j = 0; j < 8; j++) {
            uint32_t k0 = ex2h2(packh2(sc[j][0] - mn0, sc[j][1] - mn0));
            uint32_t k1 = ex2h2(packh2(sc[j][2] - mn1, sc[j][3] - mn1));
            pk[j][0] = k0; pk[j][1] = k1;
            float2 f0 = h2f2(k0), f1 = h2f2(k1);
            ls0 += f0.x + f0.y;
            ls1 += f1.x + f1.y;
        }
        ls0 += __shfl_xor_sync(0xffffffffu, ls0, 1);
        ls0 += __shfl_xor_sync(0xffffffffu, ls0, 2);
        ls1 += __shfl_xor_sync(0xffffffffu, ls1, 1);
        ls1 += __shfl_xor_sync(0xffffffffu, ls1, 2);
        l0 = l0 * c0 + ls0;
        l1 = l1 * c1 + ls1;
        m0 = mn0; m1 = mn1;
        #pragma unroll
        for (int nd = 0; nd < 8; nd++) {
            o[nd][0] *= c0; o[nd][1] *= c0;
            o[nd][2] *= c1; o[nd][3] *= c1;
        }

        // ---- O += P(fp16) @ V(fp16) ----
        #pragma unroll
        for (int g = 0; g < 4; g++) {
            uint32_t rbase = (g * 16 + f_row) * KPW;
            #pragma unroll
            for (int t = 0; t < 4; t++) {
                uint32_t ra = stage + (rbase + t * 8 + f_kw) * 4 + VF0 * 4;
                uint32_t v0, v1, v2, v3;
                ldsm4(v0, v1, v2, v3, ra);
                uint32_t a[4] = {pk[2 * t][0], pk[2 * t][1], pk[2 * t + 1][0], pk[2 * t + 1][1]};
                mma_f16(o[2 * g],     a, v0, v1);
                mma_f16(o[2 * g + 1], a, v2, v3);
            }
        }
    }

    float inv0 = 1.0f / l0, inv1 = 1.0f / l1;
    int r0 = qg + (lane >> 2);
    #pragma unroll
    for (int nd = 0; nd < 8; nd++) {
        int d = h * Dc + nd * 8 + 2 * (lane & 3);
        float2 v0 = make_float2(o[nd][0] * inv0, o[nd][1] * inv0);
        float2 v1 = make_float2(o[nd][2] * inv1, o[nd][3] * inv1);
        *(float2*)(out + ((size_t)b * Sc + r0) * 1024 + d)     = v0;
        *(float2*)(out + ((size_t)b * Sc + r0 + 8) * 1024 + d) = v1;
    }
}

// ---------------------------------------------------------------------------
extern "C" void kernel_launch(void* const* d_in, const int* in_sizes, int n_in,
                              void* d_out, int out_size) {
    const float* X    = (const float*)d_in[0];
    const float* W    = (const float*)d_in[1];
    const float* bias = (const float*)d_in[2];
    float* out = (float*)d_out;

    split_x_kernel<<<(MROWS * DMc) / (256 * 4), 256>>>(X);
    split_w_kernel<<<dim3(NQKVc / 32, DMc / 32), dim3(32, 8)>>>(W);

    cudaFuncSetAttribute(qkv_mma_kernel, cudaFuncAttributeMaxDynamicSharedMemorySize, QKV_SMEM);
    qkv_mma_kernel<<<dim3(NQKVc / 128, MROWS / 128), 256, QKV_SMEM>>>(bias);

    cudaFuncSetAttribute(attn_kernel, cudaFuncAttributeMaxDynamicSharedMemorySize, ATTN_SMEM);
    attn_kernel<<<dim3(Sc / 128, Hc, Bc), 256, ATTN_SMEM>>>(out);
}

// round 11
// speedup vs baseline: 3.4453x; 1.0288x over previous
#include <cuda_runtime.h>
#include <cuda_bf16.h>
#include <cuda_fp16.h>
#include <cstdint>

#define Bc    2
#define Sc    2048
#define Hc    16
#define Dc    64
#define DMc   1024
#define NQKVc 3072
#define MROWS (Bc*Sc)
#define BH    (Bc*Hc)

// ---------------------------------------------------------------------------
__device__ __nv_bfloat16 g_Xh[(size_t)MROWS*DMc];
__device__ __nv_bfloat16 g_Xl[(size_t)MROWS*DMc];
__device__ __nv_bfloat16 g_Wh[(size_t)NQKVc*DMc];
__device__ __nv_bfloat16 g_Wl[(size_t)NQKVc*DMc];

__device__ __nv_bfloat16 g_Qh[(size_t)BH*Sc*Dc];    // split of 8*log2(e)*q
__device__ __nv_bfloat16 g_Ql[(size_t)BH*Sc*Dc];
__device__ __nv_bfloat16 g_Kh[(size_t)BH*Sc*Dc];
__device__ __nv_bfloat16 g_Kl[(size_t)BH*Sc*Dc];
__device__ __half        g_Vt[(size_t)BH*Dc*Sc];    // [bh][d][s], fp16

// ---------------------------------------------------------------------------
__device__ __forceinline__ uint32_t smem_u32(const void* p) {
    uint32_t a;
    asm("{ .reg .u64 t; cvta.to.shared.u64 t, %1; cvt.u32.u64 %0, t; }" : "=r"(a) : "l"(p));
    return a;
}
__device__ __forceinline__ void ldsm4(uint32_t& d0, uint32_t& d1, uint32_t& d2,
                                      uint32_t& d3, uint32_t addr) {
    asm volatile("ldmatrix.sync.aligned.m8n8.x4.shared.b16 {%0,%1,%2,%3}, [%4];"
                 : "=r"(d0), "=r"(d1), "=r"(d2), "=r"(d3) : "r"(addr));
}
__device__ __forceinline__ void mma_bf16(float* c, const uint32_t* a,
                                         uint32_t b0, uint32_t b1) {
    asm volatile(
        "mma.sync.aligned.m16n8k16.row.col.f32.bf16.bf16.f32 "
        "{%0,%1,%2,%3}, {%4,%5,%6,%7}, {%8,%9}, {%0,%1,%2,%3};"
        : "+f"(c[0]), "+f"(c[1]), "+f"(c[2]), "+f"(c[3])
        : "r"(a[0]), "r"(a[1]), "r"(a[2]), "r"(a[3]), "r"(b0), "r"(b1));
}
__device__ __forceinline__ void mma_f16(float* c, const uint32_t* a,
                                        uint32_t b0, uint32_t b1) {
    asm volatile(
        "mma.sync.aligned.m16n8k16.row.col.f32.f16.f16.f32 "
        "{%0,%1,%2,%3}, {%4,%5,%6,%7}, {%8,%9}, {%0,%1,%2,%3};"
        : "+f"(c[0]), "+f"(c[1]), "+f"(c[2]), "+f"(c[3])
        : "r"(a[0]), "r"(a[1]), "r"(a[2]), "r"(a[3]), "r"(b0), "r"(b1));
}
__device__ __forceinline__ uint32_t packh2(float f_lo, float f_hi) {
    uint32_t r;
    asm("cvt.rn.f16x2.f32 %0, %1, %2;" : "=r"(r) : "f"(f_hi), "f"(f_lo));
    return r;
}
__device__ __forceinline__ float ex2f(float x) {
    float r;
    asm("ex2.approx.f32 %0, %1;" : "=f"(r) : "f"(x));
    return r;
}
__device__ __forceinline__ uint32_t ex2h2(uint32_t x) {
    uint32_t r;
    asm("ex2.approx.f16x2 %0, %1;" : "=r"(r) : "r"(x));
    return r;
}
__device__ __forceinline__ void split2b(float x, __nv_bfloat16& h, __nv_bfloat16& l) {
    h = __float2bfloat16_rn(x);
    l = __float2bfloat16_rn(x - __bfloat162float(h));
}
__device__ __forceinline__ void cpa16(uint32_t dst, const void* src) {
    asm volatile("cp.async.cg.shared.global [%0], [%1], 16;" :: "r"(dst), "l"(src) : "memory");
}
#define CPA_COMMIT() asm volatile("cp.async.commit_group;" ::: "memory")
#define CPA_WAIT(n)  asm volatile("cp.async.wait_group %0;" :: "n"(n) : "memory")

// ---------------------------------------------------------------------------
__global__ __launch_bounds__(256) void split_x_kernel(const float* __restrict__ X) {
    size_t i = (size_t)blockIdx.x * 256 + threadIdx.x;
    float4 v = ((const float4*)X)[i];
    float xs[4] = {v.x, v.y, v.z, v.w};
    __nv_bfloat16 h[4], l[4];
    #pragma unroll
    for (int e = 0; e < 4; e++) split2b(xs[e], h[e], l[e]);
    *(uint2*)&g_Xh[4 * i] = *(uint2*)h;
    *(uint2*)&g_Xl[4 * i] = *(uint2*)l;
}

__global__ void split_w_kernel(const float* __restrict__ W) {
    __shared__ float tile[32][33];
    int n0 = blockIdx.x * 32, k0 = blockIdx.y * 32;
    int tx = threadIdx.x, ty = threadIdx.y;
    for (int i = ty; i < 32; i += 8)
        tile[i][tx] = W[(size_t)(k0 + i) * NQKVc + n0 + tx];
    __syncthreads();
    for (int i = ty; i < 32; i += 8) {
        __nv_bfloat16 h, l;
        split2b(tile[tx][i], h, l);
        size_t o = (size_t)(n0 + i) * DMc + k0 + tx;
        g_Wh[o] = h; g_Wl[o] = l;
    }
}

// ---------------------------------------------------------------------------
// QKV GEMM: bf16 3-product m16n8k16, 2-stage cp.async.
// ---------------------------------------------------------------------------
#define QPW     20
#define QTW     (128 * QPW)
#define QSTAGEW (4 * QTW)
#define QKV_SMEM (2 * QSTAGEW * 4)

__global__ __launch_bounds__(256, 2) void qkv_mma_kernel(const float* __restrict__ bias) {
    extern __shared__ uint32_t sw[];
    const uint32_t sb = smem_u32(sw);

    const int tid  = threadIdx.x;
    const int lane = tid & 31;
    const int wid  = tid >> 5;
    const int wm   = wid & 3;
    const int wn   = wid >> 2;
    const int n0   = blockIdx.x * 128;
    const int m0   = blockIdx.y * 128;

    float acc[2][8][4];
    #pragma unroll
    for (int mt = 0; mt < 2; mt++)
        #pragma unroll
        for (int j = 0; j < 8; j++)
            #pragma unroll
            for (int e = 0; e < 4; e++) acc[mt][j][e] = 0.f;

    const uint32_t a_row = lane & 15;
    const uint32_t a_kw  = (lane & 16) >> 2;
    const uint32_t b_row = (lane & 7) + ((lane & 16) >> 1);
    const uint32_t b_kw  = (lane & 8) >> 1;

    const uint4* srcs[4] = {
        (const uint4*)g_Xh + (size_t)m0 * 128,
        (const uint4*)g_Xl + (size_t)m0 * 128,
        (const uint4*)g_Wh + (size_t)n0 * 128,
        (const uint4*)g_Wl + (size_t)n0 * 128};

    auto load_chunk = [&](int buf, int kc) {
        uint32_t base = sb + (buf * QSTAGEW) * 4;
        #pragma unroll
        for (int t = tid; t < 2048; t += 256) {
            int tl = t >> 9, rem = t & 511, r = rem >> 2, q = rem & 3;
            cpa16(base + (tl * QTW + r * QPW + q * 4) * 4,
                  srcs[tl] + (size_t)r * 128 + kc * 4 + q);
        }
    };

    load_chunk(0, 0);
    CPA_COMMIT();

    for (int kc = 0; kc < DMc / 32; kc++) {
        int buf = kc & 1;
        if (kc + 1 < DMc / 32) { load_chunk(buf ^ 1, kc + 1); CPA_COMMIT(); CPA_WAIT(1); }
        else                   { CPA_WAIT(0); }
        __syncthreads();

        uint32_t stage = sb + (buf * QSTAGEW) * 4;
        #pragma unroll
        for (int s = 0; s < 2; s++) {
            uint32_t axh[2][4], axl[2][4];
            #pragma unroll
            for (int mt = 0; mt < 2; mt++) {
                uint32_t ra = ((wm * 32 + mt * 16 + a_row) * QPW + s * 8 + a_kw) * 4;
                ldsm4(axh[mt][0], axh[mt][1], axh[mt][2], axh[mt][3], stage + ra);
                ldsm4(axl[mt][0], axl[mt][1], axl[mt][2], axl[mt][3], stage + QTW * 4 + ra);
            }
            #pragma unroll
            for (int j2 = 0; j2 < 4; j2++) {
                uint32_t rb = ((wn * 64 + j2 * 16 + b_row) * QPW + s * 8 + b_kw) * 4;
                uint32_t bh0, bh1, bh2, bh3, bl0, bl1, bl2, bl3;
                ldsm4(bh0, bh1, bh2, bh3, stage + 2 * QTW * 4 + rb);
                ldsm4(bl0, bl1, bl2, bl3, stage + 3 * QTW * 4 + rb);
                #pragma unroll
                for (int mt = 0; mt < 2; mt++) {
                    mma_bf16(acc[mt][2 * j2],     axh[mt], bh0, bh1);
                    mma_bf16(acc[mt][2 * j2],     axh[mt], bl0, bl1);
                    mma_bf16(acc[mt][2 * j2],     axl[mt], bh0, bh1);
                    mma_bf16(acc[mt][2 * j2 + 1], axh[mt], bh2, bh3);
                    mma_bf16(acc[mt][2 * j2 + 1], axh[mt], bl2, bl3);
                    mma_bf16(acc[mt][2 * j2 + 1], axl[mt], bh2, bh3);
                }
            }
        }
        __syncthreads();
    }

    // ---- Epilogue via smem, pitch 129 ----
    float* Cs = (float*)sw;
    #pragma unroll
    for (int mt = 0; mt < 2; mt++) {
        #pragma unroll
        for (int j = 0; j < 8; j++) {
            #pragma unroll
            for (int e = 0; e < 4; e++) {
                int rl = wm * 32 + mt * 16 + (lane >> 2) + (e >> 1) * 8;
                int cl = wn * 64 + j * 8 + 2 * (lane & 3) + (e & 1);
                Cs[rl * 129 + cl] = acc[mt][j][e] + __ldg(&bias[n0 + cl]);
            }
        }
    }
    __syncthreads();

    const int b  = (m0 >> 11);
    const int s0 = m0 & 2047;

    for (int idx = tid; idx < 16384; idx += 256) {
        int r = idx >> 7, c = idx & 127;
        int cg = n0 + c;
        int hh = cg / 192, rr = cg - hh * 192;
        if (rr < 128) {
            float v = Cs[r * 129 + c];
            int bh = b * Hc + hh;
            __nv_bfloat16 h, l;
            if (rr < 64) {
                // logits in log2 domain: fold 8*log2(e) into Q
                split2b(11.5415603272f * v, h, l);
                size_t o = ((size_t)bh * Sc + s0 + r) * Dc + rr;
                g_Qh[o] = h; g_Ql[o] = l;
            } else {
                split2b(v, h, l);
                size_t o = ((size_t)bh * Sc + s0 + r) * Dc + rr - 64;
                g_Kh[o] = h; g_Kl[o] = l;
            }
        }
    }

    {   // V: fp16 single, transposed store
        int cgrp = tid >> 7;
        int sr   = tid & 127;
        #pragma unroll 2
        for (int cp = 0; cp < 64; cp++) {
            int c  = cp * 2 + cgrp;
            int cg = n0 + c;
            int hh = cg / 192, rr = cg - hh * 192;
            if (rr >= 128) {
                float v = Cs[sr * 129 + c];
                size_t o = ((size_t)(b * Hc + hh) * Dc + rr - 128) * Sc + s0 + sr;
                g_Vt[o] = __float2half_rn(v);
            }
        }
    }
}

// ---------------------------------------------------------------------------
// Attention FA2: KV tile 64, 3-stage cp.async, 1 barrier/iter.
// QK^T: bf16 3-product (log2-domain). Softmax: ex2.approx.f16x2.
// PV: fp16 single-product. l accumulated ON THE TENSOR PIPE via a
// ones-column B fragment (removes per-iter shuffles/unpacks).
// ---------------------------------------------------------------------------
#define KPW 36
#define KH0 0
#define KL0 (64 * KPW)
#define VF0 (2 * 64 * KPW)
#define ABUFW (3 * 64 * KPW)
#define NSTAGE 3
#define ATTN_SMEM (NSTAGE * ABUFW * 4)

__global__ __launch_bounds__(256, 2) void attn_kernel(float* __restrict__ out) {
    extern __shared__ uint32_t sw[];
    const uint32_t sb = smem_u32(sw);

    const int qt = blockIdx.x, h = blockIdx.y, b = blockIdx.z;
    const int bh = b * Hc + h;
    const int tid = threadIdx.x;
    const int lane = tid & 31;
    const int wid = tid >> 5;
    const int qg = qt * 128 + wid * 16;
    const int NT = Sc / 64;

    const uint4* Kh4 = (const uint4*)g_Kh + (size_t)bh * Sc * 8;
    const uint4* Kl4 = (const uint4*)g_Kl + (size_t)bh * Sc * 8;
    const uint4* Vf4 = (const uint4*)g_Vt + (size_t)bh * Dc * 256;

    auto load_kv = [&](int stg, int kt) {
        uint32_t base = sb + (stg * ABUFW) * 4;
        int kv0 = kt * 64;
        #pragma unroll
        for (int t = tid; t < 1536; t += 256) {
            int sec = t >> 9, rem = t & 511;
            int r = rem >> 3, q = rem & 7;
            if (sec == 0)
                cpa16(base + (KH0 + r * KPW + q * 4) * 4, Kh4 + (size_t)(kv0 + r) * 8 + q);
            else if (sec == 1)
                cpa16(base + (KL0 + r * KPW + q * 4) * 4, Kl4 + (size_t)(kv0 + r) * 8 + q);
            else
                cpa16(base + (VF0 + r * KPW + q * 4) * 4, Vf4 + (size_t)r * 256 + kt * 8 + q);
        }
    };

    // ---- preload Q fragments (pre-scaled by 8*log2e) ----
    uint32_t qh[4][4], ql[4][4];
    {
        const uint32_t* Qhw = (const uint32_t*)g_Qh + (size_t)bh * Sc * 32;
        const uint32_t* Qlw = (const uint32_t*)g_Ql + (size_t)bh * Sc * 32;
        int r0 = qg + (lane >> 2);
        #pragma unroll
        for (int s = 0; s < 4; s++) {
            int w0 = s * 8 + (lane & 3);
            qh[s][0] = Qhw[(size_t)r0 * 32 + w0];
            qh[s][1] = Qhw[(size_t)(r0 + 8) * 32 + w0];
            qh[s][2] = Qhw[(size_t)r0 * 32 + w0 + 4];
            qh[s][3] = Qhw[(size_t)(r0 + 8) * 32 + w0 + 4];
            ql[s][0] = Qlw[(size_t)r0 * 32 + w0];
            ql[s][1] = Qlw[(size_t)(r0 + 8) * 32 + w0];
            ql[s][2] = Qlw[(size_t)r0 * 32 + w0 + 4];
            ql[s][3] = Qlw[(size_t)(r0 + 8) * 32 + w0 + 4];
        }
    }

    float o[8][4];
    #pragma unroll
    for (int nd = 0; nd < 8; nd++)
        #pragma unroll
        for (int e = 0; e < 4; e++) o[nd][e] = 0.f;
    float lacc[4] = {0.f, 0.f, 0.f, 0.f};       // l via ones-column mma
    float m0 = -1e30f, m1 = -1e30f;

    // ones-column B fragment: B[k][0] = 1.0h for all k, other cols 0
    const uint32_t ones_b = (lane < 4) ? 0x3C003C00u : 0u;

    const uint32_t f_row = (lane & 7) + ((lane & 16) >> 1);
    const uint32_t f_kw  = (lane & 8) >> 1;

    load_kv(0, 0); CPA_COMMIT();
    load_kv(1, 1); CPA_COMMIT();

    for (int kt = 0; kt < NT; kt++) {
        if (kt == NT - 1) { CPA_WAIT(0); } else { CPA_WAIT(1); }
        __syncthreads();
        if (kt + 2 < NT) { load_kv((kt + 2) % NSTAGE, kt + 2); CPA_COMMIT(); }

        uint32_t stage = sb + ((kt % NSTAGE) * ABUFW) * 4;

        // ---- scores (log2-domain) ----
        float sc[8][4];
        #pragma unroll
        for (int j = 0; j < 8; j++)
            #pragma unroll
            for (int e = 0; e < 4; e++) sc[j][e] = 0.f;

        #pragma unroll
        for (int j2 = 0; j2 < 4; j2++) {
            uint32_t rbase = (j2 * 16 + f_row) * KPW;
            #pragma unroll
            for (int s = 0; s < 4; s++) {
                uint32_t ra = stage + (rbase + s * 8 + f_kw) * 4;
                uint32_t bh0, bh1, bh2, bh3, bl0, bl1, bl2, bl3;
                ldsm4(bh0, bh1, bh2, bh3, ra + KH0 * 4);
                ldsm4(bl0, bl1, bl2, bl3, ra + KL0 * 4);
                mma_bf16(sc[2 * j2],     qh[s], bh0, bh1);
                mma_bf16(sc[2 * j2],     qh[s], bl0, bl1);
                mma_bf16(sc[2 * j2],     ql[s], bh0, bh1);
                mma_bf16(sc[2 * j2 + 1], qh[s], bh2, bh3);
                mma_bf16(sc[2 * j2 + 1], qh[s], bl2, bl3);
                mma_bf16(sc[2 * j2 + 1], ql[s], bh2, bh3);
            }
        }

        // ---- online softmax (base-2); max reduce only ----
        float tm0 = -1e30f, tm1 = -1e30f;
        #pragma unroll
        for (int j = 0; j < 8; j++) {
            tm0 = fmaxf(tm0, fmaxf(sc[j][0], sc[j][1]));
            tm1 = fmaxf(tm1, fmaxf(sc[j][2], sc[j][3]));
        }
        tm0 = fmaxf(tm0, __shfl_xor_sync(0xffffffffu, tm0, 1));
        tm0 = fmaxf(tm0, __shfl_xor_sync(0xffffffffu, tm0, 2));
        tm1 = fmaxf(tm1, __shfl_xor_sync(0xffffffffu, tm1, 1));
        tm1 = fmaxf(tm1, __shfl_xor_sync(0xffffffffu, tm1, 2));
        float mn0 = fmaxf(m0, tm0), mn1 = fmaxf(m1, tm1);
        float c0 = ex2f(m0 - mn0), c1 = ex2f(m1 - mn1);

        uint32_t pk[8][2];
        #pragma unroll
        for (int j = 0; j < 8; j++) {
            pk[j][0] = ex2h2(packh2(sc[j][0] - mn0, sc[j][1] - mn0));
            pk[j][1] = ex2h2(packh2(sc[j][2] - mn1, sc[j][3] - mn1));
        }
        m0 = mn0; m1 = mn1;
        #pragma unroll
        for (int nd = 0; nd < 8; nd++) {
            o[nd][0] *= c0; o[nd][1] *= c0;
            o[nd][2] *= c1; o[nd][3] *= c1;
        }
        lacc[0] *= c0; lacc[1] *= c0;
        lacc[2] *= c1; lacc[3] *= c1;

        // ---- O += P(fp16) @ V(fp16);  l += P @ 1 (tensor pipe) ----
        #pragma unroll
        for (int g = 0; g < 4; g++) {
            uint32_t rbase = (g * 16 + f_row) * KPW;
            #pragma unroll
            for (int t = 0; t < 4; t++) {
                uint32_t ra = stage + (rbase + t * 8 + f_kw) * 4 + VF0 * 4;
                uint32_t v0, v1, v2, v3;
                ldsm4(v0, v1, v2, v3, ra);
                uint32_t a[4] = {pk[2 * t][0], pk[2 * t][1], pk[2 * t + 1][0], pk[2 * t + 1][1]};
                mma_f16(o[2 * g],     a, v0, v1);
                mma_f16(o[2 * g + 1], a, v2, v3);
            }
        }
        #pragma unroll
        for (int t = 0; t < 4; t++) {
            uint32_t a[4] = {pk[2 * t][0], pk[2 * t][1], pk[2 * t + 1][0], pk[2 * t + 1][1]};
            mma_f16(lacc, a, ones_b, ones_b);
        }
    }

    // l lives in column 0 of the lacc fragment: lane&3 == 0, regs 0 (row) / 2 (row+8)
    float l0 = __shfl_sync(0xffffffffu, lacc[0], lane & ~3);
    float l1 = __shfl_sync(0xffffffffu, lacc[2], lane & ~3);
    float inv0 = 1.0f / l0, inv1 = 1.0f / l1;
    int r0 = qg + (lane >> 2);
    #pragma unroll
    for (int nd = 0; nd < 8; nd++) {
        int d = h * Dc + nd * 8 + 2 * (lane & 3);
        float2 v0 = make_float2(o[nd][0] * inv0, o[nd][1] * inv0);
        float2 v1 = make_float2(o[nd][2] * inv1, o[nd][3] * inv1);
        *(float2*)(out + ((size_t)b * Sc + r0) * 1024 + d)     = v0;
        *(float2*)(out + ((size_t)b * Sc + r0 + 8) * 1024 + d) = v1;
    }
}

// ---------------------------------------------------------------------------
extern "C" void kernel_launch(void* const* d_in, const int* in_sizes, int n_in,
                              void* d_out, int out_size) {
    const float* X    = (const float*)d_in[0];
    const float* W    = (const float*)d_in[1];
    const float* bias = (const float*)d_in[2];
    float* out = (float*)d_out;

    split_x_kernel<<<(MROWS * DMc) / (256 * 4), 256>>>(X);
    split_w_kernel<<<dim3(NQKVc / 32, DMc / 32), dim3(32, 8)>>>(W);

    cudaFuncSetAttribute(qkv_mma_kernel, cudaFuncAttributeMaxDynamicSharedMemorySize, QKV_SMEM);
    qkv_mma_kernel<<<dim3(NQKVc / 128, MROWS / 128), 256, QKV_SMEM>>>(bias);

    cudaFuncSetAttribute(attn_kernel, cudaFuncAttributeMaxDynamicSharedMemorySize, ATTN_SMEM);
    attn_kernel<<<dim3(Sc / 128, Hc, Bc), 256, ATTN_SMEM>>>(out);
}

// round 12
// speedup vs baseline: 3.8624x; 1.1211x over previous
#include <cuda_runtime.h>
#include <cuda_bf16.h>
#include <cuda_fp16.h>
#include <cstdint>

#define Bc    2
#define Sc    2048
#define Hc    16
#define Dc    64
#define DMc   1024
#define NQKVc 3072
#define NQKc  2048
#define MROWS (Bc*Sc)
#define BH    (Bc*Hc)

// ---------------------------------------------------------------------------
__device__ __nv_bfloat16 g_Xh[(size_t)MROWS*DMc];
__device__ __nv_bfloat16 g_Xl[(size_t)MROWS*DMc];
__device__ __half        g_Xf[(size_t)MROWS*DMc];     // fp16 X for V-gemm
__device__ __nv_bfloat16 g_Wh[(size_t)NQKc*DMc];      // QK cols compacted
__device__ __nv_bfloat16 g_Wl[(size_t)NQKc*DMc];
__device__ __half        g_Wvf[(size_t)1024*DMc];     // V cols, fp16

__device__ __nv_bfloat16 g_Qh[(size_t)BH*Sc*Dc];      // split of 8*log2(e)*q
__device__ __nv_bfloat16 g_Ql[(size_t)BH*Sc*Dc];
__device__ __nv_bfloat16 g_Kh[(size_t)BH*Sc*Dc];
__device__ __nv_bfloat16 g_Kl[(size_t)BH*Sc*Dc];
__device__ __half        g_Vt[(size_t)BH*Dc*Sc];      // [bh][d][s], fp16

// ---------------------------------------------------------------------------
__device__ __forceinline__ uint32_t smem_u32(const void* p) {
    uint32_t a;
    asm("{ .reg .u64 t; cvta.to.shared.u64 t, %1; cvt.u32.u64 %0, t; }" : "=r"(a) : "l"(p));
    return a;
}
__device__ __forceinline__ void ldsm4(uint32_t& d0, uint32_t& d1, uint32_t& d2,
                                      uint32_t& d3, uint32_t addr) {
    asm volatile("ldmatrix.sync.aligned.m8n8.x4.shared.b16 {%0,%1,%2,%3}, [%4];"
                 : "=r"(d0), "=r"(d1), "=r"(d2), "=r"(d3) : "r"(addr));
}
__device__ __forceinline__ void mma_bf16(float* c, const uint32_t* a,
                                         uint32_t b0, uint32_t b1) {
    asm volatile(
        "mma.sync.aligned.m16n8k16.row.col.f32.bf16.bf16.f32 "
        "{%0,%1,%2,%3}, {%4,%5,%6,%7}, {%8,%9}, {%0,%1,%2,%3};"
        : "+f"(c[0]), "+f"(c[1]), "+f"(c[2]), "+f"(c[3])
        : "r"(a[0]), "r"(a[1]), "r"(a[2]), "r"(a[3]), "r"(b0), "r"(b1));
}
__device__ __forceinline__ void mma_f16(float* c, const uint32_t* a,
                                        uint32_t b0, uint32_t b1) {
    asm volatile(
        "mma.sync.aligned.m16n8k16.row.col.f32.f16.f16.f32 "
        "{%0,%1,%2,%3}, {%4,%5,%6,%7}, {%8,%9}, {%0,%1,%2,%3};"
        : "+f"(c[0]), "+f"(c[1]), "+f"(c[2]), "+f"(c[3])
        : "r"(a[0]), "r"(a[1]), "r"(a[2]), "r"(a[3]), "r"(b0), "r"(b1));
}
__device__ __forceinline__ uint32_t packh2(float f_lo, float f_hi) {
    uint32_t r;
    asm("cvt.rn.f16x2.f32 %0, %1, %2;" : "=r"(r) : "f"(f_hi), "f"(f_lo));
    return r;
}
__device__ __forceinline__ float ex2f(float x) {
    float r;
    asm("ex2.approx.f32 %0, %1;" : "=f"(r) : "f"(x));
    return r;
}
__device__ __forceinline__ uint32_t ex2h2(uint32_t x) {
    uint32_t r;
    asm("ex2.approx.f16x2 %0, %1;" : "=r"(r) : "r"(x));
    return r;
}
__device__ __forceinline__ void split2b(float x, __nv_bfloat16& h, __nv_bfloat16& l) {
    h = __float2bfloat16_rn(x);
    l = __float2bfloat16_rn(x - __bfloat162float(h));
}
__device__ __forceinline__ void cpa16(uint32_t dst, const void* src) {
    asm volatile("cp.async.cg.shared.global [%0], [%1], 16;" :: "r"(dst), "l"(src) : "memory");
}
#define CPA_COMMIT() asm volatile("cp.async.commit_group;" ::: "memory")
#define CPA_WAIT(n)  asm volatile("cp.async.wait_group %0;" :: "n"(n) : "memory")

// ---------------------------------------------------------------------------
__global__ __launch_bounds__(256) void split_x_kernel(const float* __restrict__ X) {
    size_t i = (size_t)blockIdx.x * 256 + threadIdx.x;
    float4 v = ((const float4*)X)[i];
    float xs[4] = {v.x, v.y, v.z, v.w};
    __nv_bfloat16 h[4], l[4];
    __half f[4];
    #pragma unroll
    for (int e = 0; e < 4; e++) { split2b(xs[e], h[e], l[e]); f[e] = __float2half_rn(xs[e]); }
    *(uint2*)&g_Xh[4 * i] = *(uint2*)h;
    *(uint2*)&g_Xl[4 * i] = *(uint2*)l;
    *(uint2*)&g_Xf[4 * i] = *(uint2*)f;
}

// W [1024][3072] -> compacted: QK cols (bf16 hi/lo) + V cols (fp16)
__global__ void split_w_kernel(const float* __restrict__ W) {
    __shared__ float tile[32][33];
    int n0 = blockIdx.x * 32, k0 = blockIdx.y * 32;
    int tx = threadIdx.x, ty = threadIdx.y;
    for (int i = ty; i < 32; i += 8)
        tile[i][tx] = W[(size_t)(k0 + i) * NQKVc + n0 + tx];
    __syncthreads();
    for (int i = ty; i < 32; i += 8) {
        float w = tile[tx][i];                        // W[k0+tx][n0+i]
        int col = n0 + i, k = k0 + tx;
        int hh = col / 192, rr = col - hh * 192;
        if (rr < 128) {
            __nv_bfloat16 h, l;
            split2b(w, h, l);
            size_t o = (size_t)(hh * 128 + rr) * DMc + k;
            g_Wh[o] = h; g_Wl[o] = l;
        } else {
            g_Wvf[(size_t)(hh * 64 + rr - 128) * DMc + k] = __float2half_rn(w);
        }
    }
}

// ---------------------------------------------------------------------------
// QK GEMM: C[4096,2048] = X@W_qk + b, bf16 3-product, 2-stage cp.async.
// ---------------------------------------------------------------------------
#define QPW     20
#define QTW     (128 * QPW)
#define QSTAGEW (4 * QTW)
#define QKV_SMEM (2 * QSTAGEW * 4)

__global__ __launch_bounds__(256, 2) void qkv_mma_kernel(const float* __restrict__ bias) {
    extern __shared__ uint32_t sw[];
    const uint32_t sb = smem_u32(sw);

    const int tid  = threadIdx.x;
    const int lane = tid & 31;
    const int wid  = tid >> 5;
    const int wm   = wid & 3;
    const int wn   = wid >> 2;
    const int n0   = blockIdx.x * 128;
    const int m0   = blockIdx.y * 128;

    float acc[2][8][4];
    #pragma unroll
    for (int mt = 0; mt < 2; mt++)
        #pragma unroll
        for (int j = 0; j < 8; j++)
            #pragma unroll
            for (int e = 0; e < 4; e++) acc[mt][j][e] = 0.f;

    const uint32_t a_row = lane & 15;
    const uint32_t a_kw  = (lane & 16) >> 2;
    const uint32_t b_row = (lane & 7) + ((lane & 16) >> 1);
    const uint32_t b_kw  = (lane & 8) >> 1;

    const uint4* srcs[4] = {
        (const uint4*)g_Xh + (size_t)m0 * 128,
        (const uint4*)g_Xl + (size_t)m0 * 128,
        (const uint4*)g_Wh + (size_t)n0 * 128,
        (const uint4*)g_Wl + (size_t)n0 * 128};

    auto load_chunk = [&](int buf, int kc) {
        uint32_t base = sb + (buf * QSTAGEW) * 4;
        #pragma unroll
        for (int t = tid; t < 2048; t += 256) {
            int tl = t >> 9, rem = t & 511, r = rem >> 2, q = rem & 3;
            cpa16(base + (tl * QTW + r * QPW + q * 4) * 4,
                  srcs[tl] + (size_t)r * 128 + kc * 4 + q);
        }
    };

    load_chunk(0, 0);
    CPA_COMMIT();

    for (int kc = 0; kc < DMc / 32; kc++) {
        int buf = kc & 1;
        if (kc + 1 < DMc / 32) { load_chunk(buf ^ 1, kc + 1); CPA_COMMIT(); CPA_WAIT(1); }
        else                   { CPA_WAIT(0); }
        __syncthreads();

        uint32_t stage = sb + (buf * QSTAGEW) * 4;
        #pragma unroll
        for (int s = 0; s < 2; s++) {
            uint32_t axh[2][4], axl[2][4];
            #pragma unroll
            for (int mt = 0; mt < 2; mt++) {
                uint32_t ra = ((wm * 32 + mt * 16 + a_row) * QPW + s * 8 + a_kw) * 4;
                ldsm4(axh[mt][0], axh[mt][1], axh[mt][2], axh[mt][3], stage + ra);
                ldsm4(axl[mt][0], axl[mt][1], axl[mt][2], axl[mt][3], stage + QTW * 4 + ra);
            }
            #pragma unroll
            for (int j2 = 0; j2 < 4; j2++) {
                uint32_t rb = ((wn * 64 + j2 * 16 + b_row) * QPW + s * 8 + b_kw) * 4;
                uint32_t bh0, bh1, bh2, bh3, bl0, bl1, bl2, bl3;
                ldsm4(bh0, bh1, bh2, bh3, stage + 2 * QTW * 4 + rb);
                ldsm4(bl0, bl1, bl2, bl3, stage + 3 * QTW * 4 + rb);
                // interleaved accumulators: dependency distance 2
                #pragma unroll
                for (int mt = 0; mt < 2; mt++) {
                    mma_bf16(acc[mt][2 * j2],     axh[mt], bh0, bh1);
                    mma_bf16(acc[mt][2 * j2 + 1], axh[mt], bh2, bh3);
                    mma_bf16(acc[mt][2 * j2],     axh[mt], bl0, bl1);
                    mma_bf16(acc[mt][2 * j2 + 1], axh[mt], bl2, bl3);
                    mma_bf16(acc[mt][2 * j2],     axl[mt], bh0, bh1);
                    mma_bf16(acc[mt][2 * j2 + 1], axl[mt], bh2, bh3);
                }
            }
        }
        __syncthreads();
    }

    // ---- Epilogue via smem, pitch 129 ----
    float* Cs = (float*)sw;
    #pragma unroll
    for (int mt = 0; mt < 2; mt++) {
        #pragma unroll
        for (int j = 0; j < 8; j++) {
            #pragma unroll
            for (int e = 0; e < 4; e++) {
                int rl = wm * 32 + mt * 16 + (lane >> 2) + (e >> 1) * 8;
                int cl = wn * 64 + j * 8 + 2 * (lane & 3) + (e & 1);
                int cg = n0 + cl;
                int bidx = (cg >> 7) * 192 + (cg & 127);
                Cs[rl * 129 + cl] = acc[mt][j][e] + __ldg(&bias[bidx]);
            }
        }
    }
    __syncthreads();

    const int b  = (m0 >> 11);
    const int s0 = m0 & 2047;

    for (int idx = tid; idx < 16384; idx += 256) {
        int r = idx >> 7, c = idx & 127;
        int cg = n0 + c;
        int hh = cg >> 7, rr = cg & 127;
        float v = Cs[r * 129 + c];
        int bh = b * Hc + hh;
        __nv_bfloat16 h, l;
        if (rr < 64) {
            split2b(11.5415603272f * v, h, l);   // 8*log2(e) folded into Q
            size_t o = ((size_t)bh * Sc + s0 + r) * Dc + rr;
            g_Qh[o] = h; g_Ql[o] = l;
        } else {
            split2b(v, h, l);
            size_t o = ((size_t)bh * Sc + s0 + r) * Dc + rr - 64;
            g_Kh[o] = h; g_Kl[o] = l;
        }
    }
}

// ---------------------------------------------------------------------------
// V GEMM: V[4096,1024] = X@W_v + b, fp16 SINGLE product (error ~2^-11,
// same order as the fp16 V storage rounding it already pays).
// ---------------------------------------------------------------------------
#define VQW     20
#define VTW     (128 * VQW)
#define VSTAGEW (2 * VTW)
#define VG_SMEM (2 * VSTAGEW * 4)     // 40,960 B

__global__ __launch_bounds__(256, 2) void v_mma_kernel(const float* __restrict__ bias) {
    extern __shared__ uint32_t sw[];
    const uint32_t sb = smem_u32(sw);

    const int tid  = threadIdx.x;
    const int lane = tid & 31;
    const int wid  = tid >> 5;
    const int wm   = wid & 3;
    const int wn   = wid >> 2;
    const int n0   = blockIdx.x * 128;
    const int m0   = blockIdx.y * 128;

    float acc[2][8][4];
    #pragma unroll
    for (int mt = 0; mt < 2; mt++)
        #pragma unroll
        for (int j = 0; j < 8; j++)
            #pragma unroll
            for (int e = 0; e < 4; e++) acc[mt][j][e] = 0.f;

    const uint32_t a_row = lane & 15;
    const uint32_t a_kw  = (lane & 16) >> 2;
    const uint32_t b_row = (lane & 7) + ((lane & 16) >> 1);
    const uint32_t b_kw  = (lane & 8) >> 1;

    const uint4* srcA = (const uint4*)g_Xf  + (size_t)m0 * 128;
    const uint4* srcB = (const uint4*)g_Wvf + (size_t)n0 * 128;

    auto load_chunk = [&](int buf, int kc) {
        uint32_t base = sb + (buf * VSTAGEW) * 4;
        #pragma unroll
        for (int t = tid; t < 1024; t += 256) {
            int tl = t >> 9, rem = t & 511, r = rem >> 2, q = rem & 3;
            const uint4* src = (tl == 0 ? srcA : srcB) + (size_t)r * 128 + kc * 4 + q;
            cpa16(base + (tl * VTW + r * VQW + q * 4) * 4, src);
        }
    };

    load_chunk(0, 0);
    CPA_COMMIT();

    for (int kc = 0; kc < DMc / 32; kc++) {
        int buf = kc & 1;
        if (kc + 1 < DMc / 32) { load_chunk(buf ^ 1, kc + 1); CPA_COMMIT(); CPA_WAIT(1); }
        else                   { CPA_WAIT(0); }
        __syncthreads();

        uint32_t stage = sb + (buf * VSTAGEW) * 4;
        #pragma unroll
        for (int s = 0; s < 2; s++) {
            uint32_t af[2][4];
            #pragma unroll
            for (int mt = 0; mt < 2; mt++) {
                uint32_t ra = ((wm * 32 + mt * 16 + a_row) * VQW + s * 8 + a_kw) * 4;
                ldsm4(af[mt][0], af[mt][1], af[mt][2], af[mt][3], stage + ra);
            }
            #pragma unroll
            for (int j2 = 0; j2 < 4; j2++) {
                uint32_t rb = ((wn * 64 + j2 * 16 + b_row) * VQW + s * 8 + b_kw) * 4;
                uint32_t b0, b1, b2, b3;
                ldsm4(b0, b1, b2, b3, stage + VTW * 4 + rb);
                #pragma unroll
                for (int mt = 0; mt < 2; mt++) {
                    mma_f16(acc[mt][2 * j2],     af[mt], b0, b1);
                    mma_f16(acc[mt][2 * j2 + 1], af[mt], b2, b3);
                }
            }
        }
        __syncthreads();
    }

    // ---- Epilogue: stage fp16 C tile (pitch 132), then coalesced V^T store ----
    __half* Cs = (__half*)sw;
    #pragma unroll
    for (int mt = 0; mt < 2; mt++) {
        #pragma unroll
        for (int j = 0; j < 8; j++) {
            #pragma unroll
            for (int e = 0; e < 4; e++) {
                int rl = wm * 32 + mt * 16 + (lane >> 2) + (e >> 1) * 8;
                int cl = wn * 64 + j * 8 + 2 * (lane & 3) + (e & 1);
                int cg = n0 + cl;
                int bidx = (cg >> 6) * 192 + 128 + (cg & 63);
                Cs[rl * 132 + cl] = __float2half_rn(acc[mt][j][e] + __ldg(&bias[bidx]));
            }
        }
    }
    __syncthreads();

    const int b  = (m0 >> 11);
    const int s0 = m0 & 2047;
    {
        int cgrp = tid >> 7;          // 0..1
        int sr   = tid & 127;
        #pragma unroll 2
        for (int cp = 0; cp < 64; cp++) {
            int c  = cp * 2 + cgrp;
            int cg = n0 + c;
            int hh = cg >> 6, d = cg & 63;
            g_Vt[((size_t)(b * Hc + hh) * Dc + d) * Sc + s0 + sr] = Cs[sr * 132 + c];
        }
    }
}

// ---------------------------------------------------------------------------
// Attention FA2: KV tile 64, 3-stage cp.async, 1 barrier/iter.
// QK^T: bf16 3-product (log2-domain). Softmax: ex2.approx.f16x2.
// PV: fp16 single-product. l on tensor pipe; lacc mma interleaved into PV.
// ---------------------------------------------------------------------------
#define KPW 36
#define KH0 0
#define KL0 (64 * KPW)
#define VF0 (2 * 64 * KPW)
#define ABUFW (3 * 64 * KPW)
#define NSTAGE 3
#define ATTN_SMEM (NSTAGE * ABUFW * 4)

__global__ __launch_bounds__(256, 2) void attn_kernel(float* __restrict__ out) {
    extern __shared__ uint32_t sw[];
    const uint32_t sb = smem_u32(sw);

    const int qt = blockIdx.x, h = blockIdx.y, b = blockIdx.z;
    const int bh = b * Hc + h;
    const int tid = threadIdx.x;
    const int lane = tid & 31;
    const int wid = tid >> 5;
    const int qg = qt * 128 + wid * 16;
    const int NT = Sc / 64;

    const uint4* Kh4 = (const uint4*)g_Kh + (size_t)bh * Sc * 8;
    const uint4* Kl4 = (const uint4*)g_Kl + (size_t)bh * Sc * 8;
    const uint4* Vf4 = (const uint4*)g_Vt + (size_t)bh * Dc * 256;

    auto load_kv = [&](int stg, int kt) {
        uint32_t base = sb + (stg * ABUFW) * 4;
        int kv0 = kt * 64;
        #pragma unroll
        for (int t = tid; t < 1536; t += 256) {
            int sec = t >> 9, rem = t & 511;
            int r = rem >> 3, q = rem & 7;
            if (sec == 0)
                cpa16(base + (KH0 + r * KPW + q * 4) * 4, Kh4 + (size_t)(kv0 + r) * 8 + q);
            else if (sec == 1)
                cpa16(base + (KL0 + r * KPW + q * 4) * 4, Kl4 + (size_t)(kv0 + r) * 8 + q);
            else
                cpa16(base + (VF0 + r * KPW + q * 4) * 4, Vf4 + (size_t)r * 256 + kt * 8 + q);
        }
    };

    // ---- preload Q fragments (pre-scaled by 8*log2e) ----
    uint32_t qh[4][4], ql[4][4];
    {
        const uint32_t* Qhw = (const uint32_t*)g_Qh + (size_t)bh * Sc * 32;
        const uint32_t* Qlw = (const uint32_t*)g_Ql + (size_t)bh * Sc * 32;
        int r0 = qg + (lane >> 2);
        #pragma unroll
        for (int s = 0; s < 4; s++) {
            int w0 = s * 8 + (lane & 3);
            qh[s][0] = Qhw[(size_t)r0 * 32 + w0];
            qh[s][1] = Qhw[(size_t)(r0 + 8) * 32 + w0];
            qh[s][2] = Qhw[(size_t)r0 * 32 + w0 + 4];
            qh[s][3] = Qhw[(size_t)(r0 + 8) * 32 + w0 + 4];
            ql[s][0] = Qlw[(size_t)r0 * 32 + w0];
            ql[s][1] = Qlw[(size_t)(r0 + 8) * 32 + w0];
            ql[s][2] = Qlw[(size_t)r0 * 32 + w0 + 4];
            ql[s][3] = Qlw[(size_t)(r0 + 8) * 32 + w0 + 4];
        }
    }

    float o[8][4];
    #pragma unroll
    for (int nd = 0; nd < 8; nd++)
        #pragma unroll
        for (int e = 0; e < 4; e++) o[nd][e] = 0.f;
    float lacc[4] = {0.f, 0.f, 0.f, 0.f};
    float m0 = -1e30f, m1 = -1e30f;

    const uint32_t ones_b = (lane < 4) ? 0x3C003C00u : 0u;

    const uint32_t f_row = (lane & 7) + ((lane & 16) >> 1);
    const uint32_t f_kw  = (lane & 8) >> 1;

    load_kv(0, 0); CPA_COMMIT();
    load_kv(1, 1); CPA_COMMIT();

    for (int kt = 0; kt < NT; kt++) {
        if (kt == NT - 1) { CPA_WAIT(0); } else { CPA_WAIT(1); }
        __syncthreads();
        if (kt + 2 < NT) { load_kv((kt + 2) % NSTAGE, kt + 2); CPA_COMMIT(); }

        uint32_t stage = sb + ((kt % NSTAGE) * ABUFW) * 4;

        // ---- scores (log2-domain), interleaved accumulators ----
        float sc[8][4];
        #pragma unroll
        for (int j = 0; j < 8; j++)
            #pragma unroll
            for (int e = 0; e < 4; e++) sc[j][e] = 0.f;

        #pragma unroll
        for (int j2 = 0; j2 < 4; j2++) {
            uint32_t rbase = (j2 * 16 + f_row) * KPW;
            #pragma unroll
            for (int s = 0; s < 4; s++) {
                uint32_t ra = stage + (rbase + s * 8 + f_kw) * 4;
                uint32_t bh0, bh1, bh2, bh3, bl0, bl1, bl2, bl3;
                ldsm4(bh0, bh1, bh2, bh3, ra + KH0 * 4);
                ldsm4(bl0, bl1, bl2, bl3, ra + KL0 * 4);
                mma_bf16(sc[2 * j2],     qh[s], bh0, bh1);
                mma_bf16(sc[2 * j2 + 1], qh[s], bh2, bh3);
                mma_bf16(sc[2 * j2],     qh[s], bl0, bl1);
                mma_bf16(sc[2 * j2 + 1], qh[s], bl2, bl3);
                mma_bf16(sc[2 * j2],     ql[s], bh0, bh1);
                mma_bf16(sc[2 * j2 + 1], ql[s], bh2, bh3);
            }
        }

        // ---- online softmax (base-2); max reduce only ----
        float tm0 = -1e30f, tm1 = -1e30f;
        #pragma unroll
        for (int j = 0; j < 8; j++) {
            tm0 = fmaxf(tm0, fmaxf(sc[j][0], sc[j][1]));
            tm1 = fmaxf(tm1, fmaxf(sc[j][2], sc[j][3]));
        }
        tm0 = fmaxf(tm0, __shfl_xor_sync(0xffffffffu, tm0, 1));
        tm0 = fmaxf(tm0, __shfl_xor_sync(0xffffffffu, tm0, 2));
        tm1 = fmaxf(tm1, __shfl_xor_sync(0xffffffffu, tm1, 1));
        tm1 = fmaxf(tm1, __shfl_xor_sync(0xffffffffu, tm1, 2));
        float mn0 = fmaxf(m0, tm0), mn1 = fmaxf(m1, tm1);
        float c0 = ex2f(m0 - mn0), c1 = ex2f(m1 - mn1);

        uint32_t pk[8][2];
        #pragma unroll
        for (int j = 0; j < 8; j++) {
            pk[j][0] = ex2h2(packh2(sc[j][0] - mn0, sc[j][1] - mn0));
            pk[j][1] = ex2h2(packh2(sc[j][2] - mn1, sc[j][3] - mn1));
        }
        m0 = mn0; m1 = mn1;
        #pragma unroll
        for (int nd = 0; nd < 8; nd++) {
            o[nd][0] *= c0; o[nd][1] *= c0;
            o[nd][2] *= c1; o[nd][3] *= c1;
        }
        lacc[0] *= c0; lacc[1] *= c0;
        lacc[2] *= c1; lacc[3] *= c1;

        // ---- O += P @ V; lacc mma interleaved (one per g) ----
        #pragma unroll
        for (int g = 0; g < 4; g++) {
            uint32_t rbase = (g * 16 + f_row) * KPW;
            #pragma unroll
            for (int t = 0; t < 4; t++) {
                uint32_t ra = stage + (rbase + t * 8 + f_kw) * 4 + VF0 * 4;
                uint32_t v0, v1, v2, v3;
                ldsm4(v0, v1, v2, v3, ra);
                uint32_t a[4] = {pk[2 * t][0], pk[2 * t][1], pk[2 * t + 1][0], pk[2 * t + 1][1]};
                mma_f16(o[2 * g],     a, v0, v1);
                mma_f16(o[2 * g + 1], a, v2, v3);
            }
            uint32_t al[4] = {pk[2 * g][0], pk[2 * g][1], pk[2 * g + 1][0], pk[2 * g + 1][1]};
            mma_f16(lacc, al, ones_b, ones_b);
        }
    }

    float l0 = __shfl_sync(0xffffffffu, lacc[0], lane & ~3);
    float l1 = __shfl_sync(0xffffffffu, lacc[2], lane & ~3);
    float inv0 = 1.0f / l0, inv1 = 1.0f / l1;
    int r0 = qg + (lane >> 2);
    #pragma unroll
    for (int nd = 0; nd < 8; nd++) {
        int d = h * Dc + nd * 8 + 2 * (lane & 3);
        float2 v0 = make_float2(o[nd][0] * inv0, o[nd][1] * inv0);
        float2 v1 = make_float2(o[nd][2] * inv1, o[nd][3] * inv1);
        *(float2*)(out + ((size_t)b * Sc + r0) * 1024 + d)     = v0;
        *(float2*)(out + ((size_t)b * Sc + r0 + 8) * 1024 + d) = v1;
    }
}

// ---------------------------------------------------------------------------
extern "C" void kernel_launch(void* const* d_in, const int* in_sizes, int n_in,
                              void* d_out, int out_size) {
    const float* X    = (const float*)d_in[0];
    const float* W    = (const float*)d_in[1];
    const float* bias = (const float*)d_in[2];
    float* out = (float*)d_out;

    split_x_kernel<<<(MROWS * DMc) / (256 * 4), 256>>>(X);
    split_w_kernel<<<dim3(NQKVc / 32, DMc / 32), dim3(32, 8)>>>(W);

    cudaFuncSetAttribute(qkv_mma_kernel, cudaFuncAttributeMaxDynamicSharedMemorySize, QKV_SMEM);
    qkv_mma_kernel<<<dim3(NQKc / 128, MROWS / 128), 256, QKV_SMEM>>>(bias);

    cudaFuncSetAttribute(v_mma_kernel, cudaFuncAttributeMaxDynamicSharedMemorySize, VG_SMEM);
    v_mma_kernel<<<dim3(1024 / 128, MROWS / 128), 256, VG_SMEM>>>(bias);

    cudaFuncSetAttribute(attn_kernel, cudaFuncAttributeMaxDynamicSharedMemorySize, ATTN_SMEM);
    attn_kernel<<<dim3(Sc / 128, Hc, Bc), 256, ATTN_SMEM>>>(out);
}